// round 1
// baseline (speedup 1.0000x reference)
#include <cuda_runtime.h>
#include <math.h>

// Problem constants
#define BATCH   8
#define C_DIM   512
#define N_SEQ   2048
#define HEADS   8
#define DHEAD   64
#define HIDDEN  512            // HEADS*DHEAD
#define QKV_ROWS 1536          // 3*HIDDEN
#define ATT_SCALE 0.125f       // DHEAD^-0.5

// Scratch (device globals: no allocation allowed in kernel_launch)
__device__ float g_qkv[(size_t)BATCH * QKV_ROWS * N_SEQ];   // [b][1536][2048]
__device__ float g_att[(size_t)BATCH * HIDDEN * N_SEQ];     // [b][512][2048]

// ---------------------------------------------------------------------------
// Tiled SGEMM: C[b] = A @ B[b] (+ bias per output row)
// A: [M,K] row-major (shared across batch), B: [K,N] row-major per batch,
// C: [M,N] per batch. BM=BN=128, BK=8, 256 threads, 8x8 per thread.
// Requires M%128==0, N%128==0, K%8==0 (holds for our shapes).
// ---------------------------------------------------------------------------
__global__ __launch_bounds__(256) void sgemm_kernel(
    const float* __restrict__ A, const float* __restrict__ Bg,
    float* __restrict__ Cg, const float* __restrict__ bias,
    int M, int N, int K)
{
    __shared__ float As[8][128];
    __shared__ float Bs[8][128];

    const float* B = Bg + (size_t)blockIdx.z * K * N;
    float*       C = Cg + (size_t)blockIdx.z * M * N;

    const int brow = blockIdx.y * 128;
    const int bcol = blockIdx.x * 128;
    const int tid  = threadIdx.x;
    const int tx   = tid & 15;        // 0..15
    const int ty   = tid >> 4;        // 0..15

    // load mapping
    const int aRow = tid >> 1;            // 0..127
    const int aCol = (tid & 1) * 4;       // 0 or 4
    const int bRow = tid >> 5;            // 0..7
    const int bCol = (tid & 31) * 4;      // 0..124

    float acc[8][8];
#pragma unroll
    for (int i = 0; i < 8; i++)
#pragma unroll
        for (int j = 0; j < 8; j++) acc[i][j] = 0.f;

    for (int k0 = 0; k0 < K; k0 += 8) {
        float4 a4 = *(const float4*)(A + (size_t)(brow + aRow) * K + k0 + aCol);
        As[aCol + 0][aRow] = a4.x;
        As[aCol + 1][aRow] = a4.y;
        As[aCol + 2][aRow] = a4.z;
        As[aCol + 3][aRow] = a4.w;
        float4 b4 = *(const float4*)(B + (size_t)(k0 + bRow) * N + bcol + bCol);
        *(float4*)&Bs[bRow][bCol] = b4;
        __syncthreads();

#pragma unroll
        for (int k = 0; k < 8; k++) {
            float4 a0 = *(const float4*)&As[k][ty * 8];
            float4 a1 = *(const float4*)&As[k][ty * 8 + 4];
            float4 b0 = *(const float4*)&Bs[k][tx * 8];
            float4 b1 = *(const float4*)&Bs[k][tx * 8 + 4];
            float ar[8] = {a0.x, a0.y, a0.z, a0.w, a1.x, a1.y, a1.z, a1.w};
            float br[8] = {b0.x, b0.y, b0.z, b0.w, b1.x, b1.y, b1.z, b1.w};
#pragma unroll
            for (int i = 0; i < 8; i++)
#pragma unroll
                for (int j = 0; j < 8; j++) acc[i][j] += ar[i] * br[j];
        }
        __syncthreads();
    }

#pragma unroll
    for (int i = 0; i < 8; i++) {
        const int row = brow + ty * 8 + i;
        const float bv = bias ? bias[row] : 0.f;
#pragma unroll
        for (int j = 0; j < 8; j += 4) {
            const int col = bcol + tx * 8 + j;
            float4 v;
            v.x = acc[i][j + 0] + bv;
            v.y = acc[i][j + 1] + bv;
            v.z = acc[i][j + 2] + bv;
            v.w = acc[i][j + 3] + bv;
            *(float4*)(C + (size_t)row * N + col) = v;
        }
    }
}

// ---------------------------------------------------------------------------
// Fused flash attention (fp32, online softmax).
// qkv layout: [b][1536][2048]; q = rows [0,512), k = [512,1024), v = [1024,1536)
// with channel o = h*64 + d (so q[b][h][d][i] == qkv[b][h*64+d][i]).
// Per block: one (b, h, 64-query tile). 256 threads.
// out: [b][512][2048], channel o = h*64 + d.
// ---------------------------------------------------------------------------
struct FlashSmem {
    float Qs[64][68];   // [d][i]
    float Ks[64][68];   // [d][j]
    float Vst[64][65];  // [j][d] (transposed)
    float Ss[64][65];   // [i][j] scores -> probs; reused for output staging
    float m_s[64];
    float l_s[64];
    float al_s[64];
};

__global__ __launch_bounds__(256) void flash_kernel(
    const float* __restrict__ qkv, float* __restrict__ outp)
{
    extern __shared__ char smem_raw[];
    FlashSmem& sm = *reinterpret_cast<FlashSmem*>(smem_raw);

    const int b  = blockIdx.z;
    const int h  = blockIdx.y;
    const int q0 = blockIdx.x * 64;

    const float* Q  = qkv + ((size_t)b * QKV_ROWS + h * 64) * N_SEQ;
    const float* Kp = qkv + ((size_t)b * QKV_ROWS + 512 + h * 64) * N_SEQ;
    const float* Vp = qkv + ((size_t)b * QKV_ROWS + 1024 + h * 64) * N_SEQ;

    const int tid  = threadIdx.x;
    const int tx   = tid & 15;
    const int ty   = tid >> 4;
    const int warp = tid >> 5;
    const int lane = tid & 31;

    // Load Q tile [64 d][64 i]
    for (int idx = tid; idx < 1024; idx += 256) {
        const int d  = idx >> 4;
        const int i4 = (idx & 15) << 2;
        float4 v = *(const float4*)(Q + (size_t)d * N_SEQ + q0 + i4);
        *(float4*)&sm.Qs[d][i4] = v;
    }
    if (tid < 64) { sm.m_s[tid] = -1e30f; sm.l_s[tid] = 0.f; }

    float O[4][4];
#pragma unroll
    for (int i = 0; i < 4; i++)
#pragma unroll
        for (int j = 0; j < 4; j++) O[i][j] = 0.f;

    for (int k0 = 0; k0 < N_SEQ; k0 += 64) {
        __syncthreads();  // prior readers of Ks/Vst done (also covers Q/m/l init)

        // Load K tile [d][j] and V tile transposed [j][d]
        for (int idx = tid; idx < 1024; idx += 256) {
            const int d  = idx >> 4;
            const int j4 = (idx & 15) << 2;
            float4 kv = *(const float4*)(Kp + (size_t)d * N_SEQ + k0 + j4);
            *(float4*)&sm.Ks[d][j4] = kv;
            float4 vv = *(const float4*)(Vp + (size_t)d * N_SEQ + k0 + j4);
            sm.Vst[j4 + 0][d] = vv.x;
            sm.Vst[j4 + 1][d] = vv.y;
            sm.Vst[j4 + 2][d] = vv.z;
            sm.Vst[j4 + 3][d] = vv.w;
        }
        __syncthreads();

        // S = (Q^T K) * scale ; thread (tx,ty) owns rows ty*4.., cols tx*4..
        float S[4][4];
#pragma unroll
        for (int i = 0; i < 4; i++)
#pragma unroll
            for (int j = 0; j < 4; j++) S[i][j] = 0.f;

#pragma unroll 8
        for (int d = 0; d < 64; d++) {
            float4 a = *(const float4*)&sm.Qs[d][ty * 4];
            float4 k = *(const float4*)&sm.Ks[d][tx * 4];
            float ar[4] = {a.x, a.y, a.z, a.w};
            float br[4] = {k.x, k.y, k.z, k.w};
#pragma unroll
            for (int i = 0; i < 4; i++)
#pragma unroll
                for (int j = 0; j < 4; j++) S[i][j] += ar[i] * br[j];
        }
#pragma unroll
        for (int i = 0; i < 4; i++)
#pragma unroll
            for (int j = 0; j < 4; j++)
                sm.Ss[ty * 4 + i][tx * 4 + j] = S[i][j] * ATT_SCALE;
        __syncthreads();

        // Online softmax: warp w handles rows w*8 .. w*8+7
#pragma unroll
        for (int r = 0; r < 8; r++) {
            const int row = warp * 8 + r;
            float s0 = sm.Ss[row][lane];
            float s1 = sm.Ss[row][lane + 32];
            float tmax = fmaxf(s0, s1);
#pragma unroll
            for (int o = 16; o > 0; o >>= 1)
                tmax = fmaxf(tmax, __shfl_xor_sync(0xffffffffu, tmax, o));
            const float oldm = sm.m_s[row];
            const float newm = fmaxf(oldm, tmax);
            float p0 = __expf(s0 - newm);
            float p1 = __expf(s1 - newm);
            sm.Ss[row][lane]      = p0;
            sm.Ss[row][lane + 32] = p1;
            float psum = p0 + p1;
#pragma unroll
            for (int o = 16; o > 0; o >>= 1)
                psum += __shfl_xor_sync(0xffffffffu, psum, o);
            if (lane == 0) {
                const float alpha = __expf(oldm - newm);
                sm.l_s[row] = sm.l_s[row] * alpha + psum;
                sm.m_s[row] = newm;
                sm.al_s[row] = alpha;
            }
        }
        __syncthreads();

        // Rescale accumulators, then O += P @ V^T (rows=i, cols=d)
        float alr[4];
#pragma unroll
        for (int i = 0; i < 4; i++) alr[i] = sm.al_s[ty * 4 + i];
#pragma unroll
        for (int i = 0; i < 4; i++)
#pragma unroll
            for (int c = 0; c < 4; c++) O[i][c] *= alr[i];

#pragma unroll 8
        for (int j = 0; j < 64; j++) {
            float ar[4], br[4];
#pragma unroll
            for (int i = 0; i < 4; i++) ar[i] = sm.Ss[ty * 4 + i][j];
#pragma unroll
            for (int c = 0; c < 4; c++) br[c] = sm.Vst[j][tx * 4 + c];
#pragma unroll
            for (int i = 0; i < 4; i++)
#pragma unroll
                for (int c = 0; c < 4; c++) O[i][c] += ar[i] * br[c];
        }
    }

    __syncthreads();  // everyone done reading Ss before we reuse it

    // Normalize and stage output in Ss as [i][dd]
#pragma unroll
    for (int i = 0; i < 4; i++) {
        const float inv_l = 1.f / sm.l_s[ty * 4 + i];
#pragma unroll
        for (int c = 0; c < 4; c++)
            sm.Ss[ty * 4 + i][tx * 4 + c] = O[i][c] * inv_l;
    }
    __syncthreads();

    // Coalesced writeout: out[b][h*64+dd][q0+i]
    for (int idx = tid; idx < 1024; idx += 256) {
        const int dd = idx >> 4;
        const int i4 = (idx & 15) << 2;
        float4 v;
        v.x = sm.Ss[i4 + 0][dd];
        v.y = sm.Ss[i4 + 1][dd];
        v.z = sm.Ss[i4 + 2][dd];
        v.w = sm.Ss[i4 + 3][dd];
        *(float4*)(outp + ((size_t)b * HIDDEN + h * 64 + dd) * N_SEQ + q0 + i4) = v;
    }
}

// ---------------------------------------------------------------------------
// Launch
// ---------------------------------------------------------------------------
extern "C" void kernel_launch(void* const* d_in, const int* in_sizes, int n_in,
                              void* d_out, int out_size)
{
    const float* x     = (const float*)d_in[0];  // [8,512,2048]
    const float* w_qkv = (const float*)d_in[1];  // [1536,512]
    const float* w_out = (const float*)d_in[2];  // [512,512]
    const float* b_out = (const float*)d_in[3];  // [512]
    float* y = (float*)d_out;                    // [8,512,2048]

    float* qkv = nullptr;
    float* att = nullptr;
    cudaGetSymbolAddress((void**)&qkv, g_qkv);
    cudaGetSymbolAddress((void**)&att, g_att);

    // 1) qkv = w_qkv @ x   (per batch)
    sgemm_kernel<<<dim3(N_SEQ / 128, QKV_ROWS / 128, BATCH), 256>>>(
        w_qkv, x, qkv, nullptr, QKV_ROWS, N_SEQ, C_DIM);

    // 2) fused attention
    const int flash_smem = (int)sizeof(FlashSmem);
    cudaFuncSetAttribute(flash_kernel,
                         cudaFuncAttributeMaxDynamicSharedMemorySize, flash_smem);
    flash_kernel<<<dim3(N_SEQ / 64, HEADS, BATCH), 256, flash_smem>>>(qkv, att);

    // 3) y = w_out @ att + b_out   (per batch)
    sgemm_kernel<<<dim3(N_SEQ / 128, HIDDEN / 128, BATCH), 256>>>(
        w_out, att, y, b_out, HIDDEN, N_SEQ, C_DIM);
}

// round 2
// speedup vs baseline: 2.8764x; 2.8764x over previous
#include <cuda_runtime.h>
#include <stdint.h>

#define BATCH    8
#define C_DIM    512
#define N_SEQ    2048
#define HEADS    8
#define QKV_ROWS 1536
#define HIDDEN   512
// 0.125 (=dhead^-0.5) * log2(e): softmax run in exp2 domain
#define SM_SCALE_LOG2 0.18033688011112042f

__device__ float g_qkv[(size_t)BATCH * QKV_ROWS * N_SEQ];   // [b][1536][2048]
__device__ float g_att[(size_t)BATCH * HIDDEN * N_SEQ];     // [b][512][2048]

__device__ __forceinline__ uint32_t f2tf(float f) {
    uint32_t r; asm("cvt.rna.tf32.f32 %0, %1;" : "=r"(r) : "f"(f)); return r;
}
__device__ __forceinline__ float ex2(float x) {
    float r; asm("ex2.approx.f32 %0, %1;" : "=f"(r) : "f"(x)); return r;
}
// D += A(16x8,row) * B(8x8,col), tf32, fp32 accum
__device__ __forceinline__ void mma8(float* c, const uint32_t* a, const uint32_t* b) {
    asm volatile(
        "mma.sync.aligned.m16n8k8.row.col.f32.tf32.tf32.f32 "
        "{%0,%1,%2,%3},{%4,%5,%6,%7},{%8,%9},{%0,%1,%2,%3};"
        : "+f"(c[0]), "+f"(c[1]), "+f"(c[2]), "+f"(c[3])
        : "r"(a[0]), "r"(a[1]), "r"(a[2]), "r"(a[3]), "r"(b[0]), "r"(b[1]));
}

// ---------------------------------------------------------------------------
// tf32 GEMM: C[b] = A[M,K] @ B[b][K,N] (+bias). Block 128x128, BK=32.
// 8 warps in 2x4 grid, each warp 64x32 (4 m-tiles x 4 n-tiles of m16n8k8).
// ---------------------------------------------------------------------------
#define ASTR 36    // As[128][36]: frag bank = 4*g + t  (conflict-free)
#define BSTR 136   // Bs[32][136]: frag bank = 8*t + g  (conflict-free)

__global__ __launch_bounds__(256, 2) void gemm_tf32(
    const float* __restrict__ A, const float* __restrict__ Bg,
    float* __restrict__ Cg, const float* __restrict__ bias,
    int M, int N, int K)
{
    __shared__ uint32_t As[128 * ASTR];
    __shared__ uint32_t Bs[32 * BSTR];

    const float* B = Bg + (size_t)blockIdx.z * K * N;
    float*       C = Cg + (size_t)blockIdx.z * M * N;
    const int brow = blockIdx.y * 128;
    const int bcol = blockIdx.x * 128;
    const int tid  = threadIdx.x;
    const int lane = tid & 31;
    const int w    = tid >> 5;
    const int wm   = (w >> 2) * 64;
    const int wn   = (w & 3) * 32;
    const int g    = lane >> 2;
    const int t    = lane & 3;

    float acc[4][4][4];
#pragma unroll
    for (int mt = 0; mt < 4; mt++)
#pragma unroll
        for (int nt = 0; nt < 4; nt++)
#pragma unroll
            for (int c = 0; c < 4; c++) acc[mt][nt][c] = 0.f;

    for (int k0 = 0; k0 < K; k0 += 32) {
        // stage A tile [128m][32k]
#pragma unroll
        for (int r = 0; r < 4; r++) {
            int idx = tid + 256 * r;
            int m = idx >> 3, k4 = (idx & 7) * 4;
            float4 v = *(const float4*)(A + (size_t)(brow + m) * K + k0 + k4);
            uint32_t* p = &As[m * ASTR + k4];
            p[0] = f2tf(v.x); p[1] = f2tf(v.y); p[2] = f2tf(v.z); p[3] = f2tf(v.w);
        }
        // stage B tile [32k][128n]
#pragma unroll
        for (int r = 0; r < 4; r++) {
            int idx = tid + 256 * r;
            int kk = idx >> 5, n4 = (idx & 31) * 4;
            float4 v = *(const float4*)(B + (size_t)(k0 + kk) * N + bcol + n4);
            uint32_t* p = &Bs[kk * BSTR + n4];
            p[0] = f2tf(v.x); p[1] = f2tf(v.y); p[2] = f2tf(v.z); p[3] = f2tf(v.w);
        }
        __syncthreads();

#pragma unroll
        for (int kc = 0; kc < 4; kc++) {
            const int k8 = kc * 8;
            uint32_t af[4][4], bf[4][2];
#pragma unroll
            for (int mt = 0; mt < 4; mt++) {
                const int r0 = wm + mt * 16 + g;
                af[mt][0] = As[r0 * ASTR + k8 + t];
                af[mt][1] = As[(r0 + 8) * ASTR + k8 + t];
                af[mt][2] = As[r0 * ASTR + k8 + t + 4];
                af[mt][3] = As[(r0 + 8) * ASTR + k8 + t + 4];
            }
#pragma unroll
            for (int nt = 0; nt < 4; nt++) {
                const int c0 = wn + nt * 8 + g;
                bf[nt][0] = Bs[(k8 + t) * BSTR + c0];
                bf[nt][1] = Bs[(k8 + t + 4) * BSTR + c0];
            }
#pragma unroll
            for (int mt = 0; mt < 4; mt++)
#pragma unroll
                for (int nt = 0; nt < 4; nt++)
                    mma8(acc[mt][nt], af[mt], bf[nt]);
        }
        __syncthreads();
    }

#pragma unroll
    for (int mt = 0; mt < 4; mt++) {
        const int r0 = brow + wm + mt * 16 + g;
        const float b0 = bias ? bias[r0] : 0.f;
        const float b1 = bias ? bias[r0 + 8] : 0.f;
#pragma unroll
        for (int nt = 0; nt < 4; nt++) {
            const int c = bcol + wn + nt * 8 + 2 * t;
            float2 v0 = make_float2(acc[mt][nt][0] + b0, acc[mt][nt][1] + b0);
            float2 v1 = make_float2(acc[mt][nt][2] + b1, acc[mt][nt][3] + b1);
            *(float2*)(C + (size_t)r0 * N + c)       = v0;
            *(float2*)(C + (size_t)(r0 + 8) * N + c) = v1;
        }
    }
}

// ---------------------------------------------------------------------------
// tf32 flash attention. Block = (b, h, 128 queries). 8 warps, each owns 16 q
// rows. Key tiles of 64. Online softmax in exp2 domain. P round-trips smem
// as tf32 (warp-private rows). Output staged in smem for coalesced [d][i].
// ---------------------------------------------------------------------------
#define QSTR 68    // Qs/Ps [128][68]
#define KSTR 72    // Ks/Vt [64][72]
#define FLASH_SMEM_WORDS (128 * QSTR + 64 * KSTR + 64 * KSTR + 128 * QSTR)

__global__ __launch_bounds__(256, 2) void flash_tf32(
    const float* __restrict__ qkv, float* __restrict__ outp)
{
    extern __shared__ uint32_t sm[];
    uint32_t* Qs = sm;                   // [i][d] tf32
    uint32_t* Ks = Qs + 128 * QSTR;      // [d][j] tf32
    uint32_t* Vt = Ks + 64 * KSTR;       // [j][d] tf32
    uint32_t* Ps = Vt + 64 * KSTR;       // [i][j] tf32 (reused as Os float[64][132])

    const int b  = blockIdx.z;
    const int h  = blockIdx.y;
    const int q0 = blockIdx.x * 128;
    const float* Q  = qkv + ((size_t)b * QKV_ROWS + h * 64) * N_SEQ;
    const float* Kp = Q + (size_t)512 * N_SEQ;
    const float* Vp = Q + (size_t)1024 * N_SEQ;

    const int tid  = threadIdx.x;
    const int lane = tid & 31;
    const int w    = tid >> 5;
    const int g    = lane >> 2;
    const int t    = lane & 3;
    const int r0   = w * 16 + g;     // this thread's q rows (local)
    const int r1   = r0 + 8;

    // Load Q [d][i] -> Qs[i][d] (transposed), tf32
#pragma unroll
    for (int r = 0; r < 8; r++) {
        int idx = tid + 256 * r;
        int d = idx >> 5, i4 = (idx & 31) * 4;
        float4 v = *(const float4*)(Q + (size_t)d * N_SEQ + q0 + i4);
        Qs[(i4 + 0) * QSTR + d] = f2tf(v.x);
        Qs[(i4 + 1) * QSTR + d] = f2tf(v.y);
        Qs[(i4 + 2) * QSTR + d] = f2tf(v.z);
        Qs[(i4 + 3) * QSTR + d] = f2tf(v.w);
    }

    float o[8][4];
#pragma unroll
    for (int dt = 0; dt < 8; dt++)
#pragma unroll
        for (int c = 0; c < 4; c++) o[dt][c] = 0.f;
    float m0 = -1e30f, m1 = -1e30f, l0 = 0.f, l1 = 0.f;

    for (int j0 = 0; j0 < N_SEQ; j0 += 64) {
        __syncthreads();   // previous tile's Ks/Vt readers done
        // Load K [d][j] -> Ks[d][j]; V [d][j] -> Vt[j][d]
#pragma unroll
        for (int r = 0; r < 4; r++) {
            int idx = tid + 256 * r;
            int d = idx >> 4, j4 = (idx & 15) * 4;
            float4 kv = *(const float4*)(Kp + (size_t)d * N_SEQ + j0 + j4);
            uint32_t* p = &Ks[d * KSTR + j4];
            p[0] = f2tf(kv.x); p[1] = f2tf(kv.y); p[2] = f2tf(kv.z); p[3] = f2tf(kv.w);
            float4 vv = *(const float4*)(Vp + (size_t)d * N_SEQ + j0 + j4);
            Vt[(j4 + 0) * KSTR + d] = f2tf(vv.x);
            Vt[(j4 + 1) * KSTR + d] = f2tf(vv.y);
            Vt[(j4 + 2) * KSTR + d] = f2tf(vv.z);
            Vt[(j4 + 3) * KSTR + d] = f2tf(vv.w);
        }
        __syncthreads();

        // S = Q^T K  (M = 16 q rows of this warp, N = 64 keys, K = 64 dims)
        float s[8][4];
#pragma unroll
        for (int nt = 0; nt < 8; nt++)
#pragma unroll
            for (int c = 0; c < 4; c++) s[nt][c] = 0.f;
#pragma unroll
        for (int kc = 0; kc < 8; kc++) {
            const int d8 = kc * 8;
            uint32_t a[4];
            a[0] = Qs[r0 * QSTR + d8 + t];
            a[1] = Qs[r1 * QSTR + d8 + t];
            a[2] = Qs[r0 * QSTR + d8 + t + 4];
            a[3] = Qs[r1 * QSTR + d8 + t + 4];
#pragma unroll
            for (int nt = 0; nt < 8; nt++) {
                uint32_t bb[2];
                bb[0] = Ks[(d8 + t) * KSTR + nt * 8 + g];
                bb[1] = Ks[(d8 + t + 4) * KSTR + nt * 8 + g];
                mma8(s[nt], a, bb);
            }
        }

        // scale into exp2 domain + row max
        float mx0 = -1e30f, mx1 = -1e30f;
#pragma unroll
        for (int nt = 0; nt < 8; nt++) {
            s[nt][0] *= SM_SCALE_LOG2; s[nt][1] *= SM_SCALE_LOG2;
            s[nt][2] *= SM_SCALE_LOG2; s[nt][3] *= SM_SCALE_LOG2;
            mx0 = fmaxf(mx0, fmaxf(s[nt][0], s[nt][1]));
            mx1 = fmaxf(mx1, fmaxf(s[nt][2], s[nt][3]));
        }
        mx0 = fmaxf(mx0, __shfl_xor_sync(0xffffffffu, mx0, 1));
        mx0 = fmaxf(mx0, __shfl_xor_sync(0xffffffffu, mx0, 2));
        mx1 = fmaxf(mx1, __shfl_xor_sync(0xffffffffu, mx1, 1));
        mx1 = fmaxf(mx1, __shfl_xor_sync(0xffffffffu, mx1, 2));

        const float nm0 = fmaxf(m0, mx0), nm1 = fmaxf(m1, mx1);
        const float al0 = ex2(m0 - nm0),  al1 = ex2(m1 - nm1);

        float ps0 = 0.f, ps1 = 0.f;
#pragma unroll
        for (int nt = 0; nt < 8; nt++) {
            float p0 = ex2(s[nt][0] - nm0);
            float p1 = ex2(s[nt][1] - nm0);
            float p2 = ex2(s[nt][2] - nm1);
            float p3 = ex2(s[nt][3] - nm1);
            ps0 += p0 + p1; ps1 += p2 + p3;
            uint2 u0 = make_uint2(f2tf(p0), f2tf(p1));
            uint2 u1 = make_uint2(f2tf(p2), f2tf(p3));
            *(uint2*)&Ps[r0 * QSTR + nt * 8 + 2 * t] = u0;
            *(uint2*)&Ps[r1 * QSTR + nt * 8 + 2 * t] = u1;
        }
        ps0 += __shfl_xor_sync(0xffffffffu, ps0, 1);
        ps0 += __shfl_xor_sync(0xffffffffu, ps0, 2);
        ps1 += __shfl_xor_sync(0xffffffffu, ps1, 1);
        ps1 += __shfl_xor_sync(0xffffffffu, ps1, 2);
        l0 = l0 * al0 + ps0; l1 = l1 * al1 + ps1;
        m0 = nm0; m1 = nm1;

        // rescale O
#pragma unroll
        for (int dt = 0; dt < 8; dt++) {
            o[dt][0] *= al0; o[dt][1] *= al0;
            o[dt][2] *= al1; o[dt][3] *= al1;
        }
        __syncwarp();   // Ps rows written by this warp, read cross-lane below

        // O += P @ V  (M = 16 q rows, N = 64 dims, K = 64 keys)
#pragma unroll
        for (int kc = 0; kc < 8; kc++) {
            const int j8 = kc * 8;
            uint32_t a[4];
            a[0] = Ps[r0 * QSTR + j8 + t];
            a[1] = Ps[r1 * QSTR + j8 + t];
            a[2] = Ps[r0 * QSTR + j8 + t + 4];
            a[3] = Ps[r1 * QSTR + j8 + t + 4];
#pragma unroll
            for (int dt = 0; dt < 8; dt++) {
                uint32_t bb[2];
                bb[0] = Vt[(j8 + t) * KSTR + dt * 8 + g];
                bb[1] = Vt[(j8 + t + 4) * KSTR + dt * 8 + g];
                mma8(o[dt], a, bb);
            }
        }
    }

    __syncthreads();   // all Ps readers done; reuse as Os[64][132] float
    float* Os = (float*)Ps;
    const float inv0 = 1.f / l0, inv1 = 1.f / l1;
#pragma unroll
    for (int dt = 0; dt < 8; dt++) {
        const int d = dt * 8 + 2 * t;
        Os[(size_t)d * 132 + r0]       = o[dt][0] * inv0;
        Os[(size_t)(d + 1) * 132 + r0] = o[dt][1] * inv0;
        Os[(size_t)d * 132 + r1]       = o[dt][2] * inv1;
        Os[(size_t)(d + 1) * 132 + r1] = o[dt][3] * inv1;
    }
    __syncthreads();

    float* out = outp + ((size_t)b * HIDDEN + h * 64) * N_SEQ;
#pragma unroll
    for (int r = 0; r < 8; r++) {
        int idx = tid + 256 * r;
        int d = idx >> 5, i4 = (idx & 31) * 4;
        float4 v;
        v.x = Os[(size_t)d * 132 + i4 + 0];
        v.y = Os[(size_t)d * 132 + i4 + 1];
        v.z = Os[(size_t)d * 132 + i4 + 2];
        v.w = Os[(size_t)d * 132 + i4 + 3];
        *(float4*)(out + (size_t)d * N_SEQ + q0 + i4) = v;
    }
}

// ---------------------------------------------------------------------------
extern "C" void kernel_launch(void* const* d_in, const int* in_sizes, int n_in,
                              void* d_out, int out_size)
{
    const float* x     = (const float*)d_in[0];  // [8,512,2048]
    const float* w_qkv = (const float*)d_in[1];  // [1536,512]
    const float* w_out = (const float*)d_in[2];  // [512,512]
    const float* b_out = (const float*)d_in[3];  // [512]
    float* y = (float*)d_out;

    float* qkv = nullptr;
    float* att = nullptr;
    cudaGetSymbolAddress((void**)&qkv, g_qkv);
    cudaGetSymbolAddress((void**)&att, g_att);

    // 1) qkv = w_qkv @ x
    gemm_tf32<<<dim3(N_SEQ / 128, QKV_ROWS / 128, BATCH), 256>>>(
        w_qkv, x, qkv, nullptr, QKV_ROWS, N_SEQ, C_DIM);

    // 2) fused flash attention (tf32 tensor cores)
    const int fsm = FLASH_SMEM_WORDS * 4;
    cudaFuncSetAttribute(flash_tf32,
                         cudaFuncAttributeMaxDynamicSharedMemorySize, fsm);
    flash_tf32<<<dim3(N_SEQ / 128, HEADS, BATCH), 256, fsm>>>(qkv, att);

    // 3) y = w_out @ att + b_out
    gemm_tf32<<<dim3(N_SEQ / 128, HIDDEN / 128, BATCH), 256>>>(
        w_out, att, y, b_out, HIDDEN, N_SEQ, C_DIM);
}

// round 3
// speedup vs baseline: 2.8796x; 1.0011x over previous
#include <cuda_runtime.h>
#include <stdint.h>

#define BATCH    8
#define C_DIM    512
#define N_SEQ    2048
#define HEADS    8
#define QKV_ROWS 1536
#define HIDDEN   512
// 0.125 (=dhead^-0.5) * log2(e): softmax run in exp2 domain
#define SM_SCALE_LOG2 0.18033688011112042f

__device__ float g_qkv[(size_t)BATCH * QKV_ROWS * N_SEQ];   // [b][1536][2048]
__device__ float g_att[(size_t)BATCH * HIDDEN * N_SEQ];     // [b][512][2048]

__device__ __forceinline__ uint32_t f2tf(float f) {
    uint32_t r; asm("cvt.rna.tf32.f32 %0, %1;" : "=r"(r) : "f"(f)); return r;
}
__device__ __forceinline__ float ex2(float x) {
    float r; asm("ex2.approx.f32 %0, %1;" : "=f"(r) : "f"(x)); return r;
}
// D += A(16x8,row) * B(8x8,col), tf32, fp32 accum
__device__ __forceinline__ void mma8(float* c, const uint32_t* a, const uint32_t* b) {
    asm volatile(
        "mma.sync.aligned.m16n8k8.row.col.f32.tf32.tf32.f32 "
        "{%0,%1,%2,%3},{%4,%5,%6,%7},{%8,%9},{%0,%1,%2,%3};"
        : "+f"(c[0]), "+f"(c[1]), "+f"(c[2]), "+f"(c[3])
        : "r"(a[0]), "r"(a[1]), "r"(a[2]), "r"(a[3]), "r"(b[0]), "r"(b[1]));
}

// ---------------------------------------------------------------------------
// tf32 GEMM: C[b] = A[M,K] @ B[b][K,N] (+bias). Block 128x128, BK=32.
// 8 warps in 2x4 grid, each warp 64x32 (4 m-tiles x 4 n-tiles of m16n8k8).
// ---------------------------------------------------------------------------
#define ASTR 36    // As[128][36]: frag bank = 4*g + t  (conflict-free)
#define BSTR 136   // Bs[32][136]: frag bank = 8*t + g  (conflict-free)

__global__ __launch_bounds__(256, 2) void gemm_tf32(
    const float* __restrict__ A, const float* __restrict__ Bg,
    float* __restrict__ Cg, const float* __restrict__ bias,
    int M, int N, int K)
{
    __shared__ uint32_t As[128 * ASTR];
    __shared__ uint32_t Bs[32 * BSTR];

    const float* B = Bg + (size_t)blockIdx.z * K * N;
    float*       C = Cg + (size_t)blockIdx.z * M * N;
    const int brow = blockIdx.y * 128;
    const int bcol = blockIdx.x * 128;
    const int tid  = threadIdx.x;
    const int lane = tid & 31;
    const int w    = tid >> 5;
    const int wm   = (w >> 2) * 64;
    const int wn   = (w & 3) * 32;
    const int g    = lane >> 2;
    const int t    = lane & 3;

    float acc[4][4][4];
#pragma unroll
    for (int mt = 0; mt < 4; mt++)
#pragma unroll
        for (int nt = 0; nt < 4; nt++)
#pragma unroll
            for (int c = 0; c < 4; c++) acc[mt][nt][c] = 0.f;

    for (int k0 = 0; k0 < K; k0 += 32) {
        // stage A tile [128m][32k]
#pragma unroll
        for (int r = 0; r < 4; r++) {
            int idx = tid + 256 * r;
            int m = idx >> 3, k4 = (idx & 7) * 4;
            float4 v = *(const float4*)(A + (size_t)(brow + m) * K + k0 + k4);
            uint32_t* p = &As[m * ASTR + k4];
            p[0] = f2tf(v.x); p[1] = f2tf(v.y); p[2] = f2tf(v.z); p[3] = f2tf(v.w);
        }
        // stage B tile [32k][128n]
#pragma unroll
        for (int r = 0; r < 4; r++) {
            int idx = tid + 256 * r;
            int kk = idx >> 5, n4 = (idx & 31) * 4;
            float4 v = *(const float4*)(B + (size_t)(k0 + kk) * N + bcol + n4);
            uint32_t* p = &Bs[kk * BSTR + n4];
            p[0] = f2tf(v.x); p[1] = f2tf(v.y); p[2] = f2tf(v.z); p[3] = f2tf(v.w);
        }
        __syncthreads();

#pragma unroll
        for (int kc = 0; kc < 4; kc++) {
            const int k8 = kc * 8;
            uint32_t af[4][4], bf[4][2];
#pragma unroll
            for (int mt = 0; mt < 4; mt++) {
                const int r0 = wm + mt * 16 + g;
                af[mt][0] = As[r0 * ASTR + k8 + t];
                af[mt][1] = As[(r0 + 8) * ASTR + k8 + t];
                af[mt][2] = As[r0 * ASTR + k8 + t + 4];
                af[mt][3] = As[(r0 + 8) * ASTR + k8 + t + 4];
            }
#pragma unroll
            for (int nt = 0; nt < 4; nt++) {
                const int c0 = wn + nt * 8 + g;
                bf[nt][0] = Bs[(k8 + t) * BSTR + c0];
                bf[nt][1] = Bs[(k8 + t + 4) * BSTR + c0];
            }
#pragma unroll
            for (int mt = 0; mt < 4; mt++)
#pragma unroll
                for (int nt = 0; nt < 4; nt++)
                    mma8(acc[mt][nt], af[mt], bf[nt]);
        }
        __syncthreads();
    }

#pragma unroll
    for (int mt = 0; mt < 4; mt++) {
        const int r0 = brow + wm + mt * 16 + g;
        const float b0 = bias ? bias[r0] : 0.f;
        const float b1 = bias ? bias[r0 + 8] : 0.f;
#pragma unroll
        for (int nt = 0; nt < 4; nt++) {
            const int c = bcol + wn + nt * 8 + 2 * t;
            float2 v0 = make_float2(acc[mt][nt][0] + b0, acc[mt][nt][1] + b0);
            float2 v1 = make_float2(acc[mt][nt][2] + b1, acc[mt][nt][3] + b1);
            *(float2*)(C + (size_t)r0 * N + c)       = v0;
            *(float2*)(C + (size_t)(r0 + 8) * N + c) = v1;
        }
    }
}

// ---------------------------------------------------------------------------
// tf32 flash attention. Block = (b, h, 128 queries). 8 warps, each owns 16 q
// rows. Key tiles of 64. Online softmax in exp2 domain. P round-trips smem
// as tf32 (warp-private rows). Output staged in smem for coalesced [d][i].
// ---------------------------------------------------------------------------
#define QSTR 68    // Qs/Ps [128][68]
#define KSTR 72    // Ks/Vt [64][72]
#define FLASH_SMEM_WORDS (128 * QSTR + 64 * KSTR + 64 * KSTR + 128 * QSTR)

__global__ __launch_bounds__(256, 2) void flash_tf32(
    const float* __restrict__ qkv, float* __restrict__ outp)
{
    extern __shared__ uint32_t sm[];
    uint32_t* Qs = sm;                   // [i][d] tf32
    uint32_t* Ks = Qs + 128 * QSTR;      // [d][j] tf32
    uint32_t* Vt = Ks + 64 * KSTR;       // [j][d] tf32
    uint32_t* Ps = Vt + 64 * KSTR;       // [i][j] tf32 (reused as Os float[64][132])

    const int b  = blockIdx.z;
    const int h  = blockIdx.y;
    const int q0 = blockIdx.x * 128;
    const float* Q  = qkv + ((size_t)b * QKV_ROWS + h * 64) * N_SEQ;
    const float* Kp = Q + (size_t)512 * N_SEQ;
    const float* Vp = Q + (size_t)1024 * N_SEQ;

    const int tid  = threadIdx.x;
    const int lane = tid & 31;
    const int w    = tid >> 5;
    const int g    = lane >> 2;
    const int t    = lane & 3;
    const int r0   = w * 16 + g;     // this thread's q rows (local)
    const int r1   = r0 + 8;

    // Load Q [d][i] -> Qs[i][d] (transposed), tf32
#pragma unroll
    for (int r = 0; r < 8; r++) {
        int idx = tid + 256 * r;
        int d = idx >> 5, i4 = (idx & 31) * 4;
        float4 v = *(const float4*)(Q + (size_t)d * N_SEQ + q0 + i4);
        Qs[(i4 + 0) * QSTR + d] = f2tf(v.x);
        Qs[(i4 + 1) * QSTR + d] = f2tf(v.y);
        Qs[(i4 + 2) * QSTR + d] = f2tf(v.z);
        Qs[(i4 + 3) * QSTR + d] = f2tf(v.w);
    }

    float o[8][4];
#pragma unroll
    for (int dt = 0; dt < 8; dt++)
#pragma unroll
        for (int c = 0; c < 4; c++) o[dt][c] = 0.f;
    float m0 = -1e30f, m1 = -1e30f, l0 = 0.f, l1 = 0.f;

    for (int j0 = 0; j0 < N_SEQ; j0 += 64) {
        __syncthreads();   // previous tile's Ks/Vt readers done
        // Load K [d][j] -> Ks[d][j]; V [d][j] -> Vt[j][d]
#pragma unroll
        for (int r = 0; r < 4; r++) {
            int idx = tid + 256 * r;
            int d = idx >> 4, j4 = (idx & 15) * 4;
            float4 kv = *(const float4*)(Kp + (size_t)d * N_SEQ + j0 + j4);
            uint32_t* p = &Ks[d * KSTR + j4];
            p[0] = f2tf(kv.x); p[1] = f2tf(kv.y); p[2] = f2tf(kv.z); p[3] = f2tf(kv.w);
            float4 vv = *(const float4*)(Vp + (size_t)d * N_SEQ + j0 + j4);
            Vt[(j4 + 0) * KSTR + d] = f2tf(vv.x);
            Vt[(j4 + 1) * KSTR + d] = f2tf(vv.y);
            Vt[(j4 + 2) * KSTR + d] = f2tf(vv.z);
            Vt[(j4 + 3) * KSTR + d] = f2tf(vv.w);
        }
        __syncthreads();

        // S = Q^T K  (M = 16 q rows of this warp, N = 64 keys, K = 64 dims)
        float s[8][4];
#pragma unroll
        for (int nt = 0; nt < 8; nt++)
#pragma unroll
            for (int c = 0; c < 4; c++) s[nt][c] = 0.f;
#pragma unroll
        for (int kc = 0; kc < 8; kc++) {
            const int d8 = kc * 8;
            uint32_t a[4];
            a[0] = Qs[r0 * QSTR + d8 + t];
            a[1] = Qs[r1 * QSTR + d8 + t];
            a[2] = Qs[r0 * QSTR + d8 + t + 4];
            a[3] = Qs[r1 * QSTR + d8 + t + 4];
#pragma unroll
            for (int nt = 0; nt < 8; nt++) {
                uint32_t bb[2];
                bb[0] = Ks[(d8 + t) * KSTR + nt * 8 + g];
                bb[1] = Ks[(d8 + t + 4) * KSTR + nt * 8 + g];
                mma8(s[nt], a, bb);
            }
        }

        // scale into exp2 domain + row max
        float mx0 = -1e30f, mx1 = -1e30f;
#pragma unroll
        for (int nt = 0; nt < 8; nt++) {
            s[nt][0] *= SM_SCALE_LOG2; s[nt][1] *= SM_SCALE_LOG2;
            s[nt][2] *= SM_SCALE_LOG2; s[nt][3] *= SM_SCALE_LOG2;
            mx0 = fmaxf(mx0, fmaxf(s[nt][0], s[nt][1]));
            mx1 = fmaxf(mx1, fmaxf(s[nt][2], s[nt][3]));
        }
        mx0 = fmaxf(mx0, __shfl_xor_sync(0xffffffffu, mx0, 1));
        mx0 = fmaxf(mx0, __shfl_xor_sync(0xffffffffu, mx0, 2));
        mx1 = fmaxf(mx1, __shfl_xor_sync(0xffffffffu, mx1, 1));
        mx1 = fmaxf(mx1, __shfl_xor_sync(0xffffffffu, mx1, 2));

        const float nm0 = fmaxf(m0, mx0), nm1 = fmaxf(m1, mx1);
        const float al0 = ex2(m0 - nm0),  al1 = ex2(m1 - nm1);

        float ps0 = 0.f, ps1 = 0.f;
#pragma unroll
        for (int nt = 0; nt < 8; nt++) {
            float p0 = ex2(s[nt][0] - nm0);
            float p1 = ex2(s[nt][1] - nm0);
            float p2 = ex2(s[nt][2] - nm1);
            float p3 = ex2(s[nt][3] - nm1);
            ps0 += p0 + p1; ps1 += p2 + p3;
            uint2 u0 = make_uint2(f2tf(p0), f2tf(p1));
            uint2 u1 = make_uint2(f2tf(p2), f2tf(p3));
            *(uint2*)&Ps[r0 * QSTR + nt * 8 + 2 * t] = u0;
            *(uint2*)&Ps[r1 * QSTR + nt * 8 + 2 * t] = u1;
        }
        ps0 += __shfl_xor_sync(0xffffffffu, ps0, 1);
        ps0 += __shfl_xor_sync(0xffffffffu, ps0, 2);
        ps1 += __shfl_xor_sync(0xffffffffu, ps1, 1);
        ps1 += __shfl_xor_sync(0xffffffffu, ps1, 2);
        l0 = l0 * al0 + ps0; l1 = l1 * al1 + ps1;
        m0 = nm0; m1 = nm1;

        // rescale O
#pragma unroll
        for (int dt = 0; dt < 8; dt++) {
            o[dt][0] *= al0; o[dt][1] *= al0;
            o[dt][2] *= al1; o[dt][3] *= al1;
        }
        __syncwarp();   // Ps rows written by this warp, read cross-lane below

        // O += P @ V  (M = 16 q rows, N = 64 dims, K = 64 keys)
#pragma unroll
        for (int kc = 0; kc < 8; kc++) {
            const int j8 = kc * 8;
            uint32_t a[4];
            a[0] = Ps[r0 * QSTR + j8 + t];
            a[1] = Ps[r1 * QSTR + j8 + t];
            a[2] = Ps[r0 * QSTR + j8 + t + 4];
            a[3] = Ps[r1 * QSTR + j8 + t + 4];
#pragma unroll
            for (int dt = 0; dt < 8; dt++) {
                uint32_t bb[2];
                bb[0] = Vt[(j8 + t) * KSTR + dt * 8 + g];
                bb[1] = Vt[(j8 + t + 4) * KSTR + dt * 8 + g];
                mma8(o[dt], a, bb);
            }
        }
    }

    __syncthreads();   // all Ps readers done; reuse as Os[64][132] float
    float* Os = (float*)Ps;
    const float inv0 = 1.f / l0, inv1 = 1.f / l1;
#pragma unroll
    for (int dt = 0; dt < 8; dt++) {
        const int d = dt * 8 + 2 * t;
        Os[(size_t)d * 132 + r0]       = o[dt][0] * inv0;
        Os[(size_t)(d + 1) * 132 + r0] = o[dt][1] * inv0;
        Os[(size_t)d * 132 + r1]       = o[dt][2] * inv1;
        Os[(size_t)(d + 1) * 132 + r1] = o[dt][3] * inv1;
    }
    __syncthreads();

    float* out = outp + ((size_t)b * HIDDEN + h * 64) * N_SEQ;
#pragma unroll
    for (int r = 0; r < 8; r++) {
        int idx = tid + 256 * r;
        int d = idx >> 5, i4 = (idx & 31) * 4;
        float4 v;
        v.x = Os[(size_t)d * 132 + i4 + 0];
        v.y = Os[(size_t)d * 132 + i4 + 1];
        v.z = Os[(size_t)d * 132 + i4 + 2];
        v.w = Os[(size_t)d * 132 + i4 + 3];
        *(float4*)(out + (size_t)d * N_SEQ + q0 + i4) = v;
    }
}

// ---------------------------------------------------------------------------
extern "C" void kernel_launch(void* const* d_in, const int* in_sizes, int n_in,
                              void* d_out, int out_size)
{
    const float* x     = (const float*)d_in[0];  // [8,512,2048]
    const float* w_qkv = (const float*)d_in[1];  // [1536,512]
    const float* w_out = (const float*)d_in[2];  // [512,512]
    const float* b_out = (const float*)d_in[3];  // [512]
    float* y = (float*)d_out;

    float* qkv = nullptr;
    float* att = nullptr;
    cudaGetSymbolAddress((void**)&qkv, g_qkv);
    cudaGetSymbolAddress((void**)&att, g_att);

    // 1) qkv = w_qkv @ x
    gemm_tf32<<<dim3(N_SEQ / 128, QKV_ROWS / 128, BATCH), 256>>>(
        w_qkv, x, qkv, nullptr, QKV_ROWS, N_SEQ, C_DIM);

    // 2) fused flash attention (tf32 tensor cores)
    const int fsm = FLASH_SMEM_WORDS * 4;
    cudaFuncSetAttribute(flash_tf32,
                         cudaFuncAttributeMaxDynamicSharedMemorySize, fsm);
    flash_tf32<<<dim3(N_SEQ / 128, HEADS, BATCH), 256, fsm>>>(qkv, att);

    // 3) y = w_out @ att + b_out
    gemm_tf32<<<dim3(N_SEQ / 128, HIDDEN / 128, BATCH), 256>>>(
        w_out, att, y, b_out, HIDDEN, N_SEQ, C_DIM);
}

// round 4
// speedup vs baseline: 3.5627x; 1.2372x over previous
#include <cuda_runtime.h>
#include <stdint.h>

#define BATCH    8
#define C_DIM    512
#define N_SEQ    2048
#define HEADS    8
#define QKV_ROWS 1536
#define HIDDEN   512
#define SM_SCALE_LOG2 0.18033688011112042f  // dhead^-0.5 * log2(e)

__device__ float g_qkv[(size_t)BATCH * QKV_ROWS * N_SEQ];
__device__ float g_att[(size_t)BATCH * HIDDEN * N_SEQ];

__device__ __forceinline__ uint32_t f2tf(float f) {
    uint32_t r; asm("cvt.rna.tf32.f32 %0, %1;" : "=r"(r) : "f"(f)); return r;
}
__device__ __forceinline__ float ex2(float x) {
    float r; asm("ex2.approx.f32 %0, %1;" : "=f"(r) : "f"(x)); return r;
}
__device__ __forceinline__ void mma8(float* c, const uint32_t* a, const uint32_t* b) {
    asm volatile(
        "mma.sync.aligned.m16n8k8.row.col.f32.tf32.tf32.f32 "
        "{%0,%1,%2,%3},{%4,%5,%6,%7},{%8,%9},{%0,%1,%2,%3};"
        : "+f"(c[0]), "+f"(c[1]), "+f"(c[2]), "+f"(c[3])
        : "r"(a[0]), "r"(a[1]), "r"(a[2]), "r"(a[3]), "r"(b[0]), "r"(b[1]));
}

// ---------------- tf32 GEMM (unchanged from R2) ----------------
#define ASTR 36
#define BSTR 136

__global__ __launch_bounds__(256, 2) void gemm_tf32(
    const float* __restrict__ A, const float* __restrict__ Bg,
    float* __restrict__ Cg, const float* __restrict__ bias,
    int M, int N, int K)
{
    __shared__ uint32_t As[128 * ASTR];
    __shared__ uint32_t Bs[32 * BSTR];

    const float* B = Bg + (size_t)blockIdx.z * K * N;
    float*       C = Cg + (size_t)blockIdx.z * M * N;
    const int brow = blockIdx.y * 128;
    const int bcol = blockIdx.x * 128;
    const int tid  = threadIdx.x;
    const int lane = tid & 31;
    const int w    = tid >> 5;
    const int wm   = (w >> 2) * 64;
    const int wn   = (w & 3) * 32;
    const int g    = lane >> 2;
    const int t    = lane & 3;

    float acc[4][4][4];
#pragma unroll
    for (int mt = 0; mt < 4; mt++)
#pragma unroll
        for (int nt = 0; nt < 4; nt++)
#pragma unroll
            for (int c = 0; c < 4; c++) acc[mt][nt][c] = 0.f;

    for (int k0 = 0; k0 < K; k0 += 32) {
#pragma unroll
        for (int r = 0; r < 4; r++) {
            int idx = tid + 256 * r;
            int m = idx >> 3, k4 = (idx & 7) * 4;
            float4 v = *(const float4*)(A + (size_t)(brow + m) * K + k0 + k4);
            uint32_t* p = &As[m * ASTR + k4];
            p[0] = f2tf(v.x); p[1] = f2tf(v.y); p[2] = f2tf(v.z); p[3] = f2tf(v.w);
        }
#pragma unroll
        for (int r = 0; r < 4; r++) {
            int idx = tid + 256 * r;
            int kk = idx >> 5, n4 = (idx & 31) * 4;
            float4 v = *(const float4*)(B + (size_t)(k0 + kk) * N + bcol + n4);
            *(uint4*)&Bs[kk * BSTR + n4] =
                make_uint4(f2tf(v.x), f2tf(v.y), f2tf(v.z), f2tf(v.w));
        }
        __syncthreads();

#pragma unroll
        for (int kc = 0; kc < 4; kc++) {
            const int k8 = kc * 8;
            uint32_t af[4][4], bf[4][2];
#pragma unroll
            for (int mt = 0; mt < 4; mt++) {
                const int r0 = wm + mt * 16 + g;
                af[mt][0] = As[r0 * ASTR + k8 + t];
                af[mt][1] = As[(r0 + 8) * ASTR + k8 + t];
                af[mt][2] = As[r0 * ASTR + k8 + t + 4];
                af[mt][3] = As[(r0 + 8) * ASTR + k8 + t + 4];
            }
#pragma unroll
            for (int nt = 0; nt < 4; nt++) {
                const int c0 = wn + nt * 8 + g;
                bf[nt][0] = Bs[(k8 + t) * BSTR + c0];
                bf[nt][1] = Bs[(k8 + t + 4) * BSTR + c0];
            }
#pragma unroll
            for (int mt = 0; mt < 4; mt++)
#pragma unroll
                for (int nt = 0; nt < 4; nt++)
                    mma8(acc[mt][nt], af[mt], bf[nt]);
        }
        __syncthreads();
    }

#pragma unroll
    for (int mt = 0; mt < 4; mt++) {
        const int r0 = brow + wm + mt * 16 + g;
        const float b0 = bias ? bias[r0] : 0.f;
        const float b1 = bias ? bias[r0 + 8] : 0.f;
#pragma unroll
        for (int nt = 0; nt < 4; nt++) {
            const int c = bcol + wn + nt * 8 + 2 * t;
            *(float2*)(C + (size_t)r0 * N + c) =
                make_float2(acc[mt][nt][0] + b0, acc[mt][nt][1] + b0);
            *(float2*)(C + (size_t)(r0 + 8) * N + c) =
                make_float2(acc[mt][nt][2] + b1, acc[mt][nt][3] + b1);
        }
    }
}

// ---------------- tf32 flash attention ----------------
// Staging now via register transpose: conflict-free wide smem stores.
#define QSTR 68
#define KSTR 72
#define FLASH_SMEM_WORDS (128 * QSTR + 64 * KSTR + 64 * KSTR + 128 * QSTR)

__global__ __launch_bounds__(256, 2) void flash_tf32(
    const float* __restrict__ qkv, float* __restrict__ outp)
{
    extern __shared__ uint32_t sm[];
    uint32_t* Qs = sm;                   // [i][d] tf32 (pre-scaled)
    uint32_t* Ks = Qs + 128 * QSTR;      // [d][j] tf32
    uint32_t* Vt = Ks + 64 * KSTR;       // [j][d] tf32
    uint32_t* Ps = Vt + 64 * KSTR;       // [i][j] tf32; reused as Os float[64][132]

    const int b  = blockIdx.z;
    const int h  = blockIdx.y;
    const int q0 = blockIdx.x * 128;
    const float* Q  = qkv + ((size_t)b * QKV_ROWS + h * 64) * N_SEQ;
    const float* Kp = Q + (size_t)512 * N_SEQ;
    const float* Vp = Q + (size_t)1024 * N_SEQ;

    const int tid  = threadIdx.x;
    const int lane = tid & 31;
    const int w    = tid >> 5;
    const int g    = lane >> 2;
    const int t    = lane & 3;
    const int r0   = w * 16 + g;
    const int r1   = r0 + 8;

    // Q staging: register transpose, scale baked in. Task (i, grp of 8 dims).
    // Store banks 4i+... conflict-free (QSTR=68).
#pragma unroll
    for (int u = 0; u < 4; u++) {
        int idx = u * 256 + tid;
        int i = idx & 127, grp = idx >> 7;
        const float* qp = Q + (size_t)(grp * 8) * N_SEQ + q0 + i;
        uint32_t v[8];
#pragma unroll
        for (int c = 0; c < 8; c++)
            v[c] = f2tf(qp[(size_t)c * N_SEQ] * SM_SCALE_LOG2);
        *(uint4*)&Qs[i * QSTR + grp * 8]     = make_uint4(v[0], v[1], v[2], v[3]);
        *(uint4*)&Qs[i * QSTR + grp * 8 + 4] = make_uint4(v[4], v[5], v[6], v[7]);
    }

    float o[8][4];
#pragma unroll
    for (int dt = 0; dt < 8; dt++)
#pragma unroll
        for (int c = 0; c < 4; c++) o[dt][c] = 0.f;
    float m0 = -1e30f, m1 = -1e30f, l0 = 0.f, l1 = 0.f;

    for (int j0 = 0; j0 < N_SEQ; j0 += 64) {
        __syncthreads();

        // K staging [d][j]: ST.128, conflict-free
#pragma unroll
        for (int r = 0; r < 4; r++) {
            int idx = tid + 256 * r;
            int d = idx >> 4, j4 = (idx & 15) * 4;
            float4 kv = *(const float4*)(Kp + (size_t)d * N_SEQ + j0 + j4);
            *(uint4*)&Ks[d * KSTR + j4] =
                make_uint4(f2tf(kv.x), f2tf(kv.y), f2tf(kv.z), f2tf(kv.w));
        }
        // V staging: register transpose -> Vt[j][d], 2x ST.128 (2-way max)
#pragma unroll
        for (int u = 0; u < 2; u++) {
            int idx = u * 256 + tid;
            int j = idx & 63, grp = idx >> 6;
            const float* vp = Vp + (size_t)(grp * 8) * N_SEQ + j0 + j;
            uint32_t v[8];
#pragma unroll
            for (int c = 0; c < 8; c++) v[c] = f2tf(vp[(size_t)c * N_SEQ]);
            *(uint4*)&Vt[j * KSTR + grp * 8]     = make_uint4(v[0], v[1], v[2], v[3]);
            *(uint4*)&Vt[j * KSTR + grp * 8 + 4] = make_uint4(v[4], v[5], v[6], v[7]);
        }
        __syncthreads();

        // S = Q @ K  (16 q rows x 64 keys, K=64 dims)
        float s[8][4];
#pragma unroll
        for (int nt = 0; nt < 8; nt++)
#pragma unroll
            for (int c = 0; c < 4; c++) s[nt][c] = 0.f;
#pragma unroll
        for (int kc = 0; kc < 8; kc++) {
            const int d8 = kc * 8;
            uint32_t a[4];
            a[0] = Qs[r0 * QSTR + d8 + t];
            a[1] = Qs[r1 * QSTR + d8 + t];
            a[2] = Qs[r0 * QSTR + d8 + t + 4];
            a[3] = Qs[r1 * QSTR + d8 + t + 4];
#pragma unroll
            for (int nt = 0; nt < 8; nt++) {
                uint32_t bb[2];
                bb[0] = Ks[(d8 + t) * KSTR + nt * 8 + g];
                bb[1] = Ks[(d8 + t + 4) * KSTR + nt * 8 + g];
                mma8(s[nt], a, bb);
            }
        }

        // online softmax (exp2 domain; scale already in Q)
        float mx0 = -1e30f, mx1 = -1e30f;
#pragma unroll
        for (int nt = 0; nt < 8; nt++) {
            mx0 = fmaxf(mx0, fmaxf(s[nt][0], s[nt][1]));
            mx1 = fmaxf(mx1, fmaxf(s[nt][2], s[nt][3]));
        }
        mx0 = fmaxf(mx0, __shfl_xor_sync(0xffffffffu, mx0, 1));
        mx0 = fmaxf(mx0, __shfl_xor_sync(0xffffffffu, mx0, 2));
        mx1 = fmaxf(mx1, __shfl_xor_sync(0xffffffffu, mx1, 1));
        mx1 = fmaxf(mx1, __shfl_xor_sync(0xffffffffu, mx1, 2));

        const float nm0 = fmaxf(m0, mx0), nm1 = fmaxf(m1, mx1);
        const float al0 = ex2(m0 - nm0),  al1 = ex2(m1 - nm1);

        float ps0 = 0.f, ps1 = 0.f;
#pragma unroll
        for (int nt = 0; nt < 8; nt++) {
            float p0 = ex2(s[nt][0] - nm0);
            float p1 = ex2(s[nt][1] - nm0);
            float p2 = ex2(s[nt][2] - nm1);
            float p3 = ex2(s[nt][3] - nm1);
            ps0 += p0 + p1; ps1 += p2 + p3;
            *(uint2*)&Ps[r0 * QSTR + nt * 8 + 2 * t] = make_uint2(f2tf(p0), f2tf(p1));
            *(uint2*)&Ps[r1 * QSTR + nt * 8 + 2 * t] = make_uint2(f2tf(p2), f2tf(p3));
        }
        ps0 += __shfl_xor_sync(0xffffffffu, ps0, 1);
        ps0 += __shfl_xor_sync(0xffffffffu, ps0, 2);
        ps1 += __shfl_xor_sync(0xffffffffu, ps1, 1);
        ps1 += __shfl_xor_sync(0xffffffffu, ps1, 2);
        l0 = l0 * al0 + ps0; l1 = l1 * al1 + ps1;
        m0 = nm0; m1 = nm1;

#pragma unroll
        for (int dt = 0; dt < 8; dt++) {
            o[dt][0] *= al0; o[dt][1] *= al0;
            o[dt][2] *= al1; o[dt][3] *= al1;
        }
        __syncwarp();

        // O += P @ V  (16 q rows x 64 dims, K=64 keys)
#pragma unroll
        for (int kc = 0; kc < 8; kc++) {
            const int j8 = kc * 8;
            uint32_t a[4];
            a[0] = Ps[r0 * QSTR + j8 + t];
            a[1] = Ps[r1 * QSTR + j8 + t];
            a[2] = Ps[r0 * QSTR + j8 + t + 4];
            a[3] = Ps[r1 * QSTR + j8 + t + 4];
#pragma unroll
            for (int dt = 0; dt < 8; dt++) {
                uint32_t bb[2];
                bb[0] = Vt[(j8 + t) * KSTR + dt * 8 + g];
                bb[1] = Vt[(j8 + t + 4) * KSTR + dt * 8 + g];
                mma8(o[dt], a, bb);
            }
        }
    }

    __syncthreads();
    float* Os = (float*)Ps;   // [64 d][132] staging
    const float inv0 = 1.f / l0, inv1 = 1.f / l1;
#pragma unroll
    for (int dt = 0; dt < 8; dt++) {
        const int d = dt * 8 + 2 * t;
        Os[(size_t)d * 132 + r0]       = o[dt][0] * inv0;
        Os[(size_t)(d + 1) * 132 + r0] = o[dt][1] * inv0;
        Os[(size_t)d * 132 + r1]       = o[dt][2] * inv1;
        Os[(size_t)(d + 1) * 132 + r1] = o[dt][3] * inv1;
    }
    __syncthreads();

    float* out = outp + ((size_t)b * HIDDEN + h * 64) * N_SEQ;
#pragma unroll
    for (int r = 0; r < 8; r++) {
        int idx = tid + 256 * r;
        int d = idx >> 5, i4 = (idx & 31) * 4;
        float4 v;
        v.x = Os[(size_t)d * 132 + i4 + 0];
        v.y = Os[(size_t)d * 132 + i4 + 1];
        v.z = Os[(size_t)d * 132 + i4 + 2];
        v.w = Os[(size_t)d * 132 + i4 + 3];
        *(float4*)(out + (size_t)d * N_SEQ + q0 + i4) = v;
    }
}

// ---------------------------------------------------------------------------
extern "C" void kernel_launch(void* const* d_in, const int* in_sizes, int n_in,
                              void* d_out, int out_size)
{
    const float* x     = (const float*)d_in[0];
    const float* w_qkv = (const float*)d_in[1];
    const float* w_out = (const float*)d_in[2];
    const float* b_out = (const float*)d_in[3];
    float* y = (float*)d_out;

    float* qkv = nullptr;
    float* att = nullptr;
    cudaGetSymbolAddress((void**)&qkv, g_qkv);
    cudaGetSymbolAddress((void**)&att, g_att);

    gemm_tf32<<<dim3(N_SEQ / 128, QKV_ROWS / 128, BATCH), 256>>>(
        w_qkv, x, qkv, nullptr, QKV_ROWS, N_SEQ, C_DIM);

    const int fsm = FLASH_SMEM_WORDS * 4;
    cudaFuncSetAttribute(flash_tf32,
                         cudaFuncAttributeMaxDynamicSharedMemorySize, fsm);
    flash_tf32<<<dim3(N_SEQ / 128, HEADS, BATCH), 256, fsm>>>(qkv, att);

    gemm_tf32<<<dim3(N_SEQ / 128, HIDDEN / 128, BATCH), 256>>>(
        w_out, att, y, b_out, HIDDEN, N_SEQ, C_DIM);
}

// round 5
// speedup vs baseline: 3.7553x; 1.0541x over previous
#include <cuda_runtime.h>
#include <stdint.h>

#define BATCH    8
#define C_DIM    512
#define N_SEQ    2048
#define HEADS    8
#define QKV_ROWS 1536
#define HIDDEN   512
#define SM_SCALE_LOG2 0.18033688011112042f  // dhead^-0.5 * log2(e)

__device__ float g_qkv[(size_t)BATCH * QKV_ROWS * N_SEQ];
__device__ float g_att[(size_t)BATCH * HIDDEN * N_SEQ];

__device__ __forceinline__ uint32_t f2tf(float f) {
    uint32_t r; asm("cvt.rna.tf32.f32 %0, %1;" : "=r"(r) : "f"(f)); return r;
}
__device__ __forceinline__ float ex2(float x) {
    float r; asm("ex2.approx.f32 %0, %1;" : "=f"(r) : "f"(x)); return r;
}
__device__ __forceinline__ void mma8(float* c, const uint32_t* a, const uint32_t* b) {
    asm volatile(
        "mma.sync.aligned.m16n8k8.row.col.f32.tf32.tf32.f32 "
        "{%0,%1,%2,%3},{%4,%5,%6,%7},{%8,%9},{%0,%1,%2,%3};"
        : "+f"(c[0]), "+f"(c[1]), "+f"(c[2]), "+f"(c[3])
        : "r"(a[0]), "r"(a[1]), "r"(a[2]), "r"(a[3]), "r"(b[0]), "r"(b[1]));
}

// ---------------- tf32 GEMM: perm-pair A layout (LDS.64 A-frags) ----------------
#define ASTR 40    // As[128][40], pairs (k,k+4) adjacent; LDS.64 banks 8g+2t CF
#define BSTR 136   // Bs[32][136]: frag bank 8t+g conflict-free

__global__ __launch_bounds__(256, 2) void gemm_tf32(
    const float* __restrict__ A, const float* __restrict__ Bg,
    float* __restrict__ Cg, const float* __restrict__ bias,
    int M, int N, int K)
{
    __shared__ uint32_t As[128 * ASTR];
    __shared__ uint32_t Bs[32 * BSTR];

    const float* B = Bg + (size_t)blockIdx.z * K * N;
    float*       C = Cg + (size_t)blockIdx.z * M * N;
    const int brow = blockIdx.y * 128;
    const int bcol = blockIdx.x * 128;
    const int tid  = threadIdx.x;
    const int lane = tid & 31;
    const int w    = tid >> 5;
    const int wm   = (w >> 2) * 64;
    const int wn   = (w & 3) * 32;
    const int g    = lane >> 2;
    const int t    = lane & 3;

    float acc[4][4][4];
#pragma unroll
    for (int mt = 0; mt < 4; mt++)
#pragma unroll
        for (int nt = 0; nt < 4; nt++)
#pragma unroll
            for (int c = 0; c < 4; c++) acc[mt][nt][c] = 0.f;

    for (int k0 = 0; k0 < K; k0 += 32) {
        // A staging: pair (k, k+4) into adjacent slots; ST.64 conflict-free
#pragma unroll
        for (int r = 0; r < 8; r++) {
            int idx = r * 256 + tid;                 // 2048 tasks
            int dp = idx & 3, grp = (idx >> 2) & 3, m = idx >> 4;
            const float* ap = A + (size_t)(brow + m) * K + k0 + grp * 8 + dp;
            *(uint2*)&As[m * ASTR + grp * 8 + 2 * dp] =
                make_uint2(f2tf(ap[0]), f2tf(ap[4]));
        }
#pragma unroll
        for (int r = 0; r < 4; r++) {
            int idx = r * 256 + tid;
            int kk = idx >> 5, n4 = (idx & 31) * 4;
            float4 v = *(const float4*)(B + (size_t)(k0 + kk) * N + bcol + n4);
            *(uint4*)&Bs[kk * BSTR + n4] =
                make_uint4(f2tf(v.x), f2tf(v.y), f2tf(v.z), f2tf(v.w));
        }
        __syncthreads();

#pragma unroll
        for (int kc = 0; kc < 4; kc++) {
            const int k8 = kc * 8;
            uint32_t af[4][4], bf[4][2];
#pragma unroll
            for (int mt = 0; mt < 4; mt++) {
                const int r0 = wm + mt * 16 + g;
                uint2 lo = *(uint2*)&As[r0 * ASTR + k8 + 2 * t];
                uint2 hi = *(uint2*)&As[(r0 + 8) * ASTR + k8 + 2 * t];
                af[mt][0] = lo.x; af[mt][1] = hi.x;
                af[mt][2] = lo.y; af[mt][3] = hi.y;
            }
#pragma unroll
            for (int nt = 0; nt < 4; nt++) {
                const int c0 = wn + nt * 8 + g;
                bf[nt][0] = Bs[(k8 + t) * BSTR + c0];
                bf[nt][1] = Bs[(k8 + t + 4) * BSTR + c0];
            }
#pragma unroll
            for (int mt = 0; mt < 4; mt++)
#pragma unroll
                for (int nt = 0; nt < 4; nt++)
                    mma8(acc[mt][nt], af[mt], bf[nt]);
        }
        __syncthreads();
    }

#pragma unroll
    for (int mt = 0; mt < 4; mt++) {
        const int r0 = brow + wm + mt * 16 + g;
        const float b0 = bias ? bias[r0] : 0.f;
        const float b1 = bias ? bias[r0 + 8] : 0.f;
#pragma unroll
        for (int nt = 0; nt < 4; nt++) {
            const int c = bcol + wn + nt * 8 + 2 * t;
            *(float2*)(C + (size_t)r0 * N + c) =
                make_float2(acc[mt][nt][0] + b0, acc[mt][nt][1] + b0);
            *(float2*)(C + (size_t)(r0 + 8) * N + c) =
                make_float2(acc[mt][nt][2] + b1, acc[mt][nt][3] + b1);
        }
    }
}

// ---------------- tf32 flash attention: 4 warps, m=32 per warp ----------------
#define QSTR 68   // Qs[128][68]: A-frag banks 4g+t CF
#define KSTR 72   // Ks[64][72]:  B-frag banks 8t+g CF
#define VSTR 68   // Vs[64][68]:  B-frag banks 4g+t CF (natural [d][j]!)
#define PSTR 76   // Ps[128][76]: A-frag banks 12g+t CF
#define FLASH_WORDS (128 * QSTR + 64 * KSTR + 64 * VSTR + 128 * PSTR)

__global__ __launch_bounds__(128, 2) void flash_tf32(
    const float* __restrict__ qkv, float* __restrict__ outp)
{
    extern __shared__ uint32_t sm[];
    uint32_t* Qs = sm;                    // [i][d] tf32, pre-scaled
    uint32_t* Ks = Qs + 128 * QSTR;       // [d][j] tf32
    uint32_t* Vs = Ks + 64 * KSTR;        // [d][j] tf32 (natural)
    uint32_t* Ps = Vs + 64 * VSTR;        // [i][j] tf32; reused as Os float[64][132]

    const int b  = blockIdx.z;
    const int h  = blockIdx.y;
    const int q0 = blockIdx.x * 128;
    const float* Q  = qkv + ((size_t)b * QKV_ROWS + h * 64) * N_SEQ;
    const float* Kp = Q + (size_t)512 * N_SEQ;
    const float* Vp = Q + (size_t)1024 * N_SEQ;

    const int tid  = threadIdx.x;        // 128 threads = 4 warps
    const int lane = tid & 31;
    const int w    = tid >> 5;
    const int g    = lane >> 2;
    const int t    = lane & 3;
    const int rb0  = w * 32;             // warp's 32 q rows: [rb0, rb0+32)
    const int rA0  = rb0 + g,      rA1 = rb0 + g + 8;       // m-tile 0
    const int rB0  = rb0 + 16 + g, rB1 = rb0 + 16 + g + 8;  // m-tile 1

    // Q staging: register transpose, scale baked in. Once per block.
#pragma unroll
    for (int grp = 0; grp < 8; grp++) {
        const float* qp = Q + (size_t)(grp * 8) * N_SEQ + q0 + tid;
        uint32_t v[8];
#pragma unroll
        for (int c = 0; c < 8; c++)
            v[c] = f2tf(qp[(size_t)c * N_SEQ] * SM_SCALE_LOG2);
        *(uint4*)&Qs[tid * QSTR + grp * 8]     = make_uint4(v[0], v[1], v[2], v[3]);
        *(uint4*)&Qs[tid * QSTR + grp * 8 + 4] = make_uint4(v[4], v[5], v[6], v[7]);
    }

    float o[2][8][4];
#pragma unroll
    for (int mt = 0; mt < 2; mt++)
#pragma unroll
        for (int dt = 0; dt < 8; dt++)
#pragma unroll
            for (int c = 0; c < 4; c++) o[mt][dt][c] = 0.f;
    float mrow[2][2] = {{-1e30f, -1e30f}, {-1e30f, -1e30f}};
    float lrow[2][2] = {{0.f, 0.f}, {0.f, 0.f}};

    for (int j0 = 0; j0 < N_SEQ; j0 += 64) {
        __syncthreads();
        // Stage K and V, natural [d][j], ST.128 conflict-free
#pragma unroll
        for (int u = 0; u < 8; u++) {
            int idx = u * 128 + tid;
            int d = idx >> 4, j4 = (idx & 15) * 4;
            float4 kv = *(const float4*)(Kp + (size_t)d * N_SEQ + j0 + j4);
            *(uint4*)&Ks[d * KSTR + j4] =
                make_uint4(f2tf(kv.x), f2tf(kv.y), f2tf(kv.z), f2tf(kv.w));
            float4 vv = *(const float4*)(Vp + (size_t)d * N_SEQ + j0 + j4);
            *(uint4*)&Vs[d * VSTR + j4] =
                make_uint4(f2tf(vv.x), f2tf(vv.y), f2tf(vv.z), f2tf(vv.w));
        }
        __syncthreads();

        // S = Q @ K^T : per warp 32 q rows x 64 keys, K=64 dims
        float s[2][8][4];
#pragma unroll
        for (int mt = 0; mt < 2; mt++)
#pragma unroll
            for (int nt = 0; nt < 8; nt++)
#pragma unroll
                for (int c = 0; c < 4; c++) s[mt][nt][c] = 0.f;
#pragma unroll
        for (int kc = 0; kc < 8; kc++) {
            const int d8 = kc * 8;
            uint32_t a0[4], a1[4];
            a0[0] = Qs[rA0 * QSTR + d8 + t];
            a0[1] = Qs[rA1 * QSTR + d8 + t];
            a0[2] = Qs[rA0 * QSTR + d8 + t + 4];
            a0[3] = Qs[rA1 * QSTR + d8 + t + 4];
            a1[0] = Qs[rB0 * QSTR + d8 + t];
            a1[1] = Qs[rB1 * QSTR + d8 + t];
            a1[2] = Qs[rB0 * QSTR + d8 + t + 4];
            a1[3] = Qs[rB1 * QSTR + d8 + t + 4];
#pragma unroll
            for (int nt = 0; nt < 8; nt++) {
                uint32_t bb[2];
                bb[0] = Ks[(d8 + t) * KSTR + nt * 8 + g];
                bb[1] = Ks[(d8 + t + 4) * KSTR + nt * 8 + g];
                mma8(s[0][nt], a0, bb);
                mma8(s[1][nt], a1, bb);
            }
        }

        // online softmax per m-tile (exp2 domain; scale baked into Q)
#pragma unroll
        for (int mt = 0; mt < 2; mt++) {
            const int q0r = (mt == 0) ? rA0 : rB0;
            const int q1r = (mt == 0) ? rA1 : rB1;
            float mx0 = -1e30f, mx1 = -1e30f;
#pragma unroll
            for (int nt = 0; nt < 8; nt++) {
                mx0 = fmaxf(mx0, fmaxf(s[mt][nt][0], s[mt][nt][1]));
                mx1 = fmaxf(mx1, fmaxf(s[mt][nt][2], s[mt][nt][3]));
            }
            mx0 = fmaxf(mx0, __shfl_xor_sync(0xffffffffu, mx0, 1));
            mx0 = fmaxf(mx0, __shfl_xor_sync(0xffffffffu, mx0, 2));
            mx1 = fmaxf(mx1, __shfl_xor_sync(0xffffffffu, mx1, 1));
            mx1 = fmaxf(mx1, __shfl_xor_sync(0xffffffffu, mx1, 2));

            const float nm0 = fmaxf(mrow[mt][0], mx0);
            const float nm1 = fmaxf(mrow[mt][1], mx1);
            const float al0 = ex2(mrow[mt][0] - nm0);
            const float al1 = ex2(mrow[mt][1] - nm1);

            float ps0 = 0.f, ps1 = 0.f;
#pragma unroll
            for (int nt = 0; nt < 8; nt++) {
                float p0 = ex2(s[mt][nt][0] - nm0);
                float p1 = ex2(s[mt][nt][1] - nm0);
                float p2 = ex2(s[mt][nt][2] - nm1);
                float p3 = ex2(s[mt][nt][3] - nm1);
                ps0 += p0 + p1; ps1 += p2 + p3;
                *(uint2*)&Ps[q0r * PSTR + nt * 8 + 2 * t] =
                    make_uint2(f2tf(p0), f2tf(p1));
                *(uint2*)&Ps[q1r * PSTR + nt * 8 + 2 * t] =
                    make_uint2(f2tf(p2), f2tf(p3));
            }
            ps0 += __shfl_xor_sync(0xffffffffu, ps0, 1);
            ps0 += __shfl_xor_sync(0xffffffffu, ps0, 2);
            ps1 += __shfl_xor_sync(0xffffffffu, ps1, 1);
            ps1 += __shfl_xor_sync(0xffffffffu, ps1, 2);
            lrow[mt][0] = lrow[mt][0] * al0 + ps0;
            lrow[mt][1] = lrow[mt][1] * al1 + ps1;
            mrow[mt][0] = nm0; mrow[mt][1] = nm1;

#pragma unroll
            for (int dt = 0; dt < 8; dt++) {
                o[mt][dt][0] *= al0; o[mt][dt][1] *= al0;
                o[mt][dt][2] *= al1; o[mt][dt][3] *= al1;
            }
        }
        __syncwarp();   // Ps rows are warp-private

        // O += P @ V : 32 q rows x 64 dims, K = 64 keys
#pragma unroll
        for (int kc = 0; kc < 8; kc++) {
            const int j8 = kc * 8;
            uint32_t a0[4], a1[4];
            a0[0] = Ps[rA0 * PSTR + j8 + t];
            a0[1] = Ps[rA1 * PSTR + j8 + t];
            a0[2] = Ps[rA0 * PSTR + j8 + t + 4];
            a0[3] = Ps[rA1 * PSTR + j8 + t + 4];
            a1[0] = Ps[rB0 * PSTR + j8 + t];
            a1[1] = Ps[rB1 * PSTR + j8 + t];
            a1[2] = Ps[rB0 * PSTR + j8 + t + 4];
            a1[3] = Ps[rB1 * PSTR + j8 + t + 4];
#pragma unroll
            for (int dt = 0; dt < 8; dt++) {
                uint32_t bv[2];
                bv[0] = Vs[(dt * 8 + g) * VSTR + j8 + t];
                bv[1] = Vs[(dt * 8 + g) * VSTR + j8 + t + 4];
                mma8(o[0][dt], a0, bv);
                mma8(o[1][dt], a1, bv);
            }
        }
    }

    __syncthreads();   // all warps done with Ps; reuse as Os[64 d][132 i]
    float* Os = (float*)Ps;
#pragma unroll
    for (int mt = 0; mt < 2; mt++) {
        const int q0r = (mt == 0) ? rA0 : rB0;
        const int q1r = (mt == 0) ? rA1 : rB1;
        const float inv0 = 1.f / lrow[mt][0];
        const float inv1 = 1.f / lrow[mt][1];
#pragma unroll
        for (int dt = 0; dt < 8; dt++) {
            const int d = dt * 8 + 2 * t;
            Os[(size_t)d * 132 + q0r]       = o[mt][dt][0] * inv0;
            Os[(size_t)(d + 1) * 132 + q0r] = o[mt][dt][1] * inv0;
            Os[(size_t)d * 132 + q1r]       = o[mt][dt][2] * inv1;
            Os[(size_t)(d + 1) * 132 + q1r] = o[mt][dt][3] * inv1;
        }
    }
    __syncthreads();

    float* out = outp + ((size_t)b * HIDDEN + h * 64) * N_SEQ;
#pragma unroll
    for (int u = 0; u < 16; u++) {
        int idx = u * 128 + tid;
        int d = idx >> 5, i4 = (idx & 31) * 4;
        float4 v;
        v.x = Os[(size_t)d * 132 + i4 + 0];
        v.y = Os[(size_t)d * 132 + i4 + 1];
        v.z = Os[(size_t)d * 132 + i4 + 2];
        v.w = Os[(size_t)d * 132 + i4 + 3];
        *(float4*)(out + (size_t)d * N_SEQ + q0 + i4) = v;
    }
}

// ---------------------------------------------------------------------------
extern "C" void kernel_launch(void* const* d_in, const int* in_sizes, int n_in,
                              void* d_out, int out_size)
{
    const float* x     = (const float*)d_in[0];
    const float* w_qkv = (const float*)d_in[1];
    const float* w_out = (const float*)d_in[2];
    const float* b_out = (const float*)d_in[3];
    float* y = (float*)d_out;

    float* qkv = nullptr;
    float* att = nullptr;
    cudaGetSymbolAddress((void**)&qkv, g_qkv);
    cudaGetSymbolAddress((void**)&att, g_att);

    gemm_tf32<<<dim3(N_SEQ / 128, QKV_ROWS / 128, BATCH), 256>>>(
        w_qkv, x, qkv, nullptr, QKV_ROWS, N_SEQ, C_DIM);

    const int fsm = FLASH_WORDS * 4;
    cudaFuncSetAttribute(flash_tf32,
                         cudaFuncAttributeMaxDynamicSharedMemorySize, fsm);
    flash_tf32<<<dim3(N_SEQ / 128, HEADS, BATCH), 128, fsm>>>(qkv, att);

    gemm_tf32<<<dim3(N_SEQ / 128, HIDDEN / 128, BATCH), 256>>>(
        w_out, att, y, b_out, HIDDEN, N_SEQ, C_DIM);
}

// round 6
// speedup vs baseline: 4.0883x; 1.0887x over previous
#include <cuda_runtime.h>
#include <stdint.h>

#define BATCH    8
#define C_DIM    512
#define N_SEQ    2048
#define HEADS    8
#define QKV_ROWS 1536
#define HIDDEN   512
#define SM_SCALE_LOG2 0.18033688011112042f  // dhead^-0.5 * log2(e)

__device__ float g_qkv[(size_t)BATCH * QKV_ROWS * N_SEQ];
__device__ float g_att[(size_t)BATCH * HIDDEN * N_SEQ];

__device__ __forceinline__ uint32_t f2tf(float f) {
    uint32_t r; asm("cvt.rna.tf32.f32 %0, %1;" : "=r"(r) : "f"(f)); return r;
}
__device__ __forceinline__ float ex2(float x) {
    float r; asm("ex2.approx.f32 %0, %1;" : "=f"(r) : "f"(x)); return r;
}
__device__ __forceinline__ void mma8(float* c, const uint32_t* a, const uint32_t* b) {
    asm volatile(
        "mma.sync.aligned.m16n8k8.row.col.f32.tf32.tf32.f32 "
        "{%0,%1,%2,%3},{%4,%5,%6,%7},{%8,%9},{%0,%1,%2,%3};"
        : "+f"(c[0]), "+f"(c[1]), "+f"(c[2]), "+f"(c[3])
        : "r"(a[0]), "r"(a[1]), "r"(a[2]), "r"(a[3]), "r"(b[0]), "r"(b[1]));
}
__device__ __forceinline__ void cpa16(uint32_t s, const void* g) {
    asm volatile("cp.async.cg.shared.global [%0], [%1], 16;" :: "r"(s), "l"(g));
}

// ---------------- tf32 GEMM (R2 version — proven 188us) ----------------
#define ASTR 36
#define BSTR 136

__global__ __launch_bounds__(256, 2) void gemm_tf32(
    const float* __restrict__ A, const float* __restrict__ Bg,
    float* __restrict__ Cg, const float* __restrict__ bias,
    int M, int N, int K)
{
    __shared__ uint32_t As[128 * ASTR];
    __shared__ uint32_t Bs[32 * BSTR];

    const float* B = Bg + (size_t)blockIdx.z * K * N;
    float*       C = Cg + (size_t)blockIdx.z * M * N;
    const int brow = blockIdx.y * 128;
    const int bcol = blockIdx.x * 128;
    const int tid  = threadIdx.x;
    const int lane = tid & 31;
    const int w    = tid >> 5;
    const int wm   = (w >> 2) * 64;
    const int wn   = (w & 3) * 32;
    const int g    = lane >> 2;
    const int t    = lane & 3;

    float acc[4][4][4];
#pragma unroll
    for (int mt = 0; mt < 4; mt++)
#pragma unroll
        for (int nt = 0; nt < 4; nt++)
#pragma unroll
            for (int c = 0; c < 4; c++) acc[mt][nt][c] = 0.f;

    for (int k0 = 0; k0 < K; k0 += 32) {
#pragma unroll
        for (int r = 0; r < 4; r++) {
            int idx = tid + 256 * r;
            int m = idx >> 3, k4 = (idx & 7) * 4;
            float4 v = *(const float4*)(A + (size_t)(brow + m) * K + k0 + k4);
            uint32_t* p = &As[m * ASTR + k4];
            p[0] = f2tf(v.x); p[1] = f2tf(v.y); p[2] = f2tf(v.z); p[3] = f2tf(v.w);
        }
#pragma unroll
        for (int r = 0; r < 4; r++) {
            int idx = tid + 256 * r;
            int kk = idx >> 5, n4 = (idx & 31) * 4;
            float4 v = *(const float4*)(B + (size_t)(k0 + kk) * N + bcol + n4);
            *(uint4*)&Bs[kk * BSTR + n4] =
                make_uint4(f2tf(v.x), f2tf(v.y), f2tf(v.z), f2tf(v.w));
        }
        __syncthreads();

#pragma unroll
        for (int kc = 0; kc < 4; kc++) {
            const int k8 = kc * 8;
            uint32_t af[4][4], bf[4][2];
#pragma unroll
            for (int mt = 0; mt < 4; mt++) {
                const int r0 = wm + mt * 16 + g;
                af[mt][0] = As[r0 * ASTR + k8 + t];
                af[mt][1] = As[(r0 + 8) * ASTR + k8 + t];
                af[mt][2] = As[r0 * ASTR + k8 + t + 4];
                af[mt][3] = As[(r0 + 8) * ASTR + k8 + t + 4];
            }
#pragma unroll
            for (int nt = 0; nt < 4; nt++) {
                const int c0 = wn + nt * 8 + g;
                bf[nt][0] = Bs[(k8 + t) * BSTR + c0];
                bf[nt][1] = Bs[(k8 + t + 4) * BSTR + c0];
            }
#pragma unroll
            for (int mt = 0; mt < 4; mt++)
#pragma unroll
                for (int nt = 0; nt < 4; nt++)
                    mma8(acc[mt][nt], af[mt], bf[nt]);
        }
        __syncthreads();
    }

#pragma unroll
    for (int mt = 0; mt < 4; mt++) {
        const int r0 = brow + wm + mt * 16 + g;
        const float b0 = bias ? bias[r0] : 0.f;
        const float b1 = bias ? bias[r0 + 8] : 0.f;
#pragma unroll
        for (int nt = 0; nt < 4; nt++) {
            const int c = bcol + wn + nt * 8 + 2 * t;
            *(float2*)(C + (size_t)r0 * N + c) =
                make_float2(acc[mt][nt][0] + b0, acc[mt][nt][1] + b0);
            *(float2*)(C + (size_t)(r0 + 8) * N + c) =
                make_float2(acc[mt][nt][2] + b1, acc[mt][nt][3] + b1);
        }
    }
}

// ---------------- flash: 256-q tile, 8 warps, cp.async double buffer ----------
#define QSTR 68   // Qs[256][68]: A-frag banks 4g+t CF
#define KSTR 72   // Ks[2][64][72]: B-frag banks 8t+8nt+g CF
#define VSTR 68   // Vs[2][64][68]: B-frag banks 4g+t CF
#define PSTR 76   // Ps[256][76]: A-frag banks 12g+t CF
#define QS_OFF 0
#define KS_OFF (256 * QSTR)                 // 17408
#define VS_OFF (KS_OFF + 2 * 64 * KSTR)     // 26624
#define PS_OFF (VS_OFF + 2 * 64 * VSTR)     // 35328
#define FLASH_WORDS (PS_OFF + 256 * PSTR)   // 54784 words = 219136 B
#define NTILES (N_SEQ / 64)

__global__ __launch_bounds__(256, 1) void flash_tf32(
    const float* __restrict__ qkv, float* __restrict__ outp)
{
    extern __shared__ uint32_t sm[];
    uint32_t* Qs = sm + QS_OFF;
    uint32_t* Ks = sm + KS_OFF;
    uint32_t* Vs = sm + VS_OFF;
    uint32_t* Ps = sm + PS_OFF;
    const uint32_t smem_u32 = (uint32_t)__cvta_generic_to_shared(sm);
    const uint32_t ksu = smem_u32 + KS_OFF * 4;
    const uint32_t vsu = smem_u32 + VS_OFF * 4;

    const int b  = blockIdx.z;
    const int h  = blockIdx.y;
    const int q0 = blockIdx.x * 256;
    const float* Q  = qkv + ((size_t)b * QKV_ROWS + h * 64) * N_SEQ;
    const float* Kp = Q + (size_t)512 * N_SEQ;
    const float* Vp = Q + (size_t)1024 * N_SEQ;

    const int tid  = threadIdx.x;
    const int lane = tid & 31;
    const int w    = tid >> 5;
    const int g    = lane >> 2;
    const int t    = lane & 3;
    const int rb0  = w * 32;
    const int rA0  = rb0 + g,      rA1 = rb0 + g + 8;
    const int rB0  = rb0 + 16 + g, rB1 = rb0 + 16 + g + 8;

    // prefetch K/V tile 0 into buffer 0 (raw fp32 -> consumed as tf32)
#pragma unroll
    for (int u = 0; u < 4; u++) {
        int idx = u * 256 + tid;
        int d = idx >> 4, j4 = (idx & 15) * 4;
        cpa16(ksu + (uint32_t)(d * KSTR + j4) * 4, Kp + (size_t)d * N_SEQ + j4);
        cpa16(vsu + (uint32_t)(d * VSTR + j4) * 4, Vp + (size_t)d * N_SEQ + j4);
    }
    asm volatile("cp.async.commit_group;");

    // Q staging: register transpose, rounded cvt + baked scale
#pragma unroll
    for (int grp = 0; grp < 8; grp++) {
        const float* qp = Q + (size_t)(grp * 8) * N_SEQ + q0 + tid;
        uint32_t v[8];
#pragma unroll
        for (int c = 0; c < 8; c++)
            v[c] = f2tf(qp[(size_t)c * N_SEQ] * SM_SCALE_LOG2);
        *(uint4*)&Qs[tid * QSTR + grp * 8]     = make_uint4(v[0], v[1], v[2], v[3]);
        *(uint4*)&Qs[tid * QSTR + grp * 8 + 4] = make_uint4(v[4], v[5], v[6], v[7]);
    }

    float o[2][8][4];
#pragma unroll
    for (int mt = 0; mt < 2; mt++)
#pragma unroll
        for (int dt = 0; dt < 8; dt++)
#pragma unroll
            for (int c = 0; c < 4; c++) o[mt][dt][c] = 0.f;
    float mrow[2][2] = {{-1e30f, -1e30f}, {-1e30f, -1e30f}};
    float lrow[2][2] = {{0.f, 0.f}, {0.f, 0.f}};

    for (int tI = 0; tI < NTILES; tI++) {
        const int cur = tI & 1;
        const uint32_t* Kc = Ks + cur * 64 * KSTR;
        const uint32_t* Vc = Vs + cur * 64 * VSTR;

        if (tI + 1 < NTILES) {
            const int nxt = cur ^ 1;
            const int j1 = (tI + 1) * 64;
#pragma unroll
            for (int u = 0; u < 4; u++) {
                int idx = u * 256 + tid;
                int d = idx >> 4, j4 = (idx & 15) * 4;
                cpa16(ksu + (uint32_t)(nxt * 64 * KSTR + d * KSTR + j4) * 4,
                      Kp + (size_t)d * N_SEQ + j1 + j4);
                cpa16(vsu + (uint32_t)(nxt * 64 * VSTR + d * VSTR + j4) * 4,
                      Vp + (size_t)d * N_SEQ + j1 + j4);
            }
            asm volatile("cp.async.commit_group;");
            asm volatile("cp.async.wait_group 1;");
        } else {
            asm volatile("cp.async.wait_group 0;");
        }
        __syncthreads();

        // S = Q @ K^T : per warp 32 q rows x 64 keys, K=64 dims
        float s[2][8][4];
#pragma unroll
        for (int mt = 0; mt < 2; mt++)
#pragma unroll
            for (int nt = 0; nt < 8; nt++)
#pragma unroll
                for (int c = 0; c < 4; c++) s[mt][nt][c] = 0.f;
#pragma unroll
        for (int kc = 0; kc < 8; kc++) {
            const int d8 = kc * 8;
            uint32_t a0[4], a1[4];
            a0[0] = Qs[rA0 * QSTR + d8 + t];
            a0[1] = Qs[rA1 * QSTR + d8 + t];
            a0[2] = Qs[rA0 * QSTR + d8 + t + 4];
            a0[3] = Qs[rA1 * QSTR + d8 + t + 4];
            a1[0] = Qs[rB0 * QSTR + d8 + t];
            a1[1] = Qs[rB1 * QSTR + d8 + t];
            a1[2] = Qs[rB0 * QSTR + d8 + t + 4];
            a1[3] = Qs[rB1 * QSTR + d8 + t + 4];
#pragma unroll
            for (int nt = 0; nt < 8; nt++) {
                uint32_t bb[2];
                bb[0] = Kc[(d8 + t) * KSTR + nt * 8 + g];
                bb[1] = Kc[(d8 + t + 4) * KSTR + nt * 8 + g];
                mma8(s[0][nt], a0, bb);
                mma8(s[1][nt], a1, bb);
            }
        }

        // online softmax (exp2 domain; scale baked into Q); P stored raw fp32
        float* Pf = (float*)Ps;
#pragma unroll
        for (int mt = 0; mt < 2; mt++) {
            const int q0r = (mt == 0) ? rA0 : rB0;
            const int q1r = (mt == 0) ? rA1 : rB1;
            float mx0 = -1e30f, mx1 = -1e30f;
#pragma unroll
            for (int nt = 0; nt < 8; nt++) {
                mx0 = fmaxf(mx0, fmaxf(s[mt][nt][0], s[mt][nt][1]));
                mx1 = fmaxf(mx1, fmaxf(s[mt][nt][2], s[mt][nt][3]));
            }
            mx0 = fmaxf(mx0, __shfl_xor_sync(0xffffffffu, mx0, 1));
            mx0 = fmaxf(mx0, __shfl_xor_sync(0xffffffffu, mx0, 2));
            mx1 = fmaxf(mx1, __shfl_xor_sync(0xffffffffu, mx1, 1));
            mx1 = fmaxf(mx1, __shfl_xor_sync(0xffffffffu, mx1, 2));

            const float nm0 = fmaxf(mrow[mt][0], mx0);
            const float nm1 = fmaxf(mrow[mt][1], mx1);
            const float al0 = ex2(mrow[mt][0] - nm0);
            const float al1 = ex2(mrow[mt][1] - nm1);

            float ps0 = 0.f, ps1 = 0.f;
#pragma unroll
            for (int nt = 0; nt < 8; nt++) {
                float p0 = ex2(s[mt][nt][0] - nm0);
                float p1 = ex2(s[mt][nt][1] - nm0);
                float p2 = ex2(s[mt][nt][2] - nm1);
                float p3 = ex2(s[mt][nt][3] - nm1);
                ps0 += p0 + p1; ps1 += p2 + p3;
                *(float2*)&Pf[q0r * PSTR + nt * 8 + 2 * t] = make_float2(p0, p1);
                *(float2*)&Pf[q1r * PSTR + nt * 8 + 2 * t] = make_float2(p2, p3);
            }
            ps0 += __shfl_xor_sync(0xffffffffu, ps0, 1);
            ps0 += __shfl_xor_sync(0xffffffffu, ps0, 2);
            ps1 += __shfl_xor_sync(0xffffffffu, ps1, 1);
            ps1 += __shfl_xor_sync(0xffffffffu, ps1, 2);
            lrow[mt][0] = lrow[mt][0] * al0 + ps0;
            lrow[mt][1] = lrow[mt][1] * al1 + ps1;
            mrow[mt][0] = nm0; mrow[mt][1] = nm1;

#pragma unroll
            for (int dt = 0; dt < 8; dt++) {
                o[mt][dt][0] *= al0; o[mt][dt][1] *= al0;
                o[mt][dt][2] *= al1; o[mt][dt][3] *= al1;
            }
        }
        __syncwarp();   // Ps rows are warp-private

        // O += P @ V : 32 q rows x 64 dims, K = 64 keys
#pragma unroll
        for (int kc = 0; kc < 8; kc++) {
            const int j8 = kc * 8;
            uint32_t a0[4], a1[4];
            a0[0] = Ps[rA0 * PSTR + j8 + t];
            a0[1] = Ps[rA1 * PSTR + j8 + t];
            a0[2] = Ps[rA0 * PSTR + j8 + t + 4];
            a0[3] = Ps[rA1 * PSTR + j8 + t + 4];
            a1[0] = Ps[rB0 * PSTR + j8 + t];
            a1[1] = Ps[rB1 * PSTR + j8 + t];
            a1[2] = Ps[rB0 * PSTR + j8 + t + 4];
            a1[3] = Ps[rB1 * PSTR + j8 + t + 4];
#pragma unroll
            for (int dt = 0; dt < 8; dt++) {
                uint32_t bv[2];
                bv[0] = Vc[(dt * 8 + g) * VSTR + j8 + t];
                bv[1] = Vc[(dt * 8 + g) * VSTR + j8 + t + 4];
                mma8(o[0][dt], a0, bv);
                mma8(o[1][dt], a1, bv);
            }
        }
        __syncthreads();   // compute done before next prefetch overwrites cur
    }

    // reuse Ps as Os[64 d][260 i] float
    float* Os = (float*)Ps;
#pragma unroll
    for (int mt = 0; mt < 2; mt++) {
        const int q0r = (mt == 0) ? rA0 : rB0;
        const int q1r = (mt == 0) ? rA1 : rB1;
        const float inv0 = 1.f / lrow[mt][0];
        const float inv1 = 1.f / lrow[mt][1];
#pragma unroll
        for (int dt = 0; dt < 8; dt++) {
            const int d = dt * 8 + 2 * t;
            Os[(size_t)d * 260 + q0r]       = o[mt][dt][0] * inv0;
            Os[(size_t)(d + 1) * 260 + q0r] = o[mt][dt][1] * inv0;
            Os[(size_t)d * 260 + q1r]       = o[mt][dt][2] * inv1;
            Os[(size_t)(d + 1) * 260 + q1r] = o[mt][dt][3] * inv1;
        }
    }
    __syncthreads();

    float* out = outp + ((size_t)b * HIDDEN + h * 64) * N_SEQ;
#pragma unroll
    for (int u = 0; u < 16; u++) {
        int idx = u * 256 + tid;
        int d = idx >> 6, i4 = (idx & 63) * 4;
        float4 v;
        v.x = Os[(size_t)d * 260 + i4 + 0];
        v.y = Os[(size_t)d * 260 + i4 + 1];
        v.z = Os[(size_t)d * 260 + i4 + 2];
        v.w = Os[(size_t)d * 260 + i4 + 3];
        *(float4*)(out + (size_t)d * N_SEQ + q0 + i4) = v;
    }
}

// ---------------------------------------------------------------------------
extern "C" void kernel_launch(void* const* d_in, const int* in_sizes, int n_in,
                              void* d_out, int out_size)
{
    const float* x     = (const float*)d_in[0];
    const float* w_qkv = (const float*)d_in[1];
    const float* w_out = (const float*)d_in[2];
    const float* b_out = (const float*)d_in[3];
    float* y = (float*)d_out;

    float* qkv = nullptr;
    float* att = nullptr;
    cudaGetSymbolAddress((void**)&qkv, g_qkv);
    cudaGetSymbolAddress((void**)&att, g_att);

    gemm_tf32<<<dim3(N_SEQ / 128, QKV_ROWS / 128, BATCH), 256>>>(
        w_qkv, x, qkv, nullptr, QKV_ROWS, N_SEQ, C_DIM);

    const int fsm = FLASH_WORDS * 4;
    cudaFuncSetAttribute(flash_tf32,
                         cudaFuncAttributeMaxDynamicSharedMemorySize, fsm);
    flash_tf32<<<dim3(N_SEQ / 256, HEADS, BATCH), 256, fsm>>>(qkv, att);

    gemm_tf32<<<dim3(N_SEQ / 128, HIDDEN / 128, BATCH), 256>>>(
        w_out, att, y, b_out, HIDDEN, N_SEQ, C_DIM);
}

// round 7
// speedup vs baseline: 4.4752x; 1.0946x over previous
#include <cuda_runtime.h>
#include <stdint.h>

#define BATCH    8
#define C_DIM    512
#define N_SEQ    2048
#define HEADS    8
#define QKV_ROWS 1536
#define HIDDEN   512
#define SM_SCALE_LOG2 0.18033688011112042f  // dhead^-0.5 * log2(e)

__device__ float g_qkv[(size_t)BATCH * QKV_ROWS * N_SEQ];
__device__ float g_att[(size_t)BATCH * HIDDEN * N_SEQ];

__device__ __forceinline__ uint32_t f2tf(float f) {
    uint32_t r; asm("cvt.rna.tf32.f32 %0, %1;" : "=r"(r) : "f"(f)); return r;
}
__device__ __forceinline__ float ex2(float x) {
    float r; asm("ex2.approx.f32 %0, %1;" : "=f"(r) : "f"(x)); return r;
}
__device__ __forceinline__ void mma8(float* c, const uint32_t* a, const uint32_t* b) {
    asm volatile(
        "mma.sync.aligned.m16n8k8.row.col.f32.tf32.tf32.f32 "
        "{%0,%1,%2,%3},{%4,%5,%6,%7},{%8,%9},{%0,%1,%2,%3};"
        : "+f"(c[0]), "+f"(c[1]), "+f"(c[2]), "+f"(c[3])
        : "r"(a[0]), "r"(a[1]), "r"(a[2]), "r"(a[3]), "r"(b[0]), "r"(b[1]));
}
__device__ __forceinline__ void cpa16(uint32_t s, const void* g) {
    asm volatile("cp.async.cg.shared.global [%0], [%1], 16;" :: "r"(s), "l"(g));
}

// ---------------- tf32 GEMM (R2 body + optional tf32-rounded output) ----------
#define ASTR 36
#define BSTR 136

__global__ __launch_bounds__(256, 2) void gemm_tf32(
    const float* __restrict__ A, const float* __restrict__ Bg,
    float* __restrict__ Cg, const float* __restrict__ bias,
    int M, int N, int K, int round_c)
{
    __shared__ uint32_t As[128 * ASTR];
    __shared__ uint32_t Bs[32 * BSTR];

    const float* B = Bg + (size_t)blockIdx.z * K * N;
    float*       C = Cg + (size_t)blockIdx.z * M * N;
    const int brow = blockIdx.y * 128;
    const int bcol = blockIdx.x * 128;
    const int tid  = threadIdx.x;
    const int lane = tid & 31;
    const int w    = tid >> 5;
    const int wm   = (w >> 2) * 64;
    const int wn   = (w & 3) * 32;
    const int g    = lane >> 2;
    const int t    = lane & 3;

    float acc[4][4][4];
#pragma unroll
    for (int mt = 0; mt < 4; mt++)
#pragma unroll
        for (int nt = 0; nt < 4; nt++)
#pragma unroll
            for (int c = 0; c < 4; c++) acc[mt][nt][c] = 0.f;

    for (int k0 = 0; k0 < K; k0 += 32) {
#pragma unroll
        for (int r = 0; r < 4; r++) {
            int idx = tid + 256 * r;
            int m = idx >> 3, k4 = (idx & 7) * 4;
            float4 v = *(const float4*)(A + (size_t)(brow + m) * K + k0 + k4);
            uint32_t* p = &As[m * ASTR + k4];
            p[0] = f2tf(v.x); p[1] = f2tf(v.y); p[2] = f2tf(v.z); p[3] = f2tf(v.w);
        }
#pragma unroll
        for (int r = 0; r < 4; r++) {
            int idx = tid + 256 * r;
            int kk = idx >> 5, n4 = (idx & 31) * 4;
            float4 v = *(const float4*)(B + (size_t)(k0 + kk) * N + bcol + n4);
            *(uint4*)&Bs[kk * BSTR + n4] =
                make_uint4(f2tf(v.x), f2tf(v.y), f2tf(v.z), f2tf(v.w));
        }
        __syncthreads();

#pragma unroll
        for (int kc = 0; kc < 4; kc++) {
            const int k8 = kc * 8;
            uint32_t af[4][4], bf[4][2];
#pragma unroll
            for (int mt = 0; mt < 4; mt++) {
                const int r0 = wm + mt * 16 + g;
                af[mt][0] = As[r0 * ASTR + k8 + t];
                af[mt][1] = As[(r0 + 8) * ASTR + k8 + t];
                af[mt][2] = As[r0 * ASTR + k8 + t + 4];
                af[mt][3] = As[(r0 + 8) * ASTR + k8 + t + 4];
            }
#pragma unroll
            for (int nt = 0; nt < 4; nt++) {
                const int c0 = wn + nt * 8 + g;
                bf[nt][0] = Bs[(k8 + t) * BSTR + c0];
                bf[nt][1] = Bs[(k8 + t + 4) * BSTR + c0];
            }
#pragma unroll
            for (int mt = 0; mt < 4; mt++)
#pragma unroll
                for (int nt = 0; nt < 4; nt++)
                    mma8(acc[mt][nt], af[mt], bf[nt]);
        }
        __syncthreads();
    }

#pragma unroll
    for (int mt = 0; mt < 4; mt++) {
        const int r0 = brow + wm + mt * 16 + g;
        const float b0 = bias ? bias[r0] : 0.f;
        const float b1 = bias ? bias[r0 + 8] : 0.f;
#pragma unroll
        for (int nt = 0; nt < 4; nt++) {
            const int c = bcol + wn + nt * 8 + 2 * t;
            float v0 = acc[mt][nt][0] + b0, v1 = acc[mt][nt][1] + b0;
            float v2 = acc[mt][nt][2] + b1, v3 = acc[mt][nt][3] + b1;
            if (round_c) {   // round to tf32 so downstream truncation is lossless
                v0 = __uint_as_float(f2tf(v0));
                v1 = __uint_as_float(f2tf(v1));
                v2 = __uint_as_float(f2tf(v2));
                v3 = __uint_as_float(f2tf(v3));
            }
            *(float2*)(C + (size_t)r0 * N + c)       = make_float2(v0, v1);
            *(float2*)(C + (size_t)(r0 + 8) * N + c) = make_float2(v2, v3);
        }
    }
}

// ------- flash: 128-q tile, 4 warps, Q-frags in registers, 2 CTAs/SM --------
#define KSTR 72   // Ks[2][64][72]: B-frag banks 8t+8nt+g CF
#define VSTR 68   // Vs[2][64][68]: B-frag banks 4g+t CF
#define PSTR 76   // Ps[128][76]: frag banks 12g+t CF; also Q temp + O staging
#define KS_OFF 0
#define VS_OFF (2 * 64 * KSTR)              // 9216
#define PS_OFF (VS_OFF + 2 * 64 * VSTR)     // 17920
#define FLASH_WORDS (PS_OFF + 128 * PSTR)   // 27648 words = 110592 B
#define NTILES (N_SEQ / 64)

__global__ __launch_bounds__(128, 2) void flash_tf32(
    const float* __restrict__ qkv, float* __restrict__ outp)
{
    extern __shared__ uint32_t sm[];
    uint32_t* Ks = sm + KS_OFF;
    uint32_t* Vs = sm + VS_OFF;
    uint32_t* Ps = sm + PS_OFF;
    const uint32_t smem_u32 = (uint32_t)__cvta_generic_to_shared(sm);
    const uint32_t ksu = smem_u32 + KS_OFF * 4;
    const uint32_t vsu = smem_u32 + VS_OFF * 4;

    const int b  = blockIdx.z;
    const int h  = blockIdx.y;
    const int q0 = blockIdx.x * 128;
    const float* Q  = qkv + ((size_t)b * QKV_ROWS + h * 64) * N_SEQ;
    const float* Kp = Q + (size_t)512 * N_SEQ;
    const float* Vp = Q + (size_t)1024 * N_SEQ;

    const int tid  = threadIdx.x;        // 128 threads = 4 warps
    const int lane = tid & 31;
    const int w    = tid >> 5;
    const int g    = lane >> 2;
    const int t    = lane & 3;
    const int rb0  = w * 32;
    const int rA0  = rb0 + g,      rA1 = rb0 + g + 8;
    const int rB0  = rb0 + 16 + g, rB1 = rb0 + 16 + g + 8;

    // prefetch K/V tile 0 (raw fp32; values pre-rounded to tf32 by gemm)
#pragma unroll
    for (int u = 0; u < 8; u++) {
        int idx = u * 128 + tid;
        int d = idx >> 4, j4 = (idx & 15) * 4;
        cpa16(ksu + (uint32_t)(d * KSTR + j4) * 4, Kp + (size_t)d * N_SEQ + j4);
        cpa16(vsu + (uint32_t)(d * VSTR + j4) * 4, Vp + (size_t)d * N_SEQ + j4);
    }
    asm volatile("cp.async.commit_group;");

    // Q staging into Ps temp [i][d] (stride PSTR), scale baked, rounded
#pragma unroll
    for (int grp = 0; grp < 8; grp++) {
        const float* qp = Q + (size_t)(grp * 8) * N_SEQ + q0 + tid;
        uint32_t v[8];
#pragma unroll
        for (int c = 0; c < 8; c++)
            v[c] = f2tf(qp[(size_t)c * N_SEQ] * SM_SCALE_LOG2);
        *(uint4*)&Ps[tid * PSTR + grp * 8]     = make_uint4(v[0], v[1], v[2], v[3]);
        *(uint4*)&Ps[tid * PSTR + grp * 8 + 4] = make_uint4(v[4], v[5], v[6], v[7]);
    }
    __syncthreads();

    // Q fragments -> registers (persistent). 64 regs/thread.
    uint32_t qf[8][8];
#pragma unroll
    for (int kc = 0; kc < 8; kc++) {
        const int d8 = kc * 8;
        qf[kc][0] = Ps[rA0 * PSTR + d8 + t];
        qf[kc][1] = Ps[rA1 * PSTR + d8 + t];
        qf[kc][2] = Ps[rA0 * PSTR + d8 + t + 4];
        qf[kc][3] = Ps[rA1 * PSTR + d8 + t + 4];
        qf[kc][4] = Ps[rB0 * PSTR + d8 + t];
        qf[kc][5] = Ps[rB1 * PSTR + d8 + t];
        qf[kc][6] = Ps[rB0 * PSTR + d8 + t + 4];
        qf[kc][7] = Ps[rB1 * PSTR + d8 + t + 4];
    }
    __syncthreads();   // Ps now free for P

    float o[2][8][4];
#pragma unroll
    for (int mt = 0; mt < 2; mt++)
#pragma unroll
        for (int dt = 0; dt < 8; dt++)
#pragma unroll
            for (int c = 0; c < 4; c++) o[mt][dt][c] = 0.f;
    float mrow[2][2] = {{-1e30f, -1e30f}, {-1e30f, -1e30f}};
    float lrow[2][2] = {{0.f, 0.f}, {0.f, 0.f}};

    for (int tI = 0; tI < NTILES; tI++) {
        const int cur = tI & 1;
        const uint32_t* Kc = Ks + cur * 64 * KSTR;
        const uint32_t* Vc = Vs + cur * 64 * VSTR;

        if (tI + 1 < NTILES) {
            const int nxt = cur ^ 1;
            const int j1 = (tI + 1) * 64;
#pragma unroll
            for (int u = 0; u < 8; u++) {
                int idx = u * 128 + tid;
                int d = idx >> 4, j4 = (idx & 15) * 4;
                cpa16(ksu + (uint32_t)(nxt * 64 * KSTR + d * KSTR + j4) * 4,
                      Kp + (size_t)d * N_SEQ + j1 + j4);
                cpa16(vsu + (uint32_t)(nxt * 64 * VSTR + d * VSTR + j4) * 4,
                      Vp + (size_t)d * N_SEQ + j1 + j4);
            }
            asm volatile("cp.async.commit_group;");
            asm volatile("cp.async.wait_group 1;");
        } else {
            asm volatile("cp.async.wait_group 0;");
        }
        __syncthreads();

        // S = Q @ K^T : 32 q rows x 64 keys (A-frags from registers)
        float s[2][8][4];
#pragma unroll
        for (int mt = 0; mt < 2; mt++)
#pragma unroll
            for (int nt = 0; nt < 8; nt++)
#pragma unroll
                for (int c = 0; c < 4; c++) s[mt][nt][c] = 0.f;
#pragma unroll
        for (int kc = 0; kc < 8; kc++) {
            const int d8 = kc * 8;
#pragma unroll
            for (int nt = 0; nt < 8; nt++) {
                uint32_t bb[2];
                bb[0] = Kc[(d8 + t) * KSTR + nt * 8 + g];
                bb[1] = Kc[(d8 + t + 4) * KSTR + nt * 8 + g];
                mma8(s[0][nt], &qf[kc][0], bb);
                mma8(s[1][nt], &qf[kc][4], bb);
            }
        }

        // online softmax; P rounded to tf32 before smem store
#pragma unroll
        for (int mt = 0; mt < 2; mt++) {
            const int q0r = (mt == 0) ? rA0 : rB0;
            const int q1r = (mt == 0) ? rA1 : rB1;
            float mx0 = -1e30f, mx1 = -1e30f;
#pragma unroll
            for (int nt = 0; nt < 8; nt++) {
                mx0 = fmaxf(mx0, fmaxf(s[mt][nt][0], s[mt][nt][1]));
                mx1 = fmaxf(mx1, fmaxf(s[mt][nt][2], s[mt][nt][3]));
            }
            mx0 = fmaxf(mx0, __shfl_xor_sync(0xffffffffu, mx0, 1));
            mx0 = fmaxf(mx0, __shfl_xor_sync(0xffffffffu, mx0, 2));
            mx1 = fmaxf(mx1, __shfl_xor_sync(0xffffffffu, mx1, 1));
            mx1 = fmaxf(mx1, __shfl_xor_sync(0xffffffffu, mx1, 2));

            const float nm0 = fmaxf(mrow[mt][0], mx0);
            const float nm1 = fmaxf(mrow[mt][1], mx1);
            const float al0 = ex2(mrow[mt][0] - nm0);
            const float al1 = ex2(mrow[mt][1] - nm1);

            float ps0 = 0.f, ps1 = 0.f;
#pragma unroll
            for (int nt = 0; nt < 8; nt++) {
                float p0 = ex2(s[mt][nt][0] - nm0);
                float p1 = ex2(s[mt][nt][1] - nm0);
                float p2 = ex2(s[mt][nt][2] - nm1);
                float p3 = ex2(s[mt][nt][3] - nm1);
                ps0 += p0 + p1; ps1 += p2 + p3;
                *(uint2*)&Ps[q0r * PSTR + nt * 8 + 2 * t] =
                    make_uint2(f2tf(p0), f2tf(p1));
                *(uint2*)&Ps[q1r * PSTR + nt * 8 + 2 * t] =
                    make_uint2(f2tf(p2), f2tf(p3));
            }
            ps0 += __shfl_xor_sync(0xffffffffu, ps0, 1);
            ps0 += __shfl_xor_sync(0xffffffffu, ps0, 2);
            ps1 += __shfl_xor_sync(0xffffffffu, ps1, 1);
            ps1 += __shfl_xor_sync(0xffffffffu, ps1, 2);
            lrow[mt][0] = lrow[mt][0] * al0 + ps0;
            lrow[mt][1] = lrow[mt][1] * al1 + ps1;
            mrow[mt][0] = nm0; mrow[mt][1] = nm1;

#pragma unroll
            for (int dt = 0; dt < 8; dt++) {
                o[mt][dt][0] *= al0; o[mt][dt][1] *= al0;
                o[mt][dt][2] *= al1; o[mt][dt][3] *= al1;
            }
        }
        __syncwarp();   // Ps rows are warp-private

        // O += P @ V : 32 q rows x 64 dims
#pragma unroll
        for (int kc = 0; kc < 8; kc++) {
            const int j8 = kc * 8;
            uint32_t a0[4], a1[4];
            a0[0] = Ps[rA0 * PSTR + j8 + t];
            a0[1] = Ps[rA1 * PSTR + j8 + t];
            a0[2] = Ps[rA0 * PSTR + j8 + t + 4];
            a0[3] = Ps[rA1 * PSTR + j8 + t + 4];
            a1[0] = Ps[rB0 * PSTR + j8 + t];
            a1[1] = Ps[rB1 * PSTR + j8 + t];
            a1[2] = Ps[rB0 * PSTR + j8 + t + 4];
            a1[3] = Ps[rB1 * PSTR + j8 + t + 4];
#pragma unroll
            for (int dt = 0; dt < 8; dt++) {
                uint32_t bv[2];
                bv[0] = Vc[(dt * 8 + g) * VSTR + j8 + t];
                bv[1] = Vc[(dt * 8 + g) * VSTR + j8 + t + 4];
                mma8(o[0][dt], a0, bv);
                mma8(o[1][dt], a1, bv);
            }
        }
        __syncthreads();   // all reads of cur buffer done before next prefetch
    }

    // reuse Ps as Os[64 d][132 i] float
    float* Os = (float*)Ps;
#pragma unroll
    for (int mt = 0; mt < 2; mt++) {
        const int q0r = (mt == 0) ? rA0 : rB0;
        const int q1r = (mt == 0) ? rA1 : rB1;
        const float inv0 = 1.f / lrow[mt][0];
        const float inv1 = 1.f / lrow[mt][1];
#pragma unroll
        for (int dt = 0; dt < 8; dt++) {
            const int d = dt * 8 + 2 * t;
            Os[(size_t)d * 132 + q0r]       = o[mt][dt][0] * inv0;
            Os[(size_t)(d + 1) * 132 + q0r] = o[mt][dt][1] * inv0;
            Os[(size_t)d * 132 + q1r]       = o[mt][dt][2] * inv1;
            Os[(size_t)(d + 1) * 132 + q1r] = o[mt][dt][3] * inv1;
        }
    }
    __syncthreads();

    float* out = outp + ((size_t)b * HIDDEN + h * 64) * N_SEQ;
#pragma unroll
    for (int u = 0; u < 16; u++) {
        int idx = u * 128 + tid;
        int d = idx >> 5, i4 = (idx & 31) * 4;
        float4 v;
        v.x = Os[(size_t)d * 132 + i4 + 0];
        v.y = Os[(size_t)d * 132 + i4 + 1];
        v.z = Os[(size_t)d * 132 + i4 + 2];
        v.w = Os[(size_t)d * 132 + i4 + 3];
        *(float4*)(out + (size_t)d * N_SEQ + q0 + i4) = v;
    }
}

// ---------------------------------------------------------------------------
extern "C" void kernel_launch(void* const* d_in, const int* in_sizes, int n_in,
                              void* d_out, int out_size)
{
    const float* x     = (const float*)d_in[0];
    const float* w_qkv = (const float*)d_in[1];
    const float* w_out = (const float*)d_in[2];
    const float* b_out = (const float*)d_in[3];
    float* y = (float*)d_out;

    float* qkv = nullptr;
    float* att = nullptr;
    cudaGetSymbolAddress((void**)&qkv, g_qkv);
    cudaGetSymbolAddress((void**)&att, g_att);

    // 1) qkv = w_qkv @ x, output rounded to tf32 (lossless flash truncation)
    gemm_tf32<<<dim3(N_SEQ / 128, QKV_ROWS / 128, BATCH), 256>>>(
        w_qkv, x, qkv, nullptr, QKV_ROWS, N_SEQ, C_DIM, 1);

    // 2) fused flash attention, 2 CTAs/SM
    const int fsm = FLASH_WORDS * 4;
    cudaFuncSetAttribute(flash_tf32,
                         cudaFuncAttributeMaxDynamicSharedMemorySize, fsm);
    flash_tf32<<<dim3(N_SEQ / 128, HEADS, BATCH), 128, fsm>>>(qkv, att);

    // 3) y = w_out @ att + b_out (full fp32 output)
    gemm_tf32<<<dim3(N_SEQ / 128, HIDDEN / 128, BATCH), 256>>>(
        w_out, att, y, b_out, HIDDEN, N_SEQ, C_DIM, 0);
}

// round 8
// speedup vs baseline: 4.4790x; 1.0009x over previous
#include <cuda_runtime.h>
#include <stdint.h>

#define BATCH    8
#define C_DIM    512
#define N_SEQ    2048
#define HEADS    8
#define QKV_ROWS 1536
#define HIDDEN   512
#define SM_SCALE_LOG2 0.18033688011112042f  // dhead^-0.5 * log2(e)

__device__ float g_qkv[(size_t)BATCH * QKV_ROWS * N_SEQ];
__device__ float g_att[(size_t)BATCH * HIDDEN * N_SEQ];

__device__ __forceinline__ uint32_t f2tf(float f) {
    uint32_t r; asm("cvt.rna.tf32.f32 %0, %1;" : "=r"(r) : "f"(f)); return r;
}
__device__ __forceinline__ uint32_t u2tf(uint32_t u) {
    uint32_t r; asm("cvt.rna.tf32.f32 %0, %1;" : "=r"(r) : "f"(__uint_as_float(u)));
    return r;
}
__device__ __forceinline__ float ex2(float x) {
    float r; asm("ex2.approx.f32 %0, %1;" : "=f"(r) : "f"(x)); return r;
}
__device__ __forceinline__ void mma8(float* c, const uint32_t* a, const uint32_t* b) {
    asm volatile(
        "mma.sync.aligned.m16n8k8.row.col.f32.tf32.tf32.f32 "
        "{%0,%1,%2,%3},{%4,%5,%6,%7},{%8,%9},{%0,%1,%2,%3};"
        : "+f"(c[0]), "+f"(c[1]), "+f"(c[2]), "+f"(c[3])
        : "r"(a[0]), "r"(a[1]), "r"(a[2]), "r"(a[3]), "r"(b[0]), "r"(b[1]));
}
__device__ __forceinline__ void cpa16(uint32_t s, const void* g) {
    asm volatile("cp.async.cg.shared.global [%0], [%1], 16;" :: "r"(s), "l"(g));
}

// ---------- tf32 GEMM: 3-stage cp.async ring, raw fp32 staged, cvt at frag load
#define ASTR 36
#define BSTR 136
#define AWORDS (128 * ASTR)               // 4608
#define BWORDS (32 * BSTR)                // 4352
#define STG_WORDS (AWORDS + BWORDS)       // 8960
#define GEMM_SMEM (3 * STG_WORDS * 4)     // 107520 B

__global__ __launch_bounds__(256, 2) void gemm_tf32(
    const float* __restrict__ A, const float* __restrict__ Bg,
    float* __restrict__ Cg, const float* __restrict__ bias,
    int M, int N, int K, int round_c)
{
    extern __shared__ uint32_t gsm[];
    const uint32_t smem_u32 = (uint32_t)__cvta_generic_to_shared(gsm);

    const float* B = Bg + (size_t)blockIdx.z * K * N;
    float*       C = Cg + (size_t)blockIdx.z * M * N;
    const int brow = blockIdx.y * 128;
    const int bcol = blockIdx.x * 128;
    const int tid  = threadIdx.x;
    const int lane = tid & 31;
    const int w    = tid >> 5;
    const int wm   = (w >> 2) * 64;
    const int wn   = (w & 3) * 32;
    const int g    = lane >> 2;
    const int t    = lane & 3;

    // staging task mapping (same for every stage)
    const int aM  = tid >> 1;             // 0..127
    const int aK4 = (tid & 1) * 16;       // byte? no: word offset 0 or 4 -> *4B
    const int bK  = tid >> 5;             // 0..7 (x4 rows per pass)
    const int bN4 = (tid & 31) * 4;

    const int nIters = K >> 5;            // K/32

    // prologue: stage tiles 0 and 1
#pragma unroll
    for (int s = 0; s < 2; s++) {
        const int k0 = s * 32;
        const uint32_t ab = smem_u32 + (uint32_t)(s * STG_WORDS) * 4;
        const uint32_t bb = ab + AWORDS * 4;
        // A: 128 rows x 32 k (8 float4 per row); 2 chunks per thread x4 passes
#pragma unroll
        for (int r = 0; r < 4; r++) {
            int idx = r * 256 + tid;                  // 1024 chunks
            int m = idx >> 3, k4 = (idx & 7) * 4;
            cpa16(ab + (uint32_t)(m * ASTR + k4) * 4,
                  A + (size_t)(brow + m) * K + k0 + k4);
        }
#pragma unroll
        for (int r = 0; r < 4; r++) {
            int idx = r * 256 + tid;
            int kk = idx >> 5, n4 = (idx & 31) * 4;
            cpa16(bb + (uint32_t)(kk * BSTR + n4) * 4,
                  B + (size_t)(k0 + kk) * N + bcol + n4);
        }
        asm volatile("cp.async.commit_group;");
    }

    float acc[4][4][4];
#pragma unroll
    for (int mt = 0; mt < 4; mt++)
#pragma unroll
        for (int nt = 0; nt < 4; nt++)
#pragma unroll
            for (int c = 0; c < 4; c++) acc[mt][nt][c] = 0.f;

    int cur = 0;
    for (int it = 0; it < nIters; it++) {
        // wait for tile `it` to land
        if (it + 1 < nIters) asm volatile("cp.async.wait_group 1;");
        else                 asm volatile("cp.async.wait_group 0;");
        __syncthreads();   // also: all warps done reading the buffer we overwrite next

        // prefetch tile it+2 into ring slot (it+2)%3 (overwrites it-1's buffer)
        if (it + 2 < nIters) {
            const int s = (it + 2) % 3;
            const int k0 = (it + 2) * 32;
            const uint32_t ab = smem_u32 + (uint32_t)(s * STG_WORDS) * 4;
            const uint32_t bb = ab + AWORDS * 4;
#pragma unroll
            for (int r = 0; r < 4; r++) {
                int idx = r * 256 + tid;
                int m = idx >> 3, k4 = (idx & 7) * 4;
                cpa16(ab + (uint32_t)(m * ASTR + k4) * 4,
                      A + (size_t)(brow + m) * K + k0 + k4);
            }
#pragma unroll
            for (int r = 0; r < 4; r++) {
                int idx = r * 256 + tid;
                int kk = idx >> 5, n4 = (idx & 31) * 4;
                cpa16(bb + (uint32_t)(kk * BSTR + n4) * 4,
                      B + (size_t)(k0 + kk) * N + bcol + n4);
            }
        }
        asm volatile("cp.async.commit_group;");   // empty group OK on tail

        const uint32_t* As = gsm + cur * STG_WORDS;
        const uint32_t* Bs = As + AWORDS;

#pragma unroll
        for (int kc = 0; kc < 4; kc++) {
            const int k8 = kc * 8;
            uint32_t af[4][4], bf[4][2];
#pragma unroll
            for (int mt = 0; mt < 4; mt++) {
                const int r0 = wm + mt * 16 + g;
                af[mt][0] = u2tf(As[r0 * ASTR + k8 + t]);
                af[mt][1] = u2tf(As[(r0 + 8) * ASTR + k8 + t]);
                af[mt][2] = u2tf(As[r0 * ASTR + k8 + t + 4]);
                af[mt][3] = u2tf(As[(r0 + 8) * ASTR + k8 + t + 4]);
            }
#pragma unroll
            for (int nt = 0; nt < 4; nt++) {
                const int c0 = wn + nt * 8 + g;
                bf[nt][0] = u2tf(Bs[(k8 + t) * BSTR + c0]);
                bf[nt][1] = u2tf(Bs[(k8 + t + 4) * BSTR + c0]);
            }
#pragma unroll
            for (int mt = 0; mt < 4; mt++)
#pragma unroll
                for (int nt = 0; nt < 4; nt++)
                    mma8(acc[mt][nt], af[mt], bf[nt]);
        }
        cur = (cur + 1) % 3;
    }

#pragma unroll
    for (int mt = 0; mt < 4; mt++) {
        const int r0 = brow + wm + mt * 16 + g;
        const float b0 = bias ? bias[r0] : 0.f;
        const float b1 = bias ? bias[r0 + 8] : 0.f;
#pragma unroll
        for (int nt = 0; nt < 4; nt++) {
            const int c = bcol + wn + nt * 8 + 2 * t;
            float v0 = acc[mt][nt][0] + b0, v1 = acc[mt][nt][1] + b0;
            float v2 = acc[mt][nt][2] + b1, v3 = acc[mt][nt][3] + b1;
            if (round_c) {   // round to tf32 so downstream truncation is lossless
                v0 = __uint_as_float(f2tf(v0));
                v1 = __uint_as_float(f2tf(v1));
                v2 = __uint_as_float(f2tf(v2));
                v3 = __uint_as_float(f2tf(v3));
            }
            *(float2*)(C + (size_t)r0 * N + c)       = make_float2(v0, v1);
            *(float2*)(C + (size_t)(r0 + 8) * N + c) = make_float2(v2, v3);
        }
    }
}

// ------- flash: 128-q tile, 4 warps, Q-frags in registers, 2 CTAs/SM --------
#define KSTR 72
#define VSTR 68
#define PSTR 76
#define KS_OFF 0
#define VS_OFF (2 * 64 * KSTR)
#define PS_OFF (VS_OFF + 2 * 64 * VSTR)
#define FLASH_WORDS (PS_OFF + 128 * PSTR)   // 110592 B
#define NTILES (N_SEQ / 64)

__global__ __launch_bounds__(128, 2) void flash_tf32(
    const float* __restrict__ qkv, float* __restrict__ outp)
{
    extern __shared__ uint32_t sm[];
    uint32_t* Ks = sm + KS_OFF;
    uint32_t* Vs = sm + VS_OFF;
    uint32_t* Ps = sm + PS_OFF;
    const uint32_t smem_u32 = (uint32_t)__cvta_generic_to_shared(sm);
    const uint32_t ksu = smem_u32 + KS_OFF * 4;
    const uint32_t vsu = smem_u32 + VS_OFF * 4;

    const int b  = blockIdx.z;
    const int h  = blockIdx.y;
    const int q0 = blockIdx.x * 128;
    const float* Q  = qkv + ((size_t)b * QKV_ROWS + h * 64) * N_SEQ;
    const float* Kp = Q + (size_t)512 * N_SEQ;
    const float* Vp = Q + (size_t)1024 * N_SEQ;

    const int tid  = threadIdx.x;
    const int lane = tid & 31;
    const int w    = tid >> 5;
    const int g    = lane >> 2;
    const int t    = lane & 3;
    const int rb0  = w * 32;
    const int rA0  = rb0 + g,      rA1 = rb0 + g + 8;
    const int rB0  = rb0 + 16 + g, rB1 = rb0 + 16 + g + 8;

    // prefetch K/V tile 0 (raw fp32; pre-rounded to tf32 by gemm)
#pragma unroll
    for (int u = 0; u < 8; u++) {
        int idx = u * 128 + tid;
        int d = idx >> 4, j4 = (idx & 15) * 4;
        cpa16(ksu + (uint32_t)(d * KSTR + j4) * 4, Kp + (size_t)d * N_SEQ + j4);
        cpa16(vsu + (uint32_t)(d * VSTR + j4) * 4, Vp + (size_t)d * N_SEQ + j4);
    }
    asm volatile("cp.async.commit_group;");

    // Q staging into Ps temp [i][d], scale baked, rounded
#pragma unroll
    for (int grp = 0; grp < 8; grp++) {
        const float* qp = Q + (size_t)(grp * 8) * N_SEQ + q0 + tid;
        uint32_t v[8];
#pragma unroll
        for (int c = 0; c < 8; c++)
            v[c] = f2tf(qp[(size_t)c * N_SEQ] * SM_SCALE_LOG2);
        *(uint4*)&Ps[tid * PSTR + grp * 8]     = make_uint4(v[0], v[1], v[2], v[3]);
        *(uint4*)&Ps[tid * PSTR + grp * 8 + 4] = make_uint4(v[4], v[5], v[6], v[7]);
    }
    __syncthreads();

    uint32_t qf[8][8];
#pragma unroll
    for (int kc = 0; kc < 8; kc++) {
        const int d8 = kc * 8;
        qf[kc][0] = Ps[rA0 * PSTR + d8 + t];
        qf[kc][1] = Ps[rA1 * PSTR + d8 + t];
        qf[kc][2] = Ps[rA0 * PSTR + d8 + t + 4];
        qf[kc][3] = Ps[rA1 * PSTR + d8 + t + 4];
        qf[kc][4] = Ps[rB0 * PSTR + d8 + t];
        qf[kc][5] = Ps[rB1 * PSTR + d8 + t];
        qf[kc][6] = Ps[rB0 * PSTR + d8 + t + 4];
        qf[kc][7] = Ps[rB1 * PSTR + d8 + t + 4];
    }
    __syncthreads();

    float o[2][8][4];
#pragma unroll
    for (int mt = 0; mt < 2; mt++)
#pragma unroll
        for (int dt = 0; dt < 8; dt++)
#pragma unroll
            for (int c = 0; c < 4; c++) o[mt][dt][c] = 0.f;
    float mrow[2][2] = {{-1e30f, -1e30f}, {-1e30f, -1e30f}};
    float lrow[2][2] = {{0.f, 0.f}, {0.f, 0.f}};

    for (int tI = 0; tI < NTILES; tI++) {
        const int cur = tI & 1;
        const uint32_t* Kc = Ks + cur * 64 * KSTR;
        const uint32_t* Vc = Vs + cur * 64 * VSTR;

        if (tI + 1 < NTILES) {
            const int nxt = cur ^ 1;
            const int j1 = (tI + 1) * 64;
#pragma unroll
            for (int u = 0; u < 8; u++) {
                int idx = u * 128 + tid;
                int d = idx >> 4, j4 = (idx & 15) * 4;
                cpa16(ksu + (uint32_t)(nxt * 64 * KSTR + d * KSTR + j4) * 4,
                      Kp + (size_t)d * N_SEQ + j1 + j4);
                cpa16(vsu + (uint32_t)(nxt * 64 * VSTR + d * VSTR + j4) * 4,
                      Vp + (size_t)d * N_SEQ + j1 + j4);
            }
            asm volatile("cp.async.commit_group;");
            asm volatile("cp.async.wait_group 1;");
        } else {
            asm volatile("cp.async.wait_group 0;");
        }
        __syncthreads();

        float s[2][8][4];
#pragma unroll
        for (int mt = 0; mt < 2; mt++)
#pragma unroll
            for (int nt = 0; nt < 8; nt++)
#pragma unroll
                for (int c = 0; c < 4; c++) s[mt][nt][c] = 0.f;
#pragma unroll
        for (int kc = 0; kc < 8; kc++) {
            const int d8 = kc * 8;
#pragma unroll
            for (int nt = 0; nt < 8; nt++) {
                uint32_t bb[2];
                bb[0] = Kc[(d8 + t) * KSTR + nt * 8 + g];
                bb[1] = Kc[(d8 + t + 4) * KSTR + nt * 8 + g];
                mma8(s[0][nt], &qf[kc][0], bb);
                mma8(s[1][nt], &qf[kc][4], bb);
            }
        }

#pragma unroll
        for (int mt = 0; mt < 2; mt++) {
            const int q0r = (mt == 0) ? rA0 : rB0;
            const int q1r = (mt == 0) ? rA1 : rB1;
            float mx0 = -1e30f, mx1 = -1e30f;
#pragma unroll
            for (int nt = 0; nt < 8; nt++) {
                mx0 = fmaxf(mx0, fmaxf(s[mt][nt][0], s[mt][nt][1]));
                mx1 = fmaxf(mx1, fmaxf(s[mt][nt][2], s[mt][nt][3]));
            }
            mx0 = fmaxf(mx0, __shfl_xor_sync(0xffffffffu, mx0, 1));
            mx0 = fmaxf(mx0, __shfl_xor_sync(0xffffffffu, mx0, 2));
            mx1 = fmaxf(mx1, __shfl_xor_sync(0xffffffffu, mx1, 1));
            mx1 = fmaxf(mx1, __shfl_xor_sync(0xffffffffu, mx1, 2));

            const float nm0 = fmaxf(mrow[mt][0], mx0);
            const float nm1 = fmaxf(mrow[mt][1], mx1);
            const float al0 = ex2(mrow[mt][0] - nm0);
            const float al1 = ex2(mrow[mt][1] - nm1);

            float ps0 = 0.f, ps1 = 0.f;
#pragma unroll
            for (int nt = 0; nt < 8; nt++) {
                float p0 = ex2(s[mt][nt][0] - nm0);
                float p1 = ex2(s[mt][nt][1] - nm0);
                float p2 = ex2(s[mt][nt][2] - nm1);
                float p3 = ex2(s[mt][nt][3] - nm1);
                ps0 += p0 + p1; ps1 += p2 + p3;
                *(uint2*)&Ps[q0r * PSTR + nt * 8 + 2 * t] =
                    make_uint2(f2tf(p0), f2tf(p1));
                *(uint2*)&Ps[q1r * PSTR + nt * 8 + 2 * t] =
                    make_uint2(f2tf(p2), f2tf(p3));
            }
            ps0 += __shfl_xor_sync(0xffffffffu, ps0, 1);
            ps0 += __shfl_xor_sync(0xffffffffu, ps0, 2);
            ps1 += __shfl_xor_sync(0xffffffffu, ps1, 1);
            ps1 += __shfl_xor_sync(0xffffffffu, ps1, 2);
            lrow[mt][0] = lrow[mt][0] * al0 + ps0;
            lrow[mt][1] = lrow[mt][1] * al1 + ps1;
            mrow[mt][0] = nm0; mrow[mt][1] = nm1;

#pragma unroll
            for (int dt = 0; dt < 8; dt++) {
                o[mt][dt][0] *= al0; o[mt][dt][1] *= al0;
                o[mt][dt][2] *= al1; o[mt][dt][3] *= al1;
            }
        }
        __syncwarp();

#pragma unroll
        for (int kc = 0; kc < 8; kc++) {
            const int j8 = kc * 8;
            uint32_t a0[4], a1[4];
            a0[0] = Ps[rA0 * PSTR + j8 + t];
            a0[1] = Ps[rA1 * PSTR + j8 + t];
            a0[2] = Ps[rA0 * PSTR + j8 + t + 4];
            a0[3] = Ps[rA1 * PSTR + j8 + t + 4];
            a1[0] = Ps[rB0 * PSTR + j8 + t];
            a1[1] = Ps[rB1 * PSTR + j8 + t];
            a1[2] = Ps[rB0 * PSTR + j8 + t + 4];
            a1[3] = Ps[rB1 * PSTR + j8 + t + 4];
#pragma unroll
            for (int dt = 0; dt < 8; dt++) {
                uint32_t bv[2];
                bv[0] = Vc[(dt * 8 + g) * VSTR + j8 + t];
                bv[1] = Vc[(dt * 8 + g) * VSTR + j8 + t + 4];
                mma8(o[0][dt], a0, bv);
                mma8(o[1][dt], a1, bv);
            }
        }
        __syncthreads();
    }

    float* Os = (float*)Ps;
#pragma unroll
    for (int mt = 0; mt < 2; mt++) {
        const int q0r = (mt == 0) ? rA0 : rB0;
        const int q1r = (mt == 0) ? rA1 : rB1;
        const float inv0 = 1.f / lrow[mt][0];
        const float inv1 = 1.f / lrow[mt][1];
#pragma unroll
        for (int dt = 0; dt < 8; dt++) {
            const int d = dt * 8 + 2 * t;
            Os[(size_t)d * 132 + q0r]       = o[mt][dt][0] * inv0;
            Os[(size_t)(d + 1) * 132 + q0r] = o[mt][dt][1] * inv0;
            Os[(size_t)d * 132 + q1r]       = o[mt][dt][2] * inv1;
            Os[(size_t)(d + 1) * 132 + q1r] = o[mt][dt][3] * inv1;
        }
    }
    __syncthreads();

    float* out = outp + ((size_t)b * HIDDEN + h * 64) * N_SEQ;
#pragma unroll
    for (int u = 0; u < 16; u++) {
        int idx = u * 128 + tid;
        int d = idx >> 5, i4 = (idx & 31) * 4;
        float4 v;
        v.x = Os[(size_t)d * 132 + i4 + 0];
        v.y = Os[(size_t)d * 132 + i4 + 1];
        v.z = Os[(size_t)d * 132 + i4 + 2];
        v.w = Os[(size_t)d * 132 + i4 + 3];
        *(float4*)(out + (size_t)d * N_SEQ + q0 + i4) = v;
    }
}

// ---------------------------------------------------------------------------
extern "C" void kernel_launch(void* const* d_in, const int* in_sizes, int n_in,
                              void* d_out, int out_size)
{
    const float* x     = (const float*)d_in[0];
    const float* w_qkv = (const float*)d_in[1];
    const float* w_out = (const float*)d_in[2];
    const float* b_out = (const float*)d_in[3];
    float* y = (float*)d_out;

    float* qkv = nullptr;
    float* att = nullptr;
    cudaGetSymbolAddress((void**)&qkv, g_qkv);
    cudaGetSymbolAddress((void**)&att, g_att);

    cudaFuncSetAttribute(gemm_tf32,
                         cudaFuncAttributeMaxDynamicSharedMemorySize, GEMM_SMEM);
    const int fsm = FLASH_WORDS * 4;
    cudaFuncSetAttribute(flash_tf32,
                         cudaFuncAttributeMaxDynamicSharedMemorySize, fsm);

    // 1) qkv = w_qkv @ x, output rounded to tf32
    gemm_tf32<<<dim3(N_SEQ / 128, QKV_ROWS / 128, BATCH), 256, GEMM_SMEM>>>(
        w_qkv, x, qkv, nullptr, QKV_ROWS, N_SEQ, C_DIM, 1);

    // 2) fused flash attention
    flash_tf32<<<dim3(N_SEQ / 128, HEADS, BATCH), 128, fsm>>>(qkv, att);

    // 3) y = w_out @ att + b_out
    gemm_tf32<<<dim3(N_SEQ / 128, HIDDEN / 128, BATCH), 256, GEMM_SMEM>>>(
        w_out, att, y, b_out, HIDDEN, N_SEQ, C_DIM, 0);
}

// round 9
// speedup vs baseline: 4.9387x; 1.1026x over previous
#include <cuda_runtime.h>
#include <stdint.h>

#define BATCH    8
#define C_DIM    512
#define N_SEQ    2048
#define HEADS    8
#define QKV_ROWS 1536
#define HIDDEN   512
#define SM_SCALE_LOG2 0.18033688011112042f  // dhead^-0.5 * log2(e)

__device__ float g_qkv[(size_t)BATCH * QKV_ROWS * N_SEQ];
__device__ float g_att[(size_t)BATCH * HIDDEN * N_SEQ];
#define WQ_ELEMS (QKV_ROWS * C_DIM)
#define WO_ELEMS (HIDDEN * C_DIM)
__device__ float g_wq[WQ_ELEMS];
__device__ float g_wo[WO_ELEMS];

__device__ __forceinline__ uint32_t f2tf(float f) {
    uint32_t r; asm("cvt.rna.tf32.f32 %0, %1;" : "=r"(r) : "f"(f)); return r;
}
__device__ __forceinline__ uint32_t u2tf(uint32_t u) {
    uint32_t r; asm("cvt.rna.tf32.f32 %0, %1;" : "=r"(r) : "f"(__uint_as_float(u)));
    return r;
}
__device__ __forceinline__ float ex2(float x) {
    float r; asm("ex2.approx.f32 %0, %1;" : "=f"(r) : "f"(x)); return r;
}
__device__ __forceinline__ void mma8(float* c, const uint32_t* a, const uint32_t* b) {
    asm volatile(
        "mma.sync.aligned.m16n8k8.row.col.f32.tf32.tf32.f32 "
        "{%0,%1,%2,%3},{%4,%5,%6,%7},{%8,%9},{%0,%1,%2,%3};"
        : "+f"(c[0]), "+f"(c[1]), "+f"(c[2]), "+f"(c[3])
        : "r"(a[0]), "r"(a[1]), "r"(a[2]), "r"(a[3]), "r"(b[0]), "r"(b[1]));
}
__device__ __forceinline__ void cpa16(uint32_t s, const void* g) {
    asm volatile("cp.async.cg.shared.global [%0], [%1], 16;" :: "r"(s), "l"(g));
}

// ---------------- weight pre-rounding to tf32 (runs every call) --------------
__global__ __launch_bounds__(256) void round_w(
    const float* __restrict__ wq, const float* __restrict__ wo,
    float* __restrict__ dq, float* __restrict__ dwo)
{
    int i = (blockIdx.x * 256 + threadIdx.x) * 4;
    if (i < WQ_ELEMS) {
        float4 v = *(const float4*)(wq + i);
        v.x = __uint_as_float(f2tf(v.x)); v.y = __uint_as_float(f2tf(v.y));
        v.z = __uint_as_float(f2tf(v.z)); v.w = __uint_as_float(f2tf(v.w));
        *(float4*)(dq + i) = v;
    } else {
        int j = i - WQ_ELEMS;
        float4 v = *(const float4*)(wo + j);
        v.x = __uint_as_float(f2tf(v.x)); v.y = __uint_as_float(f2tf(v.y));
        v.z = __uint_as_float(f2tf(v.z)); v.w = __uint_as_float(f2tf(v.w));
        *(float4*)(dwo + j) = v;
    }
}

// ---------- tf32 GEMM: 3-stage cp.async ring; A pre-rounded (raw frags) ------
#define ASTR 36
#define BSTR 136
#define AWORDS (128 * ASTR)
#define BWORDS (32 * BSTR)
#define STG_WORDS (AWORDS + BWORDS)
#define GEMM_SMEM (3 * STG_WORDS * 4)

template <int CVT_B, int ROUND_C>
__global__ __launch_bounds__(256, 2) void gemm_tf32(
    const float* __restrict__ A, const float* __restrict__ Bg,
    float* __restrict__ Cg, const float* __restrict__ bias,
    int M, int N, int K)
{
    extern __shared__ uint32_t gsm[];
    const uint32_t smem_u32 = (uint32_t)__cvta_generic_to_shared(gsm);

    const float* B = Bg + (size_t)blockIdx.z * K * N;
    float*       C = Cg + (size_t)blockIdx.z * M * N;
    const int brow = blockIdx.y * 128;
    const int bcol = blockIdx.x * 128;
    const int tid  = threadIdx.x;
    const int lane = tid & 31;
    const int w    = tid >> 5;
    const int wm   = (w >> 2) * 64;
    const int wn   = (w & 3) * 32;
    const int g    = lane >> 2;
    const int t    = lane & 3;

    const int nIters = K >> 5;

#pragma unroll
    for (int s = 0; s < 2; s++) {
        const int k0 = s * 32;
        const uint32_t ab = smem_u32 + (uint32_t)(s * STG_WORDS) * 4;
        const uint32_t bb = ab + AWORDS * 4;
#pragma unroll
        for (int r = 0; r < 4; r++) {
            int idx = r * 256 + tid;
            int m = idx >> 3, k4 = (idx & 7) * 4;
            cpa16(ab + (uint32_t)(m * ASTR + k4) * 4,
                  A + (size_t)(brow + m) * K + k0 + k4);
        }
#pragma unroll
        for (int r = 0; r < 4; r++) {
            int idx = r * 256 + tid;
            int kk = idx >> 5, n4 = (idx & 31) * 4;
            cpa16(bb + (uint32_t)(kk * BSTR + n4) * 4,
                  B + (size_t)(k0 + kk) * N + bcol + n4);
        }
        asm volatile("cp.async.commit_group;");
    }

    float acc[4][4][4];
#pragma unroll
    for (int mt = 0; mt < 4; mt++)
#pragma unroll
        for (int nt = 0; nt < 4; nt++)
#pragma unroll
            for (int c = 0; c < 4; c++) acc[mt][nt][c] = 0.f;

    int cur = 0;
    for (int it = 0; it < nIters; it++) {
        if (it + 1 < nIters) asm volatile("cp.async.wait_group 1;");
        else                 asm volatile("cp.async.wait_group 0;");
        __syncthreads();

        if (it + 2 < nIters) {
            const int s = (it + 2) % 3;
            const int k0 = (it + 2) * 32;
            const uint32_t ab = smem_u32 + (uint32_t)(s * STG_WORDS) * 4;
            const uint32_t bb = ab + AWORDS * 4;
#pragma unroll
            for (int r = 0; r < 4; r++) {
                int idx = r * 256 + tid;
                int m = idx >> 3, k4 = (idx & 7) * 4;
                cpa16(ab + (uint32_t)(m * ASTR + k4) * 4,
                      A + (size_t)(brow + m) * K + k0 + k4);
            }
#pragma unroll
            for (int r = 0; r < 4; r++) {
                int idx = r * 256 + tid;
                int kk = idx >> 5, n4 = (idx & 31) * 4;
                cpa16(bb + (uint32_t)(kk * BSTR + n4) * 4,
                      B + (size_t)(k0 + kk) * N + bcol + n4);
            }
        }
        asm volatile("cp.async.commit_group;");

        const uint32_t* As = gsm + cur * STG_WORDS;
        const uint32_t* Bs = As + AWORDS;

#pragma unroll
        for (int kc = 0; kc < 4; kc++) {
            const int k8 = kc * 8;
            uint32_t af[4][4], bf[4][2];
#pragma unroll
            for (int mt = 0; mt < 4; mt++) {
                const int r0 = wm + mt * 16 + g;
                af[mt][0] = As[r0 * ASTR + k8 + t];          // pre-rounded, raw
                af[mt][1] = As[(r0 + 8) * ASTR + k8 + t];
                af[mt][2] = As[r0 * ASTR + k8 + t + 4];
                af[mt][3] = As[(r0 + 8) * ASTR + k8 + t + 4];
            }
#pragma unroll
            for (int nt = 0; nt < 4; nt++) {
                const int c0 = wn + nt * 8 + g;
                if (CVT_B) {
                    bf[nt][0] = u2tf(Bs[(k8 + t) * BSTR + c0]);
                    bf[nt][1] = u2tf(Bs[(k8 + t + 4) * BSTR + c0]);
                } else {
                    bf[nt][0] = Bs[(k8 + t) * BSTR + c0];    // pre-rounded, raw
                    bf[nt][1] = Bs[(k8 + t + 4) * BSTR + c0];
                }
            }
#pragma unroll
            for (int mt = 0; mt < 4; mt++)
#pragma unroll
                for (int nt = 0; nt < 4; nt++)
                    mma8(acc[mt][nt], af[mt], bf[nt]);
        }
        cur = (cur + 1) % 3;
    }

#pragma unroll
    for (int mt = 0; mt < 4; mt++) {
        const int r0 = brow + wm + mt * 16 + g;
        const float b0 = bias ? bias[r0] : 0.f;
        const float b1 = bias ? bias[r0 + 8] : 0.f;
#pragma unroll
        for (int nt = 0; nt < 4; nt++) {
            const int c = bcol + wn + nt * 8 + 2 * t;
            float v0 = acc[mt][nt][0] + b0, v1 = acc[mt][nt][1] + b0;
            float v2 = acc[mt][nt][2] + b1, v3 = acc[mt][nt][3] + b1;
            if (ROUND_C) {
                v0 = __uint_as_float(f2tf(v0));
                v1 = __uint_as_float(f2tf(v1));
                v2 = __uint_as_float(f2tf(v2));
                v3 = __uint_as_float(f2tf(v3));
            }
            *(float2*)(C + (size_t)r0 * N + c)       = make_float2(v0, v1);
            *(float2*)(C + (size_t)(r0 + 8) * N + c) = make_float2(v2, v3);
        }
    }
}

// ------- flash: no P smem (permuted-key trick), 3-stage K/V ring, 1 sync/tile
#define KVSTR 72
#define VOFF  (64 * KVSTR)                  // V inside a slot
#define SLOT_WORDS (2 * 64 * KVSTR)         // 9216 words (36864 B)
#define FLASH_SMEM (3 * SLOT_WORDS * 4)     // 110592 B
#define QTMP_STR 68
#define OS_STR 132
#define NTILES (N_SEQ / 64)

__global__ __launch_bounds__(128, 2) void flash_tf32(
    const float* __restrict__ qkv, float* __restrict__ outp)
{
    extern __shared__ uint32_t sm[];
    const uint32_t smem_u32 = (uint32_t)__cvta_generic_to_shared(sm);

    const int b  = blockIdx.z;
    const int h  = blockIdx.y;
    const int q0 = blockIdx.x * 128;
    const float* Q  = qkv + ((size_t)b * QKV_ROWS + h * 64) * N_SEQ;
    const float* Kp = Q + (size_t)512 * N_SEQ;
    const float* Vp = Q + (size_t)1024 * N_SEQ;

    const int tid  = threadIdx.x;
    const int lane = tid & 31;
    const int w    = tid >> 5;
    const int g    = lane >> 2;
    const int t    = lane & 3;
    const int rb0  = w * 32;
    const int rA0  = rb0 + g,      rA1 = rb0 + g + 8;
    const int rB0  = rb0 + 16 + g, rB1 = rb0 + 16 + g + 8;

    // prefetch tile 0 -> slot 0  (G0)
#pragma unroll
    for (int u = 0; u < 8; u++) {
        int idx = u * 128 + tid;
        int d = idx >> 4, j4 = (idx & 15) * 4;
        cpa16(smem_u32 + (uint32_t)(d * KVSTR + j4) * 4,
              Kp + (size_t)d * N_SEQ + j4);
        cpa16(smem_u32 + (uint32_t)(VOFF + d * KVSTR + j4) * 4,
              Vp + (size_t)d * N_SEQ + j4);
    }
    asm volatile("cp.async.commit_group;");

    // Q staging into slot1 region (temp), scale baked, rounded
    uint32_t* Qt = sm + SLOT_WORDS;
#pragma unroll
    for (int grp = 0; grp < 8; grp++) {
        const float* qp = Q + (size_t)(grp * 8) * N_SEQ + q0 + tid;
        uint32_t v[8];
#pragma unroll
        for (int c = 0; c < 8; c++)
            v[c] = f2tf(qp[(size_t)c * N_SEQ] * SM_SCALE_LOG2);
        *(uint4*)&Qt[tid * QTMP_STR + grp * 8]     = make_uint4(v[0], v[1], v[2], v[3]);
        *(uint4*)&Qt[tid * QTMP_STR + grp * 8 + 4] = make_uint4(v[4], v[5], v[6], v[7]);
    }
    __syncthreads();

    uint32_t qf[8][8];
#pragma unroll
    for (int kc = 0; kc < 8; kc++) {
        const int d8 = kc * 8;
        qf[kc][0] = Qt[rA0 * QTMP_STR + d8 + t];
        qf[kc][1] = Qt[rA1 * QTMP_STR + d8 + t];
        qf[kc][2] = Qt[rA0 * QTMP_STR + d8 + t + 4];
        qf[kc][3] = Qt[rA1 * QTMP_STR + d8 + t + 4];
        qf[kc][4] = Qt[rB0 * QTMP_STR + d8 + t];
        qf[kc][5] = Qt[rB1 * QTMP_STR + d8 + t];
        qf[kc][6] = Qt[rB0 * QTMP_STR + d8 + t + 4];
        qf[kc][7] = Qt[rB1 * QTMP_STR + d8 + t + 4];
    }
    __syncthreads();   // all Q-frag loads done before slot1 is overwritten

    // prefetch tile 1 -> slot 1  (G1)
#pragma unroll
    for (int u = 0; u < 8; u++) {
        int idx = u * 128 + tid;
        int d = idx >> 4, j4 = (idx & 15) * 4;
        cpa16(smem_u32 + (uint32_t)(SLOT_WORDS + d * KVSTR + j4) * 4,
              Kp + (size_t)d * N_SEQ + 64 + j4);
        cpa16(smem_u32 + (uint32_t)(SLOT_WORDS + VOFF + d * KVSTR + j4) * 4,
              Vp + (size_t)d * N_SEQ + 64 + j4);
    }
    asm volatile("cp.async.commit_group;");

    float o[2][8][4];
#pragma unroll
    for (int mt = 0; mt < 2; mt++)
#pragma unroll
        for (int dt = 0; dt < 8; dt++)
#pragma unroll
            for (int c = 0; c < 4; c++) o[mt][dt][c] = 0.f;
    float mrow[2][2] = {{-1e30f, -1e30f}, {-1e30f, -1e30f}};
    float lrow[2][2] = {{0.f, 0.f}, {0.f, 0.f}};

    int slot = 0, pslot = 2;
    for (int tI = 0; tI < NTILES; tI++) {
        if (tI < NTILES - 1) asm volatile("cp.async.wait_group 1;");
        else                 asm volatile("cp.async.wait_group 0;");
        __syncthreads();   // publish tile tI; all warps past tile tI-1's reads

        if (tI + 2 < NTILES) {
            const int j1 = (tI + 2) * 64;
            const uint32_t sb = smem_u32 + (uint32_t)(pslot * SLOT_WORDS) * 4;
#pragma unroll
            for (int u = 0; u < 8; u++) {
                int idx = u * 128 + tid;
                int d = idx >> 4, j4 = (idx & 15) * 4;
                cpa16(sb + (uint32_t)(d * KVSTR + j4) * 4,
                      Kp + (size_t)d * N_SEQ + j1 + j4);
                cpa16(sb + (uint32_t)(VOFF + d * KVSTR + j4) * 4,
                      Vp + (size_t)d * N_SEQ + j1 + j4);
            }
            asm volatile("cp.async.commit_group;");
        }

        const uint32_t* Kc = sm + slot * SLOT_WORDS;
        const uint32_t* Vc = Kc + VOFF;

        // S = Q @ K^T : 32 q rows x 64 keys (A-frags from registers)
        float s[2][8][4];
#pragma unroll
        for (int mt = 0; mt < 2; mt++)
#pragma unroll
            for (int nt = 0; nt < 8; nt++)
#pragma unroll
                for (int c = 0; c < 4; c++) s[mt][nt][c] = 0.f;
#pragma unroll
        for (int kc = 0; kc < 8; kc++) {
            const int d8 = kc * 8;
#pragma unroll
            for (int nt = 0; nt < 8; nt++) {
                uint32_t bb[2];
                bb[0] = Kc[(d8 + t) * KVSTR + nt * 8 + g];
                bb[1] = Kc[(d8 + t + 4) * KVSTR + nt * 8 + g];
                mma8(s[0][nt], &qf[kc][0], bb);
                mma8(s[1][nt], &qf[kc][4], bb);
            }
        }

        // online softmax (exp2 domain); p stored back into s as tf32 bits
#pragma unroll
        for (int mt = 0; mt < 2; mt++) {
            float mx0 = -1e30f, mx1 = -1e30f;
#pragma unroll
            for (int nt = 0; nt < 8; nt++) {
                mx0 = fmaxf(mx0, fmaxf(s[mt][nt][0], s[mt][nt][1]));
                mx1 = fmaxf(mx1, fmaxf(s[mt][nt][2], s[mt][nt][3]));
            }
            mx0 = fmaxf(mx0, __shfl_xor_sync(0xffffffffu, mx0, 1));
            mx0 = fmaxf(mx0, __shfl_xor_sync(0xffffffffu, mx0, 2));
            mx1 = fmaxf(mx1, __shfl_xor_sync(0xffffffffu, mx1, 1));
            mx1 = fmaxf(mx1, __shfl_xor_sync(0xffffffffu, mx1, 2));

            const float nm0 = fmaxf(mrow[mt][0], mx0);
            const float nm1 = fmaxf(mrow[mt][1], mx1);
            const float al0 = ex2(mrow[mt][0] - nm0);
            const float al1 = ex2(mrow[mt][1] - nm1);

            float ps0 = 0.f, ps1 = 0.f;
#pragma unroll
            for (int nt = 0; nt < 8; nt++) {
                float p0 = ex2(s[mt][nt][0] - nm0);
                float p1 = ex2(s[mt][nt][1] - nm0);
                float p2 = ex2(s[mt][nt][2] - nm1);
                float p3 = ex2(s[mt][nt][3] - nm1);
                ps0 += p0 + p1; ps1 += p2 + p3;
                s[mt][nt][0] = __uint_as_float(f2tf(p0));
                s[mt][nt][1] = __uint_as_float(f2tf(p1));
                s[mt][nt][2] = __uint_as_float(f2tf(p2));
                s[mt][nt][3] = __uint_as_float(f2tf(p3));
            }
            ps0 += __shfl_xor_sync(0xffffffffu, ps0, 1);
            ps0 += __shfl_xor_sync(0xffffffffu, ps0, 2);
            ps1 += __shfl_xor_sync(0xffffffffu, ps1, 1);
            ps1 += __shfl_xor_sync(0xffffffffu, ps1, 2);
            lrow[mt][0] = lrow[mt][0] * al0 + ps0;
            lrow[mt][1] = lrow[mt][1] * al1 + ps1;
            mrow[mt][0] = nm0; mrow[mt][1] = nm1;

#pragma unroll
            for (int dt = 0; dt < 8; dt++) {
                o[mt][dt][0] *= al0; o[mt][dt][1] *= al0;
                o[mt][dt][2] *= al1; o[mt][dt][3] *= al1;
            }
        }

        // O += P @ V, P fed straight from C-regs (keys implicitly permuted
        // p<4 -> col 2p, p>=4 -> col 2(p-4)+1); V B-frags read at cols
        // {j8+2t, j8+2t+1} to match -> adjacent -> LDS.64 (conflict-free @72)
#pragma unroll
        for (int nt = 0; nt < 8; nt++) {
            const int j8 = nt * 8;
            uint32_t a0c[4], a1c[4];
            a0c[0] = __float_as_uint(s[0][nt][0]);   // (row g,   slot t)
            a0c[1] = __float_as_uint(s[0][nt][2]);   // (row g+8, slot t)
            a0c[2] = __float_as_uint(s[0][nt][1]);   // (row g,   slot t+4)
            a0c[3] = __float_as_uint(s[0][nt][3]);   // (row g+8, slot t+4)
            a1c[0] = __float_as_uint(s[1][nt][0]);
            a1c[1] = __float_as_uint(s[1][nt][2]);
            a1c[2] = __float_as_uint(s[1][nt][1]);
            a1c[3] = __float_as_uint(s[1][nt][3]);
#pragma unroll
            for (int dt = 0; dt < 8; dt++) {
                uint2 bv = *(const uint2*)&Vc[(dt * 8 + g) * KVSTR + j8 + 2 * t];
                mma8(o[0][dt], a0c, (const uint32_t*)&bv);
                mma8(o[1][dt], a1c, (const uint32_t*)&bv);
            }
        }

        slot  = (slot  == 2) ? 0 : slot + 1;
        pslot = (pslot == 2) ? 0 : pslot + 1;
    }

    // O staging in slot0 (tile31 used slot1; slot0 free) as Os[64 d][132 i]
    float* Os = (float*)sm;
#pragma unroll
    for (int mt = 0; mt < 2; mt++) {
        const int q0r = (mt == 0) ? rA0 : rB0;
        const int q1r = (mt == 0) ? rA1 : rB1;
        const float inv0 = 1.f / lrow[mt][0];
        const float inv1 = 1.f / lrow[mt][1];
#pragma unroll
        for (int dt = 0; dt < 8; dt++) {
            const int d = dt * 8 + 2 * t;
            // pre-round to tf32 so gemm2 can consume raw
            Os[(size_t)d * OS_STR + q0r] =
                __uint_as_float(f2tf(o[mt][dt][0] * inv0));
            Os[(size_t)(d + 1) * OS_STR + q0r] =
                __uint_as_float(f2tf(o[mt][dt][1] * inv0));
            Os[(size_t)d * OS_STR + q1r] =
                __uint_as_float(f2tf(o[mt][dt][2] * inv1));
            Os[(size_t)(d + 1) * OS_STR + q1r] =
                __uint_as_float(f2tf(o[mt][dt][3] * inv1));
        }
    }
    __syncthreads();

    float* out = outp + ((size_t)b * HIDDEN + h * 64) * N_SEQ;
#pragma unroll
    for (int u = 0; u < 16; u++) {
        int idx = u * 128 + tid;
        int d = idx >> 5, i4 = (idx & 31) * 4;
        float4 v;
        v.x = Os[(size_t)d * OS_STR + i4 + 0];
        v.y = Os[(size_t)d * OS_STR + i4 + 1];
        v.z = Os[(size_t)d * OS_STR + i4 + 2];
        v.w = Os[(size_t)d * OS_STR + i4 + 3];
        *(float4*)(out + (size_t)d * N_SEQ + q0 + i4) = v;
    }
}

// ---------------------------------------------------------------------------
extern "C" void kernel_launch(void* const* d_in, const int* in_sizes, int n_in,
                              void* d_out, int out_size)
{
    const float* x     = (const float*)d_in[0];
    const float* w_qkv = (const float*)d_in[1];
    const float* w_out = (const float*)d_in[2];
    const float* b_out = (const float*)d_in[3];
    float* y = (float*)d_out;

    float* qkv = nullptr, *att = nullptr, *wq = nullptr, *wo = nullptr;
    cudaGetSymbolAddress((void**)&qkv, g_qkv);
    cudaGetSymbolAddress((void**)&att, g_att);
    cudaGetSymbolAddress((void**)&wq, g_wq);
    cudaGetSymbolAddress((void**)&wo, g_wo);

    cudaFuncSetAttribute(gemm_tf32<1, 1>,
                         cudaFuncAttributeMaxDynamicSharedMemorySize, GEMM_SMEM);
    cudaFuncSetAttribute(gemm_tf32<0, 0>,
                         cudaFuncAttributeMaxDynamicSharedMemorySize, GEMM_SMEM);
    cudaFuncSetAttribute(flash_tf32,
                         cudaFuncAttributeMaxDynamicSharedMemorySize, FLASH_SMEM);

    // 0) pre-round weights to tf32
    round_w<<<(WQ_ELEMS + WO_ELEMS) / 1024, 256>>>(w_qkv, w_out, wq, wo);

    // 1) qkv = w_qkv @ x (A raw pre-rounded, B cvt in-loop, C rounded to tf32)
    gemm_tf32<1, 1><<<dim3(N_SEQ / 128, QKV_ROWS / 128, BATCH), 256, GEMM_SMEM>>>(
        wq, x, qkv, nullptr, QKV_ROWS, N_SEQ, C_DIM);

    // 2) fused flash attention (output pre-rounded to tf32)
    flash_tf32<<<dim3(N_SEQ / 128, HEADS, BATCH), 128, FLASH_SMEM>>>(qkv, att);

    // 3) y = w_out @ att + b_out (A and B raw pre-rounded, C full fp32)
    gemm_tf32<0, 0><<<dim3(N_SEQ / 128, HIDDEN / 128, BATCH), 256, GEMM_SMEM>>>(
        wo, att, y, b_out, HIDDEN, N_SEQ, C_DIM);
}

// round 12
// speedup vs baseline: 6.7585x; 1.3685x over previous
#include <cuda_runtime.h>
#include <cuda_fp16.h>
#include <stdint.h>

#define BATCH    8
#define C_DIM    512
#define N_SEQ    2048
#define HEADS    8
#define QKV_ROWS 1536
#define HIDDEN   512
#define SM_SCALE_LOG2 0.18033688011112042f  // dhead^-0.5 * log2(e)

// scratch
__device__ __align__(256) __half g_qt[(size_t)BATCH * HEADS * N_SEQ * 64];  // Q^T [b][h][i][d], pre-scaled
__device__ __align__(256) __half g_kt[(size_t)BATCH * HEADS * N_SEQ * 64];  // K^T [b][h][j][d]
__device__ __align__(256) __half g_vh[(size_t)BATCH * HIDDEN * N_SEQ];      // V   [b][h*64+d][j]
__device__ float g_att[(size_t)BATCH * HIDDEN * N_SEQ];
#define WQ_ELEMS (QKV_ROWS * C_DIM)
#define WO_ELEMS (HIDDEN * C_DIM)
__device__ float g_wq[WQ_ELEMS];
__device__ float g_wo[WO_ELEMS];

__device__ __forceinline__ uint32_t f2tf(float f) {
    uint32_t r; asm("cvt.rna.tf32.f32 %0, %1;" : "=r"(r) : "f"(f)); return r;
}
__device__ __forceinline__ uint32_t u2tf(uint32_t u) {
    uint32_t r; asm("cvt.rna.tf32.f32 %0, %1;" : "=r"(r) : "f"(__uint_as_float(u)));
    return r;
}
__device__ __forceinline__ float ex2(float x) {
    float r; asm("ex2.approx.f32 %0, %1;" : "=f"(r) : "f"(x)); return r;
}
__device__ __forceinline__ void mma8(float* c, const uint32_t* a, const uint32_t* b) {
    asm volatile(
        "mma.sync.aligned.m16n8k8.row.col.f32.tf32.tf32.f32 "
        "{%0,%1,%2,%3},{%4,%5,%6,%7},{%8,%9},{%0,%1,%2,%3};"
        : "+f"(c[0]), "+f"(c[1]), "+f"(c[2]), "+f"(c[3])
        : "r"(a[0]), "r"(a[1]), "r"(a[2]), "r"(a[3]), "r"(b[0]), "r"(b[1]));
}
__device__ __forceinline__ void mma16(float* c, const uint32_t* a, const uint32_t* b) {
    asm volatile(
        "mma.sync.aligned.m16n8k16.row.col.f32.f16.f16.f32 "
        "{%0,%1,%2,%3},{%4,%5,%6,%7},{%8,%9},{%0,%1,%2,%3};"
        : "+f"(c[0]), "+f"(c[1]), "+f"(c[2]), "+f"(c[3])
        : "r"(a[0]), "r"(a[1]), "r"(a[2]), "r"(a[3]), "r"(b[0]), "r"(b[1]));
}
__device__ __forceinline__ void cpa16(uint32_t s, const void* g) {
    asm volatile("cp.async.cg.shared.global [%0], [%1], 16;" :: "r"(s), "l"(g));
}
__device__ __forceinline__ uint32_t packh2(float a, float b) {
    __half2 h = __floats2half2_rn(a, b);   // .x(lo)=a, .y(hi)=b
    return *(uint32_t*)&h;
}

// ---------------- weight pre-rounding to tf32 --------------------------------
__global__ __launch_bounds__(256) void round_w(
    const float* __restrict__ wq, const float* __restrict__ wo,
    float* __restrict__ dq, float* __restrict__ dwo)
{
    int i = (blockIdx.x * 256 + threadIdx.x) * 4;
    if (i < WQ_ELEMS) {
        float4 v = *(const float4*)(wq + i);
        v.x = __uint_as_float(f2tf(v.x)); v.y = __uint_as_float(f2tf(v.y));
        v.z = __uint_as_float(f2tf(v.z)); v.w = __uint_as_float(f2tf(v.w));
        *(float4*)(dq + i) = v;
    } else {
        int j = i - WQ_ELEMS;
        float4 v = *(const float4*)(wo + j);
        v.x = __uint_as_float(f2tf(v.x)); v.y = __uint_as_float(f2tf(v.y));
        v.z = __uint_as_float(f2tf(v.z)); v.w = __uint_as_float(f2tf(v.w));
        *(float4*)(dwo + j) = v;
    }
}

// ---------- tf32 GEMM (R9 ring mainloop) + MODE epilogue ---------------------
// MODE 0: C fp32 + bias (out proj). MODE 1: QKV split -> fp16 Q^T/K^T/V.
#define ASTR 36
#define BSTR 136
#define AWORDS (128 * ASTR)
#define BWORDS (32 * BSTR)
#define STG_WORDS (AWORDS + BWORDS)
#define GEMM_SMEM (3 * STG_WORDS * 4)      // 107520 B (>= bounce 128*133*4)

template <int MODE>
__global__ __launch_bounds__(256, 2) void gemm_tf32(
    const float* __restrict__ A, const float* __restrict__ Bg,
    float* __restrict__ Cg, const float* __restrict__ bias,
    __half* __restrict__ qt, __half* __restrict__ kt, __half* __restrict__ vh,
    int N, int K)
{
    extern __shared__ uint32_t gsm[];
    const uint32_t smem_u32 = (uint32_t)__cvta_generic_to_shared(gsm);

    const float* B = Bg + (size_t)blockIdx.z * K * N;
    const int brow = blockIdx.y * 128;
    const int bcol = blockIdx.x * 128;
    const int tid  = threadIdx.x;
    const int lane = tid & 31;
    const int w    = tid >> 5;
    const int wm   = (w >> 2) * 64;
    const int wn   = (w & 3) * 32;
    const int g    = lane >> 2;
    const int t    = lane & 3;

    const int nIters = K >> 5;

#pragma unroll
    for (int s = 0; s < 2; s++) {
        const int k0 = s * 32;
        const uint32_t ab = smem_u32 + (uint32_t)(s * STG_WORDS) * 4;
        const uint32_t bb = ab + AWORDS * 4;
#pragma unroll
        for (int r = 0; r < 4; r++) {
            int idx = r * 256 + tid;
            int m = idx >> 3, k4 = (idx & 7) * 4;
            cpa16(ab + (uint32_t)(m * ASTR + k4) * 4,
                  A + (size_t)(brow + m) * K + k0 + k4);
        }
#pragma unroll
        for (int r = 0; r < 4; r++) {
            int idx = r * 256 + tid;
            int kk = idx >> 5, n4 = (idx & 31) * 4;
            cpa16(bb + (uint32_t)(kk * BSTR + n4) * 4,
                  B + (size_t)(k0 + kk) * N + bcol + n4);
        }
        asm volatile("cp.async.commit_group;");
    }

    float acc[4][4][4];
#pragma unroll
    for (int mt = 0; mt < 4; mt++)
#pragma unroll
        for (int nt = 0; nt < 4; nt++)
#pragma unroll
            for (int c = 0; c < 4; c++) acc[mt][nt][c] = 0.f;

    int cur = 0;
    for (int it = 0; it < nIters; it++) {
        if (it + 1 < nIters) asm volatile("cp.async.wait_group 1;");
        else                 asm volatile("cp.async.wait_group 0;");
        __syncthreads();

        if (it + 2 < nIters) {
            const int s = (it + 2) % 3;
            const int k0 = (it + 2) * 32;
            const uint32_t ab = smem_u32 + (uint32_t)(s * STG_WORDS) * 4;
            const uint32_t bb = ab + AWORDS * 4;
#pragma unroll
            for (int r = 0; r < 4; r++) {
                int idx = r * 256 + tid;
                int m = idx >> 3, k4 = (idx & 7) * 4;
                cpa16(ab + (uint32_t)(m * ASTR + k4) * 4,
                      A + (size_t)(brow + m) * K + k0 + k4);
            }
#pragma unroll
            for (int r = 0; r < 4; r++) {
                int idx = r * 256 + tid;
                int kk = idx >> 5, n4 = (idx & 31) * 4;
                cpa16(bb + (uint32_t)(kk * BSTR + n4) * 4,
                      B + (size_t)(k0 + kk) * N + bcol + n4);
            }
        }
        asm volatile("cp.async.commit_group;");

        const uint32_t* As = gsm + cur * STG_WORDS;
        const uint32_t* Bs = As + AWORDS;

#pragma unroll
        for (int kc = 0; kc < 4; kc++) {
            const int k8 = kc * 8;
            uint32_t af[4][4], bf[4][2];
#pragma unroll
            for (int mt = 0; mt < 4; mt++) {
                const int r0 = wm + mt * 16 + g;
                af[mt][0] = As[r0 * ASTR + k8 + t];
                af[mt][1] = As[(r0 + 8) * ASTR + k8 + t];
                af[mt][2] = As[r0 * ASTR + k8 + t + 4];
                af[mt][3] = As[(r0 + 8) * ASTR + k8 + t + 4];
            }
#pragma unroll
            for (int nt = 0; nt < 4; nt++) {
                const int c0 = wn + nt * 8 + g;
                if (MODE == 1) {   // B = x raw fp32: cvt in-loop
                    bf[nt][0] = u2tf(Bs[(k8 + t) * BSTR + c0]);
                    bf[nt][1] = u2tf(Bs[(k8 + t + 4) * BSTR + c0]);
                } else {           // pre-rounded: raw
                    bf[nt][0] = Bs[(k8 + t) * BSTR + c0];
                    bf[nt][1] = Bs[(k8 + t + 4) * BSTR + c0];
                }
            }
#pragma unroll
            for (int mt = 0; mt < 4; mt++)
#pragma unroll
                for (int nt = 0; nt < 4; nt++)
                    mma8(acc[mt][nt], af[mt], bf[nt]);
        }
        cur = (cur + 1) % 3;
    }

    if (MODE == 0) {
        float* C = Cg + (size_t)blockIdx.z * (size_t)gridDim.y * 128 * N;
#pragma unroll
        for (int mt = 0; mt < 4; mt++) {
            const int r0 = brow + wm + mt * 16 + g;
            const float b0 = bias[r0];
            const float b1 = bias[r0 + 8];
#pragma unroll
            for (int nt = 0; nt < 4; nt++) {
                const int c = bcol + wn + nt * 8 + 2 * t;
                *(float2*)(C + (size_t)r0 * N + c) =
                    make_float2(acc[mt][nt][0] + b0, acc[mt][nt][1] + b0);
                *(float2*)(C + (size_t)(r0 + 8) * N + c) =
                    make_float2(acc[mt][nt][2] + b1, acc[mt][nt][3] + b1);
            }
        }
        return;
    }

    // MODE 1: bounce -> fp16 split outputs.
    // NOTE: stride 133 is odd, so stores MUST be scalar 4B (float2 at odd word
    // index is an 8B store on a 4B boundary -> misaligned trap; R11 bug).
    __syncthreads();                 // ring reads done; reuse smem as bounce
    float* Ob = (float*)gsm;         // [128][133]
#pragma unroll
    for (int mt = 0; mt < 4; mt++) {
        const int r0 = wm + mt * 16 + g;
#pragma unroll
        for (int nt = 0; nt < 4; nt++) {
            const int c = wn + nt * 8 + 2 * t;
            Ob[r0 * 133 + c]           = acc[mt][nt][0];
            Ob[r0 * 133 + c + 1]       = acc[mt][nt][1];
            Ob[(r0 + 8) * 133 + c]     = acc[mt][nt][2];
            Ob[(r0 + 8) * 133 + c + 1] = acc[mt][nt][3];
        }
    }
    __syncthreads();

    const int b = blockIdx.z;
    const int sec = brow >> 9;     // 0=Q, 1=K, 2=V
    if (sec < 2) {
        __half* base = (sec == 0) ? qt : kt;
        const float mul = (sec == 0) ? SM_SCALE_LOG2 : 1.f;
        const int hbase = (brow - sec * 512) >> 6;
#pragma unroll
        for (int u = 0; u < 8; u++) {
            int tau = u * 256 + tid;
            int chunk = tau & 7, orow = tau >> 3;
            int hh = orow >> 7, j = orow & 127;
            int d0 = chunk * 8;
            uint32_t pk[4];
#pragma unroll
            for (int q = 0; q < 4; q++) {
                float v0 = Ob[(hh * 64 + d0 + 2 * q) * 133 + j] * mul;
                float v1 = Ob[(hh * 64 + d0 + 2 * q + 1) * 133 + j] * mul;
                pk[q] = packh2(v0, v1);
            }
            __half* dst = base +
                (((size_t)b * 8 + hbase + hh) * N_SEQ + bcol + j) * 64 + d0;
            *(uint4*)dst = make_uint4(pk[0], pk[1], pk[2], pk[3]);
        }
    } else {
#pragma unroll
        for (int u = 0; u < 8; u++) {
            int tau = u * 256 + tid;
            int chunk = tau & 15, orow = tau >> 4;
            int c0 = chunk * 8;
            uint32_t pk[4];
#pragma unroll
            for (int q = 0; q < 4; q++) {
                float v0 = Ob[orow * 133 + c0 + 2 * q];
                float v1 = Ob[orow * 133 + c0 + 2 * q + 1];
                pk[q] = packh2(v0, v1);
            }
            __half* dst = vh +
                ((size_t)b * HIDDEN + (brow - 1024) + orow) * N_SEQ + bcol + c0;
            *(uint4*)dst = make_uint4(pk[0], pk[1], pk[2], pk[3]);
        }
    }
}

// ------- flash fp16: m16n8k16, all frags single CF LDS.32, 3-stage ring ------
#define KVW 36                          // words per 64-dim row (72 halfs, 144B)
#define SLOT_W (2 * 64 * KVW)           // K+V slot = 4608 words
#define QOFF_W (3 * SLOT_W)             // 13824
#define FLASH_SMEM ((QOFF_W + 128 * KVW) * 4)   // 73728 B
#define OS_STR 132
#define NTILES (N_SEQ / 64)

__global__ __launch_bounds__(128, 2) void flash_f16(
    const __half* __restrict__ qt, const __half* __restrict__ kt,
    const __half* __restrict__ vh, float* __restrict__ outp)
{
    extern __shared__ uint32_t sm[];
    const uint32_t sb = (uint32_t)__cvta_generic_to_shared(sm);

    const int b  = blockIdx.z;
    const int h  = blockIdx.y;
    const int q0 = blockIdx.x * 128;
    const __half* qp = qt + (((size_t)b * 8 + h) * N_SEQ + q0) * 64;
    const __half* kp = kt + (((size_t)b * 8 + h) * N_SEQ) * 64;
    const __half* vp = vh + ((size_t)b * HIDDEN + h * 64) * N_SEQ;

    const int tid  = threadIdx.x;
    const int lane = tid & 31;
    const int w    = tid >> 5;
    const int g    = lane >> 2;
    const int t    = lane & 3;
    const int rb0  = w * 32;
    const int rA0  = rb0 + g,      rA1 = rb0 + g + 8;
    const int rB0  = rb0 + 16 + g, rB1 = rb0 + 16 + g + 8;

    // Q cp.async: 128 rows x 8 chunks
#pragma unroll
    for (int u = 0; u < 8; u++) {
        int idx = u * 128 + tid;
        int i = idx >> 3, ch = idx & 7;
        cpa16(sb + (uint32_t)(QOFF_W + i * KVW + ch * 4) * 4,
              qp + (size_t)i * 64 + ch * 8);
    }
    asm volatile("cp.async.commit_group;");

    // K/V tiles 0,1
#pragma unroll
    for (int s = 0; s < 2; s++) {
        const int j0 = s * 64;
#pragma unroll
        for (int u = 0; u < 8; u++) {
            int idx = u * 128 + tid;
            int kv = idx >> 9, r = (idx >> 3) & 63, ch = idx & 7;
            const __half* src = kv
                ? vp + (size_t)r * N_SEQ + j0 + ch * 8
                : kp + (size_t)(j0 + r) * 64 + ch * 8;
            cpa16(sb + (uint32_t)(s * SLOT_W + kv * 64 * KVW + r * KVW + ch * 4) * 4,
                  src);
        }
        asm volatile("cp.async.commit_group;");
    }

    asm volatile("cp.async.wait_group 2;");   // Q landed
    __syncthreads();
    const uint32_t* Qs = sm + QOFF_W;
    uint32_t qf[4][8];
#pragma unroll
    for (int kc = 0; kc < 4; kc++) {
        const int k8 = kc * 8;
        qf[kc][0] = Qs[rA0 * KVW + k8 + t];
        qf[kc][1] = Qs[rA1 * KVW + k8 + t];
        qf[kc][2] = Qs[rA0 * KVW + k8 + 4 + t];
        qf[kc][3] = Qs[rA1 * KVW + k8 + 4 + t];
        qf[kc][4] = Qs[rB0 * KVW + k8 + t];
        qf[kc][5] = Qs[rB1 * KVW + k8 + t];
        qf[kc][6] = Qs[rB0 * KVW + k8 + 4 + t];
        qf[kc][7] = Qs[rB1 * KVW + k8 + 4 + t];
    }

    float o[2][8][4];
#pragma unroll
    for (int mt = 0; mt < 2; mt++)
#pragma unroll
        for (int dt = 0; dt < 8; dt++)
#pragma unroll
            for (int c = 0; c < 4; c++) o[mt][dt][c] = 0.f;
    float mrow[2][2] = {{-1e30f, -1e30f}, {-1e30f, -1e30f}};
    float lrow[2][2] = {{0.f, 0.f}, {0.f, 0.f}};

    int slot = 0, pslot = 2;
    for (int tI = 0; tI < NTILES; tI++) {
        if (tI < NTILES - 1) asm volatile("cp.async.wait_group 1;");
        else                 asm volatile("cp.async.wait_group 0;");
        __syncthreads();

        if (tI + 2 < NTILES) {
            const int j1 = (tI + 2) * 64;
#pragma unroll
            for (int u = 0; u < 8; u++) {
                int idx = u * 128 + tid;
                int kv = idx >> 9, r = (idx >> 3) & 63, ch = idx & 7;
                const __half* src = kv
                    ? vp + (size_t)r * N_SEQ + j1 + ch * 8
                    : kp + (size_t)(j1 + r) * 64 + ch * 8;
                cpa16(sb + (uint32_t)(pslot * SLOT_W + kv * 64 * KVW + r * KVW + ch * 4) * 4,
                      src);
            }
            asm volatile("cp.async.commit_group;");
        }

        const uint32_t* Kc = sm + slot * SLOT_W;
        const uint32_t* Vc = Kc + 64 * KVW;

        // S = Q @ K^T (fp16 k16): 4 kc x 8 nt
        float s[2][8][4];
#pragma unroll
        for (int mt = 0; mt < 2; mt++)
#pragma unroll
            for (int nt = 0; nt < 8; nt++)
#pragma unroll
                for (int c = 0; c < 4; c++) s[mt][nt][c] = 0.f;
#pragma unroll
        for (int kc = 0; kc < 4; kc++) {
            const int k8 = kc * 8;
#pragma unroll
            for (int nt = 0; nt < 8; nt++) {
                const uint32_t* kr = Kc + (nt * 8 + g) * KVW;
                uint32_t bb[2];
                bb[0] = kr[k8 + t];
                bb[1] = kr[k8 + 4 + t];
                mma16(s[0][nt], &qf[kc][0], bb);
                mma16(s[1][nt], &qf[kc][4], bb);
            }
        }

        // online softmax (exp2 domain; scale baked into Q at gemm1)
        uint32_t pk[2][8][2];
#pragma unroll
        for (int mt = 0; mt < 2; mt++) {
            float mx0 = -1e30f, mx1 = -1e30f;
#pragma unroll
            for (int nt = 0; nt < 8; nt++) {
                mx0 = fmaxf(mx0, fmaxf(s[mt][nt][0], s[mt][nt][1]));
                mx1 = fmaxf(mx1, fmaxf(s[mt][nt][2], s[mt][nt][3]));
            }
            mx0 = fmaxf(mx0, __shfl_xor_sync(0xffffffffu, mx0, 1));
            mx0 = fmaxf(mx0, __shfl_xor_sync(0xffffffffu, mx0, 2));
            mx1 = fmaxf(mx1, __shfl_xor_sync(0xffffffffu, mx1, 1));
            mx1 = fmaxf(mx1, __shfl_xor_sync(0xffffffffu, mx1, 2));

            const float nm0 = fmaxf(mrow[mt][0], mx0);
            const float nm1 = fmaxf(mrow[mt][1], mx1);
            const float al0 = ex2(mrow[mt][0] - nm0);
            const float al1 = ex2(mrow[mt][1] - nm1);

            float ps0 = 0.f, ps1 = 0.f;
#pragma unroll
            for (int nt = 0; nt < 8; nt++) {
                float p0 = ex2(s[mt][nt][0] - nm0);
                float p1 = ex2(s[mt][nt][1] - nm0);
                float p2 = ex2(s[mt][nt][2] - nm1);
                float p3 = ex2(s[mt][nt][3] - nm1);
                ps0 += p0 + p1; ps1 += p2 + p3;
                pk[mt][nt][0] = packh2(p0, p1);   // (row g,   j=2t,2t+1)
                pk[mt][nt][1] = packh2(p2, p3);   // (row g+8, j=2t,2t+1)
            }
            ps0 += __shfl_xor_sync(0xffffffffu, ps0, 1);
            ps0 += __shfl_xor_sync(0xffffffffu, ps0, 2);
            ps1 += __shfl_xor_sync(0xffffffffu, ps1, 1);
            ps1 += __shfl_xor_sync(0xffffffffu, ps1, 2);
            lrow[mt][0] = lrow[mt][0] * al0 + ps0;
            lrow[mt][1] = lrow[mt][1] * al1 + ps1;
            mrow[mt][0] = nm0; mrow[mt][1] = nm1;

#pragma unroll
            for (int dt = 0; dt < 8; dt++) {
                o[mt][dt][0] *= al0; o[mt][dt][1] *= al0;
                o[mt][dt][2] *= al1; o[mt][dt][3] *= al1;
            }
        }

        // O += P @ V (fp16 k16): A from packed P regs, B = V natural [d][j]
#pragma unroll
        for (int kc = 0; kc < 4; kc++) {
            const int k8 = kc * 8;
            uint32_t a0[4] = {pk[0][2*kc][0], pk[0][2*kc][1],
                              pk[0][2*kc+1][0], pk[0][2*kc+1][1]};
            uint32_t a1[4] = {pk[1][2*kc][0], pk[1][2*kc][1],
                              pk[1][2*kc+1][0], pk[1][2*kc+1][1]};
#pragma unroll
            for (int dt = 0; dt < 8; dt++) {
                const uint32_t* vr = Vc + (dt * 8 + g) * KVW;
                uint32_t bb[2];
                bb[0] = vr[k8 + t];
                bb[1] = vr[k8 + 4 + t];
                mma16(o[0][dt], a0, bb);
                mma16(o[1][dt], a1, bb);
            }
        }

        slot  = (slot  == 2) ? 0 : slot + 1;
        pslot = (pslot == 2) ? 0 : pslot + 1;
    }

    __syncthreads();   // all warps done reading slots; reuse as Os[64][132] f32
    float* Os = (float*)sm;
#pragma unroll
    for (int mt = 0; mt < 2; mt++) {
        const int q0r = (mt == 0) ? rA0 : rB0;
        const int q1r = (mt == 0) ? rA1 : rB1;
        const float inv0 = 1.f / lrow[mt][0];
        const float inv1 = 1.f / lrow[mt][1];
#pragma unroll
        for (int dt = 0; dt < 8; dt++) {
            const int d = dt * 8 + 2 * t;
            Os[(size_t)d * OS_STR + q0r] =
                __uint_as_float(f2tf(o[mt][dt][0] * inv0));
            Os[(size_t)(d + 1) * OS_STR + q0r] =
                __uint_as_float(f2tf(o[mt][dt][1] * inv0));
            Os[(size_t)d * OS_STR + q1r] =
                __uint_as_float(f2tf(o[mt][dt][2] * inv1));
            Os[(size_t)(d + 1) * OS_STR + q1r] =
                __uint_as_float(f2tf(o[mt][dt][3] * inv1));
        }
    }
    __syncthreads();

    float* out = outp + ((size_t)b * HIDDEN + h * 64) * N_SEQ;
#pragma unroll
    for (int u = 0; u < 16; u++) {
        int idx = u * 128 + tid;
        int d = idx >> 5, i4 = (idx & 31) * 4;
        float4 v;
        v.x = Os[(size_t)d * OS_STR + i4 + 0];
        v.y = Os[(size_t)d * OS_STR + i4 + 1];
        v.z = Os[(size_t)d * OS_STR + i4 + 2];
        v.w = Os[(size_t)d * OS_STR + i4 + 3];
        *(float4*)(out + (size_t)d * N_SEQ + q0 + i4) = v;
    }
}

// ---------------------------------------------------------------------------
extern "C" void kernel_launch(void* const* d_in, const int* in_sizes, int n_in,
                              void* d_out, int out_size)
{
    const float* x     = (const float*)d_in[0];
    const float* w_qkv = (const float*)d_in[1];
    const float* w_out = (const float*)d_in[2];
    const float* b_out = (const float*)d_in[3];
    float* y = (float*)d_out;

    float *att = nullptr, *wq = nullptr, *wo = nullptr;
    __half *qt = nullptr, *kt = nullptr, *vh = nullptr;
    cudaGetSymbolAddress((void**)&att, g_att);
    cudaGetSymbolAddress((void**)&wq, g_wq);
    cudaGetSymbolAddress((void**)&wo, g_wo);
    cudaGetSymbolAddress((void**)&qt, g_qt);
    cudaGetSymbolAddress((void**)&kt, g_kt);
    cudaGetSymbolAddress((void**)&vh, g_vh);

    cudaFuncSetAttribute(gemm_tf32<1>,
                         cudaFuncAttributeMaxDynamicSharedMemorySize, GEMM_SMEM);
    cudaFuncSetAttribute(gemm_tf32<0>,
                         cudaFuncAttributeMaxDynamicSharedMemorySize, GEMM_SMEM);
    cudaFuncSetAttribute(flash_f16,
                         cudaFuncAttributeMaxDynamicSharedMemorySize, FLASH_SMEM);

    // 0) pre-round weights to tf32
    round_w<<<(WQ_ELEMS + WO_ELEMS) / 1024, 256>>>(w_qkv, w_out, wq, wo);

    // 1) qkv projection -> fp16 Q^T (scaled), K^T, V
    gemm_tf32<1><<<dim3(N_SEQ / 128, QKV_ROWS / 128, BATCH), 256, GEMM_SMEM>>>(
        wq, x, nullptr, nullptr, qt, kt, vh, N_SEQ, C_DIM);

    // 2) fused flash attention (fp16 tensor path)
    flash_f16<<<dim3(N_SEQ / 128, HEADS, BATCH), 128, FLASH_SMEM>>>(
        qt, kt, vh, att);

    // 3) y = w_out @ att + b_out (tf32, raw pre-rounded operands)
    gemm_tf32<0><<<dim3(N_SEQ / 128, HIDDEN / 128, BATCH), 256, GEMM_SMEM>>>(
        wo, att, y, b_out, nullptr, nullptr, nullptr, N_SEQ, C_DIM);
}

// round 13
// speedup vs baseline: 7.7149x; 1.1415x over previous
#include <cuda_runtime.h>
#include <cuda_fp16.h>
#include <stdint.h>

#define BATCH    8
#define C_DIM    512
#define N_SEQ    2048
#define HEADS    8
#define QKV_ROWS 1536
#define HIDDEN   512
#define SM_SCALE_LOG2 0.18033688011112042f  // dhead^-0.5 * log2(e)

// scratch
__device__ __align__(256) __half g_qt[(size_t)BATCH * HEADS * N_SEQ * 64];  // Q^T [b][h][i][d], pre-scaled
__device__ __align__(256) __half g_kt[(size_t)BATCH * HEADS * N_SEQ * 64];  // K^T [b][h][j][d]
__device__ __align__(256) __half g_vh[(size_t)BATCH * HIDDEN * N_SEQ];      // V   [b][h*64+d][j]
__device__ __align__(256) __half g_attT[(size_t)BATCH * N_SEQ * HIDDEN];    // att^T [b][i][c]
__device__ __align__(256) __half g_xt[(size_t)BATCH * N_SEQ * C_DIM];       // x^T [b][n][c]
#define WQ_ELEMS (QKV_ROWS * C_DIM)
#define WO_ELEMS (HIDDEN * C_DIM)
__device__ __align__(256) __half g_wqh[WQ_ELEMS];
__device__ __align__(256) __half g_woh[WO_ELEMS];

__device__ __forceinline__ float ex2(float x) {
    float r; asm("ex2.approx.f32 %0, %1;" : "=f"(r) : "f"(x)); return r;
}
__device__ __forceinline__ void mma16(float* c, const uint32_t* a, const uint32_t* b) {
    asm volatile(
        "mma.sync.aligned.m16n8k16.row.col.f32.f16.f16.f32 "
        "{%0,%1,%2,%3},{%4,%5,%6,%7},{%8,%9},{%0,%1,%2,%3};"
        : "+f"(c[0]), "+f"(c[1]), "+f"(c[2]), "+f"(c[3])
        : "r"(a[0]), "r"(a[1]), "r"(a[2]), "r"(a[3]), "r"(b[0]), "r"(b[1]));
}
__device__ __forceinline__ void cpa16(uint32_t s, const void* g) {
    asm volatile("cp.async.cg.shared.global [%0], [%1], 16;" :: "r"(s), "l"(g));
}
__device__ __forceinline__ uint32_t packh2(float a, float b) {
    __half2 h = __floats2half2_rn(a, b);
    return *(uint32_t*)&h;
}

// ---------------- prepass: weights fp32 -> fp16 ------------------------------
__global__ __launch_bounds__(256) void cvt_w(
    const float* __restrict__ wq, const float* __restrict__ wo,
    __half* __restrict__ dq, __half* __restrict__ dwo)
{
    int i = (blockIdx.x * 256 + threadIdx.x) * 4;
    const float* s; __half* d; int j;
    if (i < WQ_ELEMS) { s = wq; d = dq;  j = i; }
    else              { s = wo; d = dwo; j = i - WQ_ELEMS; }
    float4 v = *(const float4*)(s + j);
    uint32_t p0 = packh2(v.x, v.y), p1 = packh2(v.z, v.w);
    *(uint2*)(d + j) = make_uint2(p0, p1);
}

// ---------------- prepass: x [b][c][n] fp32 -> x^T [b][n][c] fp16 ------------
__global__ __launch_bounds__(256) void cvt_x(
    const float* __restrict__ x, __half* __restrict__ xt)
{
    __shared__ __half Xs[64][72];
    const int b  = blockIdx.z;
    const int c0 = blockIdx.y * 64;
    const int n0 = blockIdx.x * 64;
    const int tid = threadIdx.x;
    const float* src = x + ((size_t)b * C_DIM + c0) * N_SEQ + n0;
#pragma unroll
    for (int u = 0; u < 4; u++) {
        int idx = u * 256 + tid;
        int c = idx >> 4, n4 = (idx & 15) * 4;
        float4 v = *(const float4*)(src + (size_t)c * N_SEQ + n4);
        Xs[n4 + 0][c] = __float2half(v.x);
        Xs[n4 + 1][c] = __float2half(v.y);
        Xs[n4 + 2][c] = __float2half(v.z);
        Xs[n4 + 3][c] = __float2half(v.w);
    }
    __syncthreads();
    __half* dst = xt + ((size_t)b * N_SEQ + n0) * C_DIM + c0;
#pragma unroll
    for (int u = 0; u < 2; u++) {
        int idx = u * 256 + tid;
        int n = idx >> 3, ch = idx & 7;
        *(uint4*)(dst + (size_t)n * C_DIM + ch * 8) = *(uint4*)&Xs[n][ch * 8];
    }
}

// ---------- fp16 GEMM: both operands K-major fp16, k-chunk 64, 3-stage ring --
// A [M,K] fp16 row-major; B^T [N,K] fp16 row-major. C = A @ B (+bias).
// MODE 0: C fp32 + bias (out proj). MODE 1: QKV split -> fp16 Q^T/K^T/V.
#define GSTR 36                         // words per 64-half row (72 halfs, pad 8)
#define GTILE (128 * GSTR)              // 4608 words
#define GSLOT (2 * GTILE)               // A+B slot: 9216 words
#define GEMM_SMEM (3 * GSLOT * 4)       // 110592 B (>= bounce 128*133*4=68096)

template <int MODE>
__global__ __launch_bounds__(256, 2) void gemm_f16(
    const __half* __restrict__ A, const __half* __restrict__ Bg,
    float* __restrict__ Cg, const float* __restrict__ bias,
    __half* __restrict__ qt, __half* __restrict__ kt, __half* __restrict__ vh,
    int N, int K)
{
    extern __shared__ uint32_t gsm[];
    const uint32_t smem_u32 = (uint32_t)__cvta_generic_to_shared(gsm);

    const __half* B = Bg + (size_t)blockIdx.z * N * K;   // B^T rows = n
    const int brow = blockIdx.y * 128;
    const int bcol = blockIdx.x * 128;
    const int tid  = threadIdx.x;
    const int lane = tid & 31;
    const int w    = tid >> 5;
    const int wm   = (w >> 2) * 64;
    const int wn   = (w & 3) * 32;
    const int g    = lane >> 2;
    const int t    = lane & 3;

    const int nIters = K >> 6;          // K/64 = 8

#pragma unroll
    for (int s = 0; s < 2; s++) {
        const int k0 = s * 64;
        const uint32_t ab = smem_u32 + (uint32_t)(s * GSLOT) * 4;
        const uint32_t bb = ab + GTILE * 4;
#pragma unroll
        for (int r = 0; r < 4; r++) {
            int idx = r * 256 + tid;
            int m = idx >> 3, ch = idx & 7;
            cpa16(ab + (uint32_t)(m * GSTR + ch * 4) * 4,
                  A + (size_t)(brow + m) * K + k0 + ch * 8);
            cpa16(bb + (uint32_t)(m * GSTR + ch * 4) * 4,
                  B + (size_t)(bcol + m) * K + k0 + ch * 8);
        }
        asm volatile("cp.async.commit_group;");
    }

    float acc[4][4][4];
#pragma unroll
    for (int mt = 0; mt < 4; mt++)
#pragma unroll
        for (int nt = 0; nt < 4; nt++)
#pragma unroll
            for (int c = 0; c < 4; c++) acc[mt][nt][c] = 0.f;

    int cur = 0;
    for (int it = 0; it < nIters; it++) {
        if (it + 1 < nIters) asm volatile("cp.async.wait_group 1;");
        else                 asm volatile("cp.async.wait_group 0;");
        __syncthreads();

        if (it + 2 < nIters) {
            const int s = (it + 2) % 3;
            const int k0 = (it + 2) * 64;
            const uint32_t ab = smem_u32 + (uint32_t)(s * GSLOT) * 4;
            const uint32_t bb = ab + GTILE * 4;
#pragma unroll
            for (int r = 0; r < 4; r++) {
                int idx = r * 256 + tid;
                int m = idx >> 3, ch = idx & 7;
                cpa16(ab + (uint32_t)(m * GSTR + ch * 4) * 4,
                      A + (size_t)(brow + m) * K + k0 + ch * 8);
                cpa16(bb + (uint32_t)(m * GSTR + ch * 4) * 4,
                      B + (size_t)(bcol + m) * K + k0 + ch * 8);
            }
        }
        asm volatile("cp.async.commit_group;");

        const uint32_t* As = gsm + cur * GSLOT;
        const uint32_t* Bs = As + GTILE;

#pragma unroll
        for (int kc = 0; kc < 4; kc++) {
            const int k8 = kc * 8;
            uint32_t af[4][4], bf[4][2];
#pragma unroll
            for (int mt = 0; mt < 4; mt++) {
                const int r0 = wm + mt * 16 + g;
                af[mt][0] = As[r0 * GSTR + k8 + t];
                af[mt][1] = As[(r0 + 8) * GSTR + k8 + t];
                af[mt][2] = As[r0 * GSTR + k8 + 4 + t];
                af[mt][3] = As[(r0 + 8) * GSTR + k8 + 4 + t];
            }
#pragma unroll
            for (int nt = 0; nt < 4; nt++) {
                const int c0 = wn + nt * 8 + g;
                bf[nt][0] = Bs[c0 * GSTR + k8 + t];
                bf[nt][1] = Bs[c0 * GSTR + k8 + 4 + t];
            }
#pragma unroll
            for (int mt = 0; mt < 4; mt++)
#pragma unroll
                for (int nt = 0; nt < 4; nt++)
                    mma16(acc[mt][nt], af[mt], bf[nt]);
        }
        cur = (cur + 1) % 3;
    }

    if (MODE == 0) {
        float* C = Cg + (size_t)blockIdx.z * (size_t)gridDim.y * 128 * N;
#pragma unroll
        for (int mt = 0; mt < 4; mt++) {
            const int r0 = brow + wm + mt * 16 + g;
            const float b0 = bias[r0];
            const float b1 = bias[r0 + 8];
#pragma unroll
            for (int nt = 0; nt < 4; nt++) {
                const int c = bcol + wn + nt * 8 + 2 * t;
                *(float2*)(C + (size_t)r0 * N + c) =
                    make_float2(acc[mt][nt][0] + b0, acc[mt][nt][1] + b0);
                *(float2*)(C + (size_t)(r0 + 8) * N + c) =
                    make_float2(acc[mt][nt][2] + b1, acc[mt][nt][3] + b1);
            }
        }
        return;
    }

    // MODE 1: bounce -> fp16 split outputs (scalar stores: stride 133 is odd)
    __syncthreads();
    float* Ob = (float*)gsm;         // [128][133]
#pragma unroll
    for (int mt = 0; mt < 4; mt++) {
        const int r0 = wm + mt * 16 + g;
#pragma unroll
        for (int nt = 0; nt < 4; nt++) {
            const int c = wn + nt * 8 + 2 * t;
            Ob[r0 * 133 + c]           = acc[mt][nt][0];
            Ob[r0 * 133 + c + 1]       = acc[mt][nt][1];
            Ob[(r0 + 8) * 133 + c]     = acc[mt][nt][2];
            Ob[(r0 + 8) * 133 + c + 1] = acc[mt][nt][3];
        }
    }
    __syncthreads();

    const int b = blockIdx.z;
    const int sec = brow >> 9;     // 0=Q, 1=K, 2=V
    if (sec < 2) {
        __half* base = (sec == 0) ? qt : kt;
        const float mul = (sec == 0) ? SM_SCALE_LOG2 : 1.f;
        const int hbase = (brow - sec * 512) >> 6;
#pragma unroll
        for (int u = 0; u < 8; u++) {
            int tau = u * 256 + tid;
            int chunk = tau & 7, orow = tau >> 3;
            int hh = orow >> 7, j = orow & 127;
            int d0 = chunk * 8;
            uint32_t pk[4];
#pragma unroll
            for (int q = 0; q < 4; q++) {
                float v0 = Ob[(hh * 64 + d0 + 2 * q) * 133 + j] * mul;
                float v1 = Ob[(hh * 64 + d0 + 2 * q + 1) * 133 + j] * mul;
                pk[q] = packh2(v0, v1);
            }
            __half* dst = base +
                (((size_t)b * 8 + hbase + hh) * N_SEQ + bcol + j) * 64 + d0;
            *(uint4*)dst = make_uint4(pk[0], pk[1], pk[2], pk[3]);
        }
    } else {
#pragma unroll
        for (int u = 0; u < 8; u++) {
            int tau = u * 256 + tid;
            int chunk = tau & 15, orow = tau >> 4;
            int c0 = chunk * 8;
            uint32_t pk[4];
#pragma unroll
            for (int q = 0; q < 4; q++) {
                float v0 = Ob[orow * 133 + c0 + 2 * q];
                float v1 = Ob[orow * 133 + c0 + 2 * q + 1];
                pk[q] = packh2(v0, v1);
            }
            __half* dst = vh +
                ((size_t)b * HIDDEN + (brow - 1024) + orow) * N_SEQ + bcol + c0;
            *(uint4*)dst = make_uint4(pk[0], pk[1], pk[2], pk[3]);
        }
    }
}

// ------- flash fp16 (R12 core): output now att^T fp16 [b][i][c] --------------
#define KVW 36
#define SLOT_W (2 * 64 * KVW)
#define QOFF_W (3 * SLOT_W)
#define FLASH_SMEM ((QOFF_W + 128 * KVW) * 4)   // 73728 B
#define OSS 72
#define NTILES (N_SEQ / 64)

__global__ __launch_bounds__(128, 2) void flash_f16(
    const __half* __restrict__ qt, const __half* __restrict__ kt,
    const __half* __restrict__ vh, __half* __restrict__ attT)
{
    extern __shared__ uint32_t sm[];
    const uint32_t sb = (uint32_t)__cvta_generic_to_shared(sm);

    const int b  = blockIdx.z;
    const int h  = blockIdx.y;
    const int q0 = blockIdx.x * 128;
    const __half* qp = qt + (((size_t)b * 8 + h) * N_SEQ + q0) * 64;
    const __half* kp = kt + (((size_t)b * 8 + h) * N_SEQ) * 64;
    const __half* vp = vh + ((size_t)b * HIDDEN + h * 64) * N_SEQ;

    const int tid  = threadIdx.x;
    const int lane = tid & 31;
    const int w    = tid >> 5;
    const int g    = lane >> 2;
    const int t    = lane & 3;
    const int rb0  = w * 32;
    const int rA0  = rb0 + g,      rA1 = rb0 + g + 8;
    const int rB0  = rb0 + 16 + g, rB1 = rb0 + 16 + g + 8;

#pragma unroll
    for (int u = 0; u < 8; u++) {
        int idx = u * 128 + tid;
        int i = idx >> 3, ch = idx & 7;
        cpa16(sb + (uint32_t)(QOFF_W + i * KVW + ch * 4) * 4,
              qp + (size_t)i * 64 + ch * 8);
    }
    asm volatile("cp.async.commit_group;");

#pragma unroll
    for (int s = 0; s < 2; s++) {
        const int j0 = s * 64;
#pragma unroll
        for (int u = 0; u < 8; u++) {
            int idx = u * 128 + tid;
            int kv = idx >> 9, r = (idx >> 3) & 63, ch = idx & 7;
            const __half* src = kv
                ? vp + (size_t)r * N_SEQ + j0 + ch * 8
                : kp + (size_t)(j0 + r) * 64 + ch * 8;
            cpa16(sb + (uint32_t)(s * SLOT_W + kv * 64 * KVW + r * KVW + ch * 4) * 4,
                  src);
        }
        asm volatile("cp.async.commit_group;");
    }

    asm volatile("cp.async.wait_group 2;");
    __syncthreads();
    const uint32_t* Qs = sm + QOFF_W;
    uint32_t qf[4][8];
#pragma unroll
    for (int kc = 0; kc < 4; kc++) {
        const int k8 = kc * 8;
        qf[kc][0] = Qs[rA0 * KVW + k8 + t];
        qf[kc][1] = Qs[rA1 * KVW + k8 + t];
        qf[kc][2] = Qs[rA0 * KVW + k8 + 4 + t];
        qf[kc][3] = Qs[rA1 * KVW + k8 + 4 + t];
        qf[kc][4] = Qs[rB0 * KVW + k8 + t];
        qf[kc][5] = Qs[rB1 * KVW + k8 + t];
        qf[kc][6] = Qs[rB0 * KVW + k8 + 4 + t];
        qf[kc][7] = Qs[rB1 * KVW + k8 + 4 + t];
    }

    float o[2][8][4];
#pragma unroll
    for (int mt = 0; mt < 2; mt++)
#pragma unroll
        for (int dt = 0; dt < 8; dt++)
#pragma unroll
            for (int c = 0; c < 4; c++) o[mt][dt][c] = 0.f;
    float mrow[2][2] = {{-1e30f, -1e30f}, {-1e30f, -1e30f}};
    float lrow[2][2] = {{0.f, 0.f}, {0.f, 0.f}};

    int slot = 0, pslot = 2;
    for (int tI = 0; tI < NTILES; tI++) {
        if (tI < NTILES - 1) asm volatile("cp.async.wait_group 1;");
        else                 asm volatile("cp.async.wait_group 0;");
        __syncthreads();

        if (tI + 2 < NTILES) {
            const int j1 = (tI + 2) * 64;
#pragma unroll
            for (int u = 0; u < 8; u++) {
                int idx = u * 128 + tid;
                int kv = idx >> 9, r = (idx >> 3) & 63, ch = idx & 7;
                const __half* src = kv
                    ? vp + (size_t)r * N_SEQ + j1 + ch * 8
                    : kp + (size_t)(j1 + r) * 64 + ch * 8;
                cpa16(sb + (uint32_t)(pslot * SLOT_W + kv * 64 * KVW + r * KVW + ch * 4) * 4,
                      src);
            }
            asm volatile("cp.async.commit_group;");
        }

        const uint32_t* Kc = sm + slot * SLOT_W;
        const uint32_t* Vc = Kc + 64 * KVW;

        float s[2][8][4];
#pragma unroll
        for (int mt = 0; mt < 2; mt++)
#pragma unroll
            for (int nt = 0; nt < 8; nt++)
#pragma unroll
                for (int c = 0; c < 4; c++) s[mt][nt][c] = 0.f;
#pragma unroll
        for (int kc = 0; kc < 4; kc++) {
            const int k8 = kc * 8;
#pragma unroll
            for (int nt = 0; nt < 8; nt++) {
                const uint32_t* kr = Kc + (nt * 8 + g) * KVW;
                uint32_t bb[2];
                bb[0] = kr[k8 + t];
                bb[1] = kr[k8 + 4 + t];
                mma16(s[0][nt], &qf[kc][0], bb);
                mma16(s[1][nt], &qf[kc][4], bb);
            }
        }

        uint32_t pk[2][8][2];
#pragma unroll
        for (int mt = 0; mt < 2; mt++) {
            float mx0 = -1e30f, mx1 = -1e30f;
#pragma unroll
            for (int nt = 0; nt < 8; nt++) {
                mx0 = fmaxf(mx0, fmaxf(s[mt][nt][0], s[mt][nt][1]));
                mx1 = fmaxf(mx1, fmaxf(s[mt][nt][2], s[mt][nt][3]));
            }
            mx0 = fmaxf(mx0, __shfl_xor_sync(0xffffffffu, mx0, 1));
            mx0 = fmaxf(mx0, __shfl_xor_sync(0xffffffffu, mx0, 2));
            mx1 = fmaxf(mx1, __shfl_xor_sync(0xffffffffu, mx1, 1));
            mx1 = fmaxf(mx1, __shfl_xor_sync(0xffffffffu, mx1, 2));

            const float nm0 = fmaxf(mrow[mt][0], mx0);
            const float nm1 = fmaxf(mrow[mt][1], mx1);
            const float al0 = ex2(mrow[mt][0] - nm0);
            const float al1 = ex2(mrow[mt][1] - nm1);

            float ps0 = 0.f, ps1 = 0.f;
#pragma unroll
            for (int nt = 0; nt < 8; nt++) {
                float p0 = ex2(s[mt][nt][0] - nm0);
                float p1 = ex2(s[mt][nt][1] - nm0);
                float p2 = ex2(s[mt][nt][2] - nm1);
                float p3 = ex2(s[mt][nt][3] - nm1);
                ps0 += p0 + p1; ps1 += p2 + p3;
                pk[mt][nt][0] = packh2(p0, p1);
                pk[mt][nt][1] = packh2(p2, p3);
            }
            ps0 += __shfl_xor_sync(0xffffffffu, ps0, 1);
            ps0 += __shfl_xor_sync(0xffffffffu, ps0, 2);
            ps1 += __shfl_xor_sync(0xffffffffu, ps1, 1);
            ps1 += __shfl_xor_sync(0xffffffffu, ps1, 2);
            lrow[mt][0] = lrow[mt][0] * al0 + ps0;
            lrow[mt][1] = lrow[mt][1] * al1 + ps1;
            mrow[mt][0] = nm0; mrow[mt][1] = nm1;

#pragma unroll
            for (int dt = 0; dt < 8; dt++) {
                o[mt][dt][0] *= al0; o[mt][dt][1] *= al0;
                o[mt][dt][2] *= al1; o[mt][dt][3] *= al1;
            }
        }

#pragma unroll
        for (int kc = 0; kc < 4; kc++) {
            const int k8 = kc * 8;
            uint32_t a0[4] = {pk[0][2*kc][0], pk[0][2*kc][1],
                              pk[0][2*kc+1][0], pk[0][2*kc+1][1]};
            uint32_t a1[4] = {pk[1][2*kc][0], pk[1][2*kc][1],
                              pk[1][2*kc+1][0], pk[1][2*kc+1][1]};
#pragma unroll
            for (int dt = 0; dt < 8; dt++) {
                const uint32_t* vr = Vc + (dt * 8 + g) * KVW;
                uint32_t bb[2];
                bb[0] = vr[k8 + t];
                bb[1] = vr[k8 + 4 + t];
                mma16(o[0][dt], a0, bb);
                mma16(o[1][dt], a1, bb);
            }
        }

        slot  = (slot  == 2) ? 0 : slot + 1;
        pslot = (pslot == 2) ? 0 : pslot + 1;
    }

    // O staging as [i][d] (stride OSS), then fp16 pack -> attT[b][q0+i][h*64+d]
    __syncthreads();
    float* Os = (float*)sm;          // 128*72*4 = 36864 B
#pragma unroll
    for (int mt = 0; mt < 2; mt++) {
        const int q0r = (mt == 0) ? rA0 : rB0;
        const int q1r = (mt == 0) ? rA1 : rB1;
        const float inv0 = 1.f / lrow[mt][0];
        const float inv1 = 1.f / lrow[mt][1];
#pragma unroll
        for (int dt = 0; dt < 8; dt++) {
            const int d = dt * 8 + 2 * t;
            Os[q0r * OSS + d]     = o[mt][dt][0] * inv0;
            Os[q0r * OSS + d + 1] = o[mt][dt][1] * inv0;
            Os[q1r * OSS + d]     = o[mt][dt][2] * inv1;
            Os[q1r * OSS + d + 1] = o[mt][dt][3] * inv1;
        }
    }
    __syncthreads();

    __half* out = attT + ((size_t)b * N_SEQ + q0) * HIDDEN + h * 64;
#pragma unroll
    for (int u = 0; u < 8; u++) {
        int idx = u * 128 + tid;
        int i = idx >> 3, ch = idx & 7;
        const float* r = Os + i * OSS + ch * 8;
        uint4 pkv;
        pkv.x = packh2(r[0], r[1]);
        pkv.y = packh2(r[2], r[3]);
        pkv.z = packh2(r[4], r[5]);
        pkv.w = packh2(r[6], r[7]);
        *(uint4*)(out + (size_t)i * HIDDEN + ch * 8) = pkv;
    }
}

// ---------------------------------------------------------------------------
extern "C" void kernel_launch(void* const* d_in, const int* in_sizes, int n_in,
                              void* d_out, int out_size)
{
    const float* x     = (const float*)d_in[0];
    const float* w_qkv = (const float*)d_in[1];
    const float* w_out = (const float*)d_in[2];
    const float* b_out = (const float*)d_in[3];
    float* y = (float*)d_out;

    __half *qt = nullptr, *kt = nullptr, *vh = nullptr;
    __half *attT = nullptr, *xt = nullptr, *wqh = nullptr, *woh = nullptr;
    cudaGetSymbolAddress((void**)&qt, g_qt);
    cudaGetSymbolAddress((void**)&kt, g_kt);
    cudaGetSymbolAddress((void**)&vh, g_vh);
    cudaGetSymbolAddress((void**)&attT, g_attT);
    cudaGetSymbolAddress((void**)&xt, g_xt);
    cudaGetSymbolAddress((void**)&wqh, g_wqh);
    cudaGetSymbolAddress((void**)&woh, g_woh);

    cudaFuncSetAttribute(gemm_f16<1>,
                         cudaFuncAttributeMaxDynamicSharedMemorySize, GEMM_SMEM);
    cudaFuncSetAttribute(gemm_f16<0>,
                         cudaFuncAttributeMaxDynamicSharedMemorySize, GEMM_SMEM);
    cudaFuncSetAttribute(flash_f16,
                         cudaFuncAttributeMaxDynamicSharedMemorySize, FLASH_SMEM);

    // 0) prepass: weights -> fp16; x -> x^T fp16
    cvt_w<<<(WQ_ELEMS + WO_ELEMS) / 1024, 256>>>(w_qkv, w_out, wqh, woh);
    cvt_x<<<dim3(N_SEQ / 64, C_DIM / 64, BATCH), 256>>>(x, xt);

    // 1) qkv projection (fp16 gemm) -> fp16 Q^T (scaled), K^T, V
    gemm_f16<1><<<dim3(N_SEQ / 128, QKV_ROWS / 128, BATCH), 256, GEMM_SMEM>>>(
        wqh, xt, nullptr, nullptr, qt, kt, vh, N_SEQ, C_DIM);

    // 2) fused flash attention (fp16) -> att^T fp16
    flash_f16<<<dim3(N_SEQ / 128, HEADS, BATCH), 128, FLASH_SMEM>>>(
        qt, kt, vh, attT);

    // 3) y = w_out @ att + b_out (fp16 gemm, fp32 out)
    gemm_f16<0><<<dim3(N_SEQ / 128, HIDDEN / 128, BATCH), 256, GEMM_SMEM>>>(
        woh, attT, y, b_out, nullptr, nullptr, nullptr, N_SEQ, C_DIM);
}

// round 14
// speedup vs baseline: 8.0917x; 1.0488x over previous
#include <cuda_runtime.h>
#include <cuda_fp16.h>
#include <stdint.h>

#define BATCH    8
#define C_DIM    512
#define N_SEQ    2048
#define HEADS    8
#define QKV_ROWS 1536
#define HIDDEN   512
#define SM_SCALE_LOG2 0.18033688011112042f  // dhead^-0.5 * log2(e)

// scratch
__device__ __align__(256) __half g_qt[(size_t)BATCH * HEADS * N_SEQ * 64];  // Q^T [b][h][i][d], pre-scaled
__device__ __align__(256) __half g_kt[(size_t)BATCH * HEADS * N_SEQ * 64];  // K^T [b][h][j][d]
__device__ __align__(256) __half g_vh[(size_t)BATCH * HIDDEN * N_SEQ];      // V   [b][h*64+d][j]
__device__ __align__(256) __half g_attT[(size_t)BATCH * N_SEQ * HIDDEN];    // att^T [b][i][c]
__device__ __align__(256) __half g_xt[(size_t)BATCH * N_SEQ * C_DIM];       // x^T [b][n][c]
#define WQ_ELEMS (QKV_ROWS * C_DIM)
#define WO_ELEMS (HIDDEN * C_DIM)
__device__ __align__(256) __half g_wqh[WQ_ELEMS];
__device__ __align__(256) __half g_woh[WO_ELEMS];

__device__ __forceinline__ float ex2(float x) {
    float r; asm("ex2.approx.f32 %0, %1;" : "=f"(r) : "f"(x)); return r;
}
__device__ __forceinline__ void mma16(float* c, const uint32_t* a, const uint32_t* b) {
    asm volatile(
        "mma.sync.aligned.m16n8k16.row.col.f32.f16.f16.f32 "
        "{%0,%1,%2,%3},{%4,%5,%6,%7},{%8,%9},{%0,%1,%2,%3};"
        : "+f"(c[0]), "+f"(c[1]), "+f"(c[2]), "+f"(c[3])
        : "r"(a[0]), "r"(a[1]), "r"(a[2]), "r"(a[3]), "r"(b[0]), "r"(b[1]));
}
__device__ __forceinline__ void cpa16(uint32_t s, const void* g) {
    asm volatile("cp.async.cg.shared.global [%0], [%1], 16;" :: "r"(s), "l"(g));
}
__device__ __forceinline__ uint32_t packh2(float a, float b) {
    __half2 h = __floats2half2_rn(a, b);
    return *(uint32_t*)&h;
}

// ---------------- prepass: weights fp32 -> fp16 ------------------------------
__global__ __launch_bounds__(256) void cvt_w(
    const float* __restrict__ wq, const float* __restrict__ wo,
    __half* __restrict__ dq, __half* __restrict__ dwo)
{
    int i = (blockIdx.x * 256 + threadIdx.x) * 4;
    const float* s; __half* d; int j;
    if (i < WQ_ELEMS) { s = wq; d = dq;  j = i; }
    else              { s = wo; d = dwo; j = i - WQ_ELEMS; }
    float4 v = *(const float4*)(s + j);
    uint32_t p0 = packh2(v.x, v.y), p1 = packh2(v.z, v.w);
    *(uint2*)(d + j) = make_uint2(p0, p1);
}

// ---------------- prepass: x [b][c][n] fp32 -> x^T [b][n][c] fp16 ------------
__global__ __launch_bounds__(256) void cvt_x(
    const float* __restrict__ x, __half* __restrict__ xt)
{
    __shared__ __half Xs[64][72];
    const int b  = blockIdx.z;
    const int c0 = blockIdx.y * 64;
    const int n0 = blockIdx.x * 64;
    const int tid = threadIdx.x;
    const float* src = x + ((size_t)b * C_DIM + c0) * N_SEQ + n0;
#pragma unroll
    for (int u = 0; u < 4; u++) {
        int idx = u * 256 + tid;
        int c = idx >> 4, n4 = (idx & 15) * 4;
        float4 v = *(const float4*)(src + (size_t)c * N_SEQ + n4);
        Xs[n4 + 0][c] = __float2half(v.x);
        Xs[n4 + 1][c] = __float2half(v.y);
        Xs[n4 + 2][c] = __float2half(v.z);
        Xs[n4 + 3][c] = __float2half(v.w);
    }
    __syncthreads();
    __half* dst = xt + ((size_t)b * N_SEQ + n0) * C_DIM + c0;
#pragma unroll
    for (int u = 0; u < 2; u++) {
        int idx = u * 256 + tid;
        int n = idx >> 3, ch = idx & 7;
        *(uint4*)(dst + (size_t)n * C_DIM + ch * 8) = *(uint4*)&Xs[n][ch * 8];
    }
}

// ---------- fp16 GEMM (R13 verbatim): K-major fp16 both sides, ring ----------
#define GSTR 36
#define GTILE (128 * GSTR)
#define GSLOT (2 * GTILE)
#define GEMM_SMEM (3 * GSLOT * 4)

template <int MODE>
__global__ __launch_bounds__(256, 2) void gemm_f16(
    const __half* __restrict__ A, const __half* __restrict__ Bg,
    float* __restrict__ Cg, const float* __restrict__ bias,
    __half* __restrict__ qt, __half* __restrict__ kt, __half* __restrict__ vh,
    int N, int K)
{
    extern __shared__ uint32_t gsm[];
    const uint32_t smem_u32 = (uint32_t)__cvta_generic_to_shared(gsm);

    const __half* B = Bg + (size_t)blockIdx.z * N * K;
    const int brow = blockIdx.y * 128;
    const int bcol = blockIdx.x * 128;
    const int tid  = threadIdx.x;
    const int lane = tid & 31;
    const int w    = tid >> 5;
    const int wm   = (w >> 2) * 64;
    const int wn   = (w & 3) * 32;
    const int g    = lane >> 2;
    const int t    = lane & 3;

    const int nIters = K >> 6;

#pragma unroll
    for (int s = 0; s < 2; s++) {
        const int k0 = s * 64;
        const uint32_t ab = smem_u32 + (uint32_t)(s * GSLOT) * 4;
        const uint32_t bb = ab + GTILE * 4;
#pragma unroll
        for (int r = 0; r < 4; r++) {
            int idx = r * 256 + tid;
            int m = idx >> 3, ch = idx & 7;
            cpa16(ab + (uint32_t)(m * GSTR + ch * 4) * 4,
                  A + (size_t)(brow + m) * K + k0 + ch * 8);
            cpa16(bb + (uint32_t)(m * GSTR + ch * 4) * 4,
                  B + (size_t)(bcol + m) * K + k0 + ch * 8);
        }
        asm volatile("cp.async.commit_group;");
    }

    float acc[4][4][4];
#pragma unroll
    for (int mt = 0; mt < 4; mt++)
#pragma unroll
        for (int nt = 0; nt < 4; nt++)
#pragma unroll
            for (int c = 0; c < 4; c++) acc[mt][nt][c] = 0.f;

    int cur = 0;
    for (int it = 0; it < nIters; it++) {
        if (it + 1 < nIters) asm volatile("cp.async.wait_group 1;");
        else                 asm volatile("cp.async.wait_group 0;");
        __syncthreads();

        if (it + 2 < nIters) {
            const int s = (it + 2) % 3;
            const int k0 = (it + 2) * 64;
            const uint32_t ab = smem_u32 + (uint32_t)(s * GSLOT) * 4;
            const uint32_t bb = ab + GTILE * 4;
#pragma unroll
            for (int r = 0; r < 4; r++) {
                int idx = r * 256 + tid;
                int m = idx >> 3, ch = idx & 7;
                cpa16(ab + (uint32_t)(m * GSTR + ch * 4) * 4,
                      A + (size_t)(brow + m) * K + k0 + ch * 8);
                cpa16(bb + (uint32_t)(m * GSTR + ch * 4) * 4,
                      B + (size_t)(bcol + m) * K + k0 + ch * 8);
            }
        }
        asm volatile("cp.async.commit_group;");

        const uint32_t* As = gsm + cur * GSLOT;
        const uint32_t* Bs = As + GTILE;

#pragma unroll
        for (int kc = 0; kc < 4; kc++) {
            const int k8 = kc * 8;
            uint32_t af[4][4], bf[4][2];
#pragma unroll
            for (int mt = 0; mt < 4; mt++) {
                const int r0 = wm + mt * 16 + g;
                af[mt][0] = As[r0 * GSTR + k8 + t];
                af[mt][1] = As[(r0 + 8) * GSTR + k8 + t];
                af[mt][2] = As[r0 * GSTR + k8 + 4 + t];
                af[mt][3] = As[(r0 + 8) * GSTR + k8 + 4 + t];
            }
#pragma unroll
            for (int nt = 0; nt < 4; nt++) {
                const int c0 = wn + nt * 8 + g;
                bf[nt][0] = Bs[c0 * GSTR + k8 + t];
                bf[nt][1] = Bs[c0 * GSTR + k8 + 4 + t];
            }
#pragma unroll
            for (int mt = 0; mt < 4; mt++)
#pragma unroll
                for (int nt = 0; nt < 4; nt++)
                    mma16(acc[mt][nt], af[mt], bf[nt]);
        }
        cur = (cur + 1) % 3;
    }

    if (MODE == 0) {
        float* C = Cg + (size_t)blockIdx.z * (size_t)gridDim.y * 128 * N;
#pragma unroll
        for (int mt = 0; mt < 4; mt++) {
            const int r0 = brow + wm + mt * 16 + g;
            const float b0 = bias[r0];
            const float b1 = bias[r0 + 8];
#pragma unroll
            for (int nt = 0; nt < 4; nt++) {
                const int c = bcol + wn + nt * 8 + 2 * t;
                *(float2*)(C + (size_t)r0 * N + c) =
                    make_float2(acc[mt][nt][0] + b0, acc[mt][nt][1] + b0);
                *(float2*)(C + (size_t)(r0 + 8) * N + c) =
                    make_float2(acc[mt][nt][2] + b1, acc[mt][nt][3] + b1);
            }
        }
        return;
    }

    // MODE 1: bounce -> fp16 split outputs (scalar stores: stride 133 odd)
    __syncthreads();
    float* Ob = (float*)gsm;         // [128][133]
#pragma unroll
    for (int mt = 0; mt < 4; mt++) {
        const int r0 = wm + mt * 16 + g;
#pragma unroll
        for (int nt = 0; nt < 4; nt++) {
            const int c = wn + nt * 8 + 2 * t;
            Ob[r0 * 133 + c]           = acc[mt][nt][0];
            Ob[r0 * 133 + c + 1]       = acc[mt][nt][1];
            Ob[(r0 + 8) * 133 + c]     = acc[mt][nt][2];
            Ob[(r0 + 8) * 133 + c + 1] = acc[mt][nt][3];
        }
    }
    __syncthreads();

    const int b = blockIdx.z;
    const int sec = brow >> 9;     // 0=Q, 1=K, 2=V
    if (sec < 2) {
        __half* base = (sec == 0) ? qt : kt;
        const float mul = (sec == 0) ? SM_SCALE_LOG2 : 1.f;
        const int hbase = (brow - sec * 512) >> 6;
#pragma unroll
        for (int u = 0; u < 8; u++) {
            int tau = u * 256 + tid;
            int chunk = tau & 7, orow = tau >> 3;
            int hh = orow >> 7, j = orow & 127;
            int d0 = chunk * 8;
            uint32_t pk[4];
#pragma unroll
            for (int q = 0; q < 4; q++) {
                float v0 = Ob[(hh * 64 + d0 + 2 * q) * 133 + j] * mul;
                float v1 = Ob[(hh * 64 + d0 + 2 * q + 1) * 133 + j] * mul;
                pk[q] = packh2(v0, v1);
            }
            __half* dst = base +
                (((size_t)b * 8 + hbase + hh) * N_SEQ + bcol + j) * 64 + d0;
            *(uint4*)dst = make_uint4(pk[0], pk[1], pk[2], pk[3]);
        }
    } else {
#pragma unroll
        for (int u = 0; u < 8; u++) {
            int tau = u * 256 + tid;
            int chunk = tau & 15, orow = tau >> 4;
            int c0 = chunk * 8;
            uint32_t pk[4];
#pragma unroll
            for (int q = 0; q < 4; q++) {
                float v0 = Ob[orow * 133 + c0 + 2 * q];
                float v1 = Ob[orow * 133 + c0 + 2 * q + 1];
                pk[q] = packh2(v0, v1);
            }
            __half* dst = vh +
                ((size_t)b * HIDDEN + (brow - 1024) + orow) * N_SEQ + bcol + c0;
            *(uint4*)dst = make_uint4(pk[0], pk[1], pk[2], pk[3]);
        }
    }
}

// ------- flash fp16: 8 warps x 16 q-rows, l-via-mma (ones row), ring ---------
#define KVW 36
#define SLOT_W (2 * 64 * KVW)               // 4608 words
#define QOFF_W (3 * SLOT_W)                 // 13824
#define VONES_W (QOFF_W + 128 * KVW)        // 18432
#define FLASH_SMEM ((VONES_W + 8 * KVW) * 4)  // 74880 B
#define OSS 72
#define NTILES (N_SEQ / 64)

__global__ __launch_bounds__(256, 2) void flash_f16(
    const __half* __restrict__ qt, const __half* __restrict__ kt,
    const __half* __restrict__ vh, __half* __restrict__ attT)
{
    extern __shared__ uint32_t sm[];
    const uint32_t sb = (uint32_t)__cvta_generic_to_shared(sm);

    const int b  = blockIdx.z;
    const int h  = blockIdx.y;
    const int q0 = blockIdx.x * 128;
    const __half* qp = qt + (((size_t)b * 8 + h) * N_SEQ + q0) * 64;
    const __half* kp = kt + (((size_t)b * 8 + h) * N_SEQ) * 64;
    const __half* vp = vh + ((size_t)b * HIDDEN + h * 64) * N_SEQ;

    const int tid  = threadIdx.x;      // 256 threads, 8 warps
    const int lane = tid & 31;
    const int w    = tid >> 5;
    const int g    = lane >> 2;
    const int t    = lane & 3;
    const int r0   = w * 16 + g;       // this warp's q rows
    const int r1   = r0 + 8;

    // Q staging (cp.async)
#pragma unroll
    for (int u = 0; u < 4; u++) {
        int idx = u * 256 + tid;
        int i = idx >> 3, ch = idx & 7;
        cpa16(sb + (uint32_t)(QOFF_W + i * KVW + ch * 4) * 4,
              qp + (size_t)i * 64 + ch * 8);
    }
    asm volatile("cp.async.commit_group;");

    // K/V tiles 0,1
#pragma unroll
    for (int s = 0; s < 2; s++) {
        const int j0 = s * 64;
#pragma unroll
        for (int u = 0; u < 4; u++) {
            int idx = u * 256 + tid;
            int kv = idx >> 9, r = (idx >> 3) & 63, ch = idx & 7;
            const __half* src = kv
                ? vp + (size_t)r * N_SEQ + j0 + ch * 8
                : kp + (size_t)(j0 + r) * 64 + ch * 8;
            cpa16(sb + (uint32_t)(s * SLOT_W + kv * 64 * KVW + r * KVW + ch * 4) * 4,
                  src);
        }
        asm volatile("cp.async.commit_group;");
    }

    // static V-ones block: row 0 (d=64) = 1.0h pairs, rows 1..7 = 0
    for (int i = tid; i < 8 * KVW; i += 256)
        sm[VONES_W + i] = (i < KVW) ? 0x3C003C00u : 0u;

    asm volatile("cp.async.wait_group 2;");   // Q landed
    __syncthreads();                          // Q + Vones visible
    const uint32_t* Qs = sm + QOFF_W;
    uint32_t qf[4][4];
#pragma unroll
    for (int kc = 0; kc < 4; kc++) {
        const int k8 = kc * 8;
        qf[kc][0] = Qs[r0 * KVW + k8 + t];
        qf[kc][1] = Qs[r1 * KVW + k8 + t];
        qf[kc][2] = Qs[r0 * KVW + k8 + 4 + t];
        qf[kc][3] = Qs[r1 * KVW + k8 + 4 + t];
    }
    const uint32_t* Vones = sm + VONES_W + g * KVW;

    // o[0..7] = output dims; o[8] = l accumulator (ones column at t==0)
    float o[9][4];
#pragma unroll
    for (int dt = 0; dt < 9; dt++)
#pragma unroll
        for (int c = 0; c < 4; c++) o[dt][c] = 0.f;
    float m0 = -1e30f, m1 = -1e30f;

    int slot = 0, pslot = 2;
    for (int tI = 0; tI < NTILES; tI++) {
        if (tI < NTILES - 1) asm volatile("cp.async.wait_group 1;");
        else                 asm volatile("cp.async.wait_group 0;");
        __syncthreads();

        if (tI + 2 < NTILES) {
            const int j1 = (tI + 2) * 64;
#pragma unroll
            for (int u = 0; u < 4; u++) {
                int idx = u * 256 + tid;
                int kv = idx >> 9, r = (idx >> 3) & 63, ch = idx & 7;
                const __half* src = kv
                    ? vp + (size_t)r * N_SEQ + j1 + ch * 8
                    : kp + (size_t)(j1 + r) * 64 + ch * 8;
                cpa16(sb + (uint32_t)(pslot * SLOT_W + kv * 64 * KVW + r * KVW + ch * 4) * 4,
                      src);
            }
            asm volatile("cp.async.commit_group;");
        }

        const uint32_t* Kc = sm + slot * SLOT_W;
        const uint32_t* Vc = Kc + 64 * KVW;

        // S = Q @ K^T : 16 q rows x 64 keys
        float s[8][4];
#pragma unroll
        for (int nt = 0; nt < 8; nt++)
#pragma unroll
            for (int c = 0; c < 4; c++) s[nt][c] = 0.f;
#pragma unroll
        for (int kc = 0; kc < 4; kc++) {
            const int k8 = kc * 8;
#pragma unroll
            for (int nt = 0; nt < 8; nt++) {
                const uint32_t* kr = Kc + (nt * 8 + g) * KVW;
                uint32_t bb[2];
                bb[0] = kr[k8 + t];
                bb[1] = kr[k8 + 4 + t];
                mma16(s[nt], qf[kc], bb);
            }
        }

        // online softmax: max + exp only (l comes from the ones-row mma)
        float mx0 = -1e30f, mx1 = -1e30f;
#pragma unroll
        for (int nt = 0; nt < 8; nt++) {
            mx0 = fmaxf(mx0, fmaxf(s[nt][0], s[nt][1]));
            mx1 = fmaxf(mx1, fmaxf(s[nt][2], s[nt][3]));
        }
        mx0 = fmaxf(mx0, __shfl_xor_sync(0xffffffffu, mx0, 1));
        mx0 = fmaxf(mx0, __shfl_xor_sync(0xffffffffu, mx0, 2));
        mx1 = fmaxf(mx1, __shfl_xor_sync(0xffffffffu, mx1, 1));
        mx1 = fmaxf(mx1, __shfl_xor_sync(0xffffffffu, mx1, 2));

        const float nm0 = fmaxf(m0, mx0);
        const float nm1 = fmaxf(m1, mx1);
        const float al0 = ex2(m0 - nm0);
        const float al1 = ex2(m1 - nm1);
        m0 = nm0; m1 = nm1;

        uint32_t pk[8][2];
#pragma unroll
        for (int nt = 0; nt < 8; nt++) {
            float p0 = ex2(s[nt][0] - nm0);
            float p1 = ex2(s[nt][1] - nm0);
            float p2 = ex2(s[nt][2] - nm1);
            float p3 = ex2(s[nt][3] - nm1);
            pk[nt][0] = packh2(p0, p1);   // row r0, keys nt*8+2t, +1
            pk[nt][1] = packh2(p2, p3);   // row r1
        }

        // rescale all accumulators (incl. l in o[8]) by alpha
#pragma unroll
        for (int dt = 0; dt < 9; dt++) {
            o[dt][0] *= al0; o[dt][1] *= al0;
            o[dt][2] *= al1; o[dt][3] *= al1;
        }

        // O += P @ V ; extra n-tile (dt=8) vs ones-row gives l += row-sum(P)
#pragma unroll
        for (int kc = 0; kc < 4; kc++) {
            const int k8 = kc * 8;
            uint32_t a[4] = {pk[2 * kc][0], pk[2 * kc][1],
                             pk[2 * kc + 1][0], pk[2 * kc + 1][1]};
#pragma unroll
            for (int dt = 0; dt < 8; dt++) {
                const uint32_t* vr = Vc + (dt * 8 + g) * KVW;
                uint32_t bb[2];
                bb[0] = vr[k8 + t];
                bb[1] = vr[k8 + 4 + t];
                mma16(o[dt], a, bb);
            }
            uint32_t bo[2];
            bo[0] = Vones[k8 + t];
            bo[1] = Vones[k8 + 4 + t];
            mma16(o[8], a, bo);
        }

        slot  = (slot  == 2) ? 0 : slot + 1;
        pslot = (pslot == 2) ? 0 : pslot + 1;
    }

    // l lives in t==0 lanes (ones column = local col 0): broadcast within group
    const float l0 = __shfl_sync(0xffffffffu, o[8][0], lane & 28);
    const float l1 = __shfl_sync(0xffffffffu, o[8][2], lane & 28);
    const float inv0 = 1.f / l0;
    const float inv1 = 1.f / l1;

    __syncthreads();   // all slot reads done; reuse ring as Os[128][OSS] f32
    float* Os = (float*)sm;
#pragma unroll
    for (int dt = 0; dt < 8; dt++) {
        const int d = dt * 8 + 2 * t;
        Os[r0 * OSS + d]     = o[dt][0] * inv0;
        Os[r0 * OSS + d + 1] = o[dt][1] * inv0;
        Os[r1 * OSS + d]     = o[dt][2] * inv1;
        Os[r1 * OSS + d + 1] = o[dt][3] * inv1;
    }
    __syncthreads();

    __half* out = attT + ((size_t)b * N_SEQ + q0) * HIDDEN + h * 64;
#pragma unroll
    for (int u = 0; u < 4; u++) {
        int idx = u * 256 + tid;
        int i = idx >> 3, ch = idx & 7;
        const float* r = Os + i * OSS + ch * 8;
        uint4 pkv;
        pkv.x = packh2(r[0], r[1]);
        pkv.y = packh2(r[2], r[3]);
        pkv.z = packh2(r[4], r[5]);
        pkv.w = packh2(r[6], r[7]);
        *(uint4*)(out + (size_t)i * HIDDEN + ch * 8) = pkv;
    }
}

// ---------------------------------------------------------------------------
extern "C" void kernel_launch(void* const* d_in, const int* in_sizes, int n_in,
                              void* d_out, int out_size)
{
    const float* x     = (const float*)d_in[0];
    const float* w_qkv = (const float*)d_in[1];
    const float* w_out = (const float*)d_in[2];
    const float* b_out = (const float*)d_in[3];
    float* y = (float*)d_out;

    __half *qt = nullptr, *kt = nullptr, *vh = nullptr;
    __half *attT = nullptr, *xt = nullptr, *wqh = nullptr, *woh = nullptr;
    cudaGetSymbolAddress((void**)&qt, g_qt);
    cudaGetSymbolAddress((void**)&kt, g_kt);
    cudaGetSymbolAddress((void**)&vh, g_vh);
    cudaGetSymbolAddress((void**)&attT, g_attT);
    cudaGetSymbolAddress((void**)&xt, g_xt);
    cudaGetSymbolAddress((void**)&wqh, g_wqh);
    cudaGetSymbolAddress((void**)&woh, g_woh);

    cudaFuncSetAttribute(gemm_f16<1>,
                         cudaFuncAttributeMaxDynamicSharedMemorySize, GEMM_SMEM);
    cudaFuncSetAttribute(gemm_f16<0>,
                         cudaFuncAttributeMaxDynamicSharedMemorySize, GEMM_SMEM);
    cudaFuncSetAttribute(flash_f16,
                         cudaFuncAttributeMaxDynamicSharedMemorySize, FLASH_SMEM);

    // 0) prepass: weights -> fp16; x -> x^T fp16
    cvt_w<<<(WQ_ELEMS + WO_ELEMS) / 1024, 256>>>(w_qkv, w_out, wqh, woh);
    cvt_x<<<dim3(N_SEQ / 64, C_DIM / 64, BATCH), 256>>>(x, xt);

    // 1) qkv projection (fp16 gemm) -> fp16 Q^T (scaled), K^T, V
    gemm_f16<1><<<dim3(N_SEQ / 128, QKV_ROWS / 128, BATCH), 256, GEMM_SMEM>>>(
        wqh, xt, nullptr, nullptr, qt, kt, vh, N_SEQ, C_DIM);

    // 2) fused flash attention (fp16) -> att^T fp16
    flash_f16<<<dim3(N_SEQ / 128, HEADS, BATCH), 256, FLASH_SMEM>>>(
        qt, kt, vh, attT);

    // 3) y = w_out @ att + b_out (fp16 gemm, fp32 out)
    gemm_f16<0><<<dim3(N_SEQ / 128, HIDDEN / 128, BATCH), 256, GEMM_SMEM>>>(
        woh, attT, y, b_out, nullptr, nullptr, nullptr, N_SEQ, C_DIM);
}